// round 3
// baseline (speedup 1.0000x reference)
#include <cuda_runtime.h>
#include <math.h>

#define BB 16
#define CC 512
#define L0 80000
#define L1 16000
#define L2 4000
#define L3 2000
#define L4 1000
#define L5 500
#define TT 500
#define HID 256
#define KCPC 12

// ------------- device scratch (no cudaMalloc allowed) -------------
__device__ float g_c1[BB*CC*L1];
__device__ float g_c2[BB*CC*L2];
__device__ float g_c3[BB*CC*L3];
__device__ float g_c4[BB*CC*L4];
__device__ float g_c5[BB*CC*L5];
__device__ float g_scale[5*CC];
__device__ float g_shift[5*CC];
__device__ float g_z[TT*BB*CC];       // masked bn_relu(conv5), row r = t*16+b
__device__ float g_gi[TT*BB*768];     // input gates (without bih)
__device__ float g_hbuf[2][BB*HID];
__device__ float g_ct[BB*HID];
__device__ float g_enc[KCPC*BB*CC];
__device__ float g_pred[KCPC*BB*CC];
__device__ float g_total[KCPC*BB*BB];
__device__ unsigned g_bar_cnt;

// ------------- init: barrier counter + initial hidden -------------
__global__ void init_kernel(const float* __restrict__ hidden) {
    if (blockIdx.x == 0 && threadIdx.x == 0) g_bar_cnt = 0u;
    int i = blockIdx.x * blockDim.x + threadIdx.x;
    if (i < BB*HID) g_hbuf[0][i] = hidden[i];
}

// ------------- conv1: 1->512, k=10, s=5, pad=3 -------------
__global__ void conv1_kernel(const float* __restrict__ x, const float* __restrict__ w) {
    __shared__ float ws[CC*10];
    __shared__ float xs[256*5 + 10];
    int b = blockIdx.y;
    int o0 = blockIdx.x * 256;
    int tid = threadIdx.x;
    for (int i = tid; i < CC*10; i += 256) ws[i] = w[i];
    int p0 = o0*5 - 3;
    for (int i = tid; i < 256*5 + 10; i += 256) {
        int p = p0 + i;
        xs[i] = (p >= 0 && p < L0) ? x[b*L0 + p] : 0.f;
    }
    __syncthreads();
    int o = o0 + tid;
    if (o >= L1) return;
    float xr[10];
#pragma unroll
    for (int j = 0; j < 10; j++) xr[j] = xs[tid*5 + j];
    for (int co = 0; co < CC; co++) {
        float acc = 0.f;
#pragma unroll
        for (int j = 0; j < 10; j++) acc = fmaf(ws[co*10 + j], xr[j], acc);
        g_c1[(b*CC + co)*L1 + o] = acc;
    }
}

// ------------- per-channel batch stats -> (scale, shift) -------------
__global__ void stats_kernel(const float* __restrict__ raw, const float* __restrict__ gamma,
                             const float* __restrict__ beta, float* __restrict__ scale,
                             float* __restrict__ shift, int L) {
    int c = blockIdx.x;
    int tid = threadIdx.x;
    double s = 0.0, s2 = 0.0;
    for (int b = 0; b < BB; b++) {
        const float* p = raw + (size_t)(b*CC + c)*L;
        for (int l = tid; l < L; l += 256) { float v = p[l]; s += v; s2 += (double)v*v; }
    }
    __shared__ double rs[256], rs2[256];
    rs[tid] = s; rs2[tid] = s2; __syncthreads();
    for (int st = 128; st > 0; st >>= 1) {
        if (tid < st) { rs[tid] += rs[tid+st]; rs2[tid] += rs2[tid+st]; }
        __syncthreads();
    }
    if (tid == 0) {
        double n = (double)BB * (double)L;
        double mean = rs[0]/n;
        double var  = rs2[0]/n - mean*mean;
        double sc = (double)gamma[c] / sqrt(var + 1e-5);
        scale[c] = (float)sc;
        shift[c] = (float)((double)beta[c] - mean*sc);
    }
}

// ------------- implicit-GEMM conv with fused input BN+ReLU -------------
template<int KW, int S, int PAD>
__global__ void conv_bn_kernel(const float* __restrict__ in, const float* __restrict__ w,
                               const float* __restrict__ scale, const float* __restrict__ shift,
                               float* __restrict__ out, int Lin, int Lout) {
    constexpr int BM = 128, BN = 64, CI = 8, CK = CI*KW;
    constexpr int SPAN = (BN-1)*S + KW;
    constexpr int BMP = BM + 1;
    __shared__ float As[CK*BMP];
    __shared__ float Bs[CI*SPAN];
    int tid = threadIdx.x;
    int tx = tid & 15, ty = tid >> 4;
    int n0 = blockIdx.x * BN;
    int m0 = blockIdx.y * BM;
    int b  = blockIdx.z;
    int p0 = n0*S - PAD;
    float acc[8][4] = {};

    for (int ci0 = 0; ci0 < CC; ci0 += CI) {
        for (int i = tid; i < BM*CK; i += 256) {
            int co = i / CK, kk = i % CK;
            As[kk*BMP + co] = w[(m0+co)*(CC*KW) + ci0*KW + kk];
        }
        for (int i = tid; i < CI*SPAN; i += 256) {
            int cil = i / SPAN, pp = i % SPAN;
            int p = p0 + pp;
            float v = 0.f;
            if (p >= 0 && p < Lin) {
                float r = in[(b*CC + ci0 + cil)*Lin + p];
                v = fmaxf(fmaf(r, __ldg(&scale[ci0+cil]), __ldg(&shift[ci0+cil])), 0.f);
            }
            Bs[cil*SPAN + pp] = v;
        }
        __syncthreads();
#pragma unroll 8
        for (int kk = 0; kk < CK; kk++) {
            int cil = kk / KW, j = kk - cil*KW;
            const float* ap = &As[kk*BMP + ty*8];
            const float* bp = &Bs[cil*SPAN + j];
            float av[8], bv[4];
#pragma unroll
            for (int r2 = 0; r2 < 8; r2++) av[r2] = ap[r2];
#pragma unroll
            for (int c2 = 0; c2 < 4; c2++) bv[c2] = bp[(tx + 16*c2)*S];
#pragma unroll
            for (int r2 = 0; r2 < 8; r2++)
#pragma unroll
                for (int c2 = 0; c2 < 4; c2++)
                    acc[r2][c2] = fmaf(av[r2], bv[c2], acc[r2][c2]);
        }
        __syncthreads();
    }
#pragma unroll
    for (int r2 = 0; r2 < 8; r2++) {
        int co = m0 + ty*8 + r2;
#pragma unroll
        for (int c2 = 0; c2 < 4; c2++) {
            int n = n0 + tx + 16*c2;
            if (n < Lout) out[(b*CC + co)*Lout + n] = acc[r2][c2];
        }
    }
}

// ------------- z build: masked bn_relu(conv5) transposed to [t*16+b][d] -------------
__global__ void buildz_kernel(const int* __restrict__ ts, const float* __restrict__ sc,
                              const float* __restrict__ sh) {
    int t = blockIdx.x, b = blockIdx.y, d = threadIdx.x;
    float v = 0.f;
    if (t <= ts[b]) {
        float r = g_c5[(b*CC + d)*L5 + t];
        v = fmaxf(fmaf(r, sc[d], sh[d]), 0.f);
    }
    g_z[(t*BB + b)*CC + d] = v;
}

// ------------- GI = z @ Wih^T  (8000 x 768, K=512) -------------
__global__ void gi_gemm_kernel(const float* __restrict__ wih) {
    __shared__ float As[16*65];
    __shared__ float Bs[16*65];
    int tid = threadIdx.x;
    int tx = tid & 15, ty = tid >> 4;
    int r0 = blockIdx.x * 64, g0 = blockIdx.y * 64;
    float acc[4][4] = {};
    for (int k0 = 0; k0 < CC; k0 += 16) {
        for (int i = tid; i < 1024; i += 256) {
            int rl = i >> 4, kk = i & 15;
            As[kk*65 + rl] = g_z[(r0+rl)*CC + k0 + kk];
            Bs[kk*65 + rl] = wih[(g0+rl)*CC + k0 + kk];
        }
        __syncthreads();
#pragma unroll
        for (int kk = 0; kk < 16; kk++) {
            float av[4], bv[4];
#pragma unroll
            for (int i = 0; i < 4; i++) av[i] = As[kk*65 + ty*4 + i];
#pragma unroll
            for (int j = 0; j < 4; j++) bv[j] = Bs[kk*65 + tx*4 + j];
#pragma unroll
            for (int i = 0; i < 4; i++)
#pragma unroll
                for (int j = 0; j < 4; j++)
                    acc[i][j] = fmaf(av[i], bv[j], acc[i][j]);
        }
        __syncthreads();
    }
#pragma unroll
    for (int i = 0; i < 4; i++)
#pragma unroll
        for (int j = 0; j < 4; j++)
            g_gi[(r0 + ty*4 + i)*768 + g0 + tx*4 + j] = acc[i][j];
}

// ------------- persistent GRU: 32 blocks, grid barrier per step -------------
__global__ void gru_kernel(const float* __restrict__ whh, const float* __restrict__ bih,
                           const float* __restrict__ bhh, const int* __restrict__ ts) {
    __shared__ float ws[3*8*256];     // whh rows for this block's 8 units x 3 gates
    __shared__ float h_s[BB*HID];
    __shared__ float part[BB*8*2*3];
    __shared__ float bih_s[24], bhh_s[24];
    __shared__ int ts_s[BB];
    int tid = threadIdx.x;
    int j0 = blockIdx.x * 8;
    int b = tid >> 4;
    int jl = (tid >> 1) & 7;
    int half = tid & 1;

    for (int i = tid; i < 6144; i += 256) {
        int g = i >> 11, rest = i & 2047;
        int jj = rest >> 8, k = rest & 255;
        ws[i] = whh[(g*256 + j0 + jj)*256 + k];
    }
    if (tid < 24) {
        int g = tid / 8, jj = tid % 8;
        bih_s[tid] = bih[g*256 + j0 + jj];
        bhh_s[tid] = bhh[g*256 + j0 + jj];
    }
    if (tid < BB) ts_s[tid] = ts[tid];
    __syncthreads();

    for (int t = 0; t < TT; t++) {
        const float* hin = g_hbuf[t & 1];
        for (int i = tid; i < BB*HID; i += 256) h_s[i] = __ldcg(&hin[i]);
        __syncthreads();

        float ar = 0.f, az = 0.f, an = 0.f;
        const float4* h4  = (const float4*)&h_s[b*256 + half*128];
        const float4* wr4 = (const float4*)&ws[(0*8 + jl)*256 + half*128];
        const float4* wz4 = (const float4*)&ws[(1*8 + jl)*256 + half*128];
        const float4* wn4 = (const float4*)&ws[(2*8 + jl)*256 + half*128];
#pragma unroll 8
        for (int k = 0; k < 32; k++) {
            float4 hv = h4[k];
            float4 a = wr4[k]; ar += a.x*hv.x + a.y*hv.y + a.z*hv.z + a.w*hv.w;
            float4 c = wz4[k]; az += c.x*hv.x + c.y*hv.y + c.z*hv.z + c.w*hv.w;
            float4 d = wn4[k]; an += d.x*hv.x + d.y*hv.y + d.z*hv.z + d.w*hv.w;
        }
        int pb = ((b*8 + jl)*2 + half)*3;
        part[pb+0] = ar; part[pb+1] = az; part[pb+2] = an;
        __syncthreads();

        if (half == 0) {
            int p2 = ((b*8 + jl)*2)*3;
            float hr = part[p2+0] + part[p2+3] + bhh_s[jl];
            float hz = part[p2+1] + part[p2+4] + bhh_s[8+jl];
            float hn = part[p2+2] + part[p2+5] + bhh_s[16+jl];
            const float* gi = &g_gi[(t*BB + b)*768];
            float ir  = gi[j0+jl]       + bih_s[jl];
            float iz  = gi[256 + j0+jl] + bih_s[8+jl];
            float in_ = gi[512 + j0+jl] + bih_s[16+jl];
            float r  = 1.f / (1.f + expf(-(ir + hr)));
            float zg = 1.f / (1.f + expf(-(iz + hz)));
            float n  = tanhf(in_ + r*hn);
            float hprev = h_s[b*256 + j0 + jl];
            float hnew = (1.f - zg)*n + zg*hprev;
            __stcg(&g_hbuf[(t+1) & 1][b*256 + j0 + jl], hnew);
            if (t == ts_s[b]) g_ct[b*256 + j0 + jl] = hnew;
            __threadfence();
        }
        __syncthreads();
        if (tid == 0) {
            atomicAdd(&g_bar_cnt, 1u);
            unsigned target = 32u * (unsigned)(t + 1);
            while (*((volatile unsigned*)&g_bar_cnt) < target) { }
        }
        __syncthreads();
    }
}

// ------------- enc gather -------------
__global__ void enc_kernel(const int* __restrict__ ts, const float* __restrict__ sc,
                           const float* __restrict__ sh) {
    int k = blockIdx.x, b = blockIdx.y, d = threadIdx.x;
    int t = ts[b] + k + 1;
    float r = g_c5[(b*CC + d)*L5 + t];
    g_enc[(k*BB + b)*CC + d] = fmaxf(fmaf(r, sc[d], sh[d]), 0.f);
}

// ------------- pred[k][b][d] = c_t[b] . Wk_w[k][d][:] + Wk_b[k][d] -------------
__global__ void pred_kernel(const float* __restrict__ wk, const float* __restrict__ wkb) {
    int k = blockIdx.x, b = blockIdx.y, d = threadIdx.x;
    __shared__ float ct[HID];
    if (d < HID) ct[d] = g_ct[b*HID + d];
    __syncthreads();
    float acc = wkb[k*CC + d];
    const float4* w4 = (const float4*)&wk[(k*CC + d)*HID];
#pragma unroll 4
    for (int h = 0; h < HID/4; h++) {
        float4 w = w4[h];
        const float* c = &ct[h*4];
        acc += w.x*c[0] + w.y*c[1] + w.z*c[2] + w.w*c[3];
    }
    g_pred[(k*BB + b)*CC + d] = acc;
}

// ------------- total[k][b][c] = enc[k][b] . pred[k][c] -------------
__global__ void total_kernel() {
    int k = blockIdx.x, tid = threadIdx.x;
    int b = tid >> 4, c = tid & 15;
    const float* e = &g_enc[(k*BB + b)*CC];
    const float* p = &g_pred[(k*BB + c)*CC];
    float acc = 0.f;
    for (int d = 0; d < CC; d++) acc += e[d] * p[d];
    g_total[(k*BB + b)*BB + c] = acc;
}

// ------------- final: nce, accuracy, h_last -------------
__global__ void final_kernel(float* __restrict__ out) {
    __shared__ float lse_s[KCPC*BB];
    __shared__ float contrib[KCPC*BB];
    __shared__ int corr[BB];
    int tid = threadIdx.x;
    if (tid < KCPC*BB) {
        int b = tid & 15;
        const float* row = &g_total[tid*BB];
        float m = row[0];
        for (int c = 1; c < BB; c++) m = fmaxf(m, row[c]);
        float s = 0.f;
        for (int c = 0; c < BB; c++) s += expf(row[c] - m);
        float lse = m + logf(s);
        lse_s[tid] = lse;
        contrib[tid] = row[b] - lse;
    }
    __syncthreads();
    if (tid == 0) {
        float s = 0.f;
        for (int i = 0; i < KCPC*BB; i++) s += contrib[i];
        out[1] = s / (-(float)(BB*KCPC));
    }
    if (tid < BB) {
        int c = tid;
        float best = -1e30f; int bi = -1;
        for (int b = 0; b < BB; b++) {
            float v = g_total[((KCPC-1)*BB + b)*BB + c] - lse_s[(KCPC-1)*BB + b];
            if (v > best) { best = v; bi = b; }
        }
        corr[tid] = (bi == c) ? 1 : 0;
    }
    __syncthreads();
    if (tid == 0) {
        int cs = 0;
        for (int i = 0; i < BB; i++) cs += corr[i];
        out[0] = (float)cs / (float)BB;
    }
    for (int i = tid; i < BB*HID; i += blockDim.x) out[2 + i] = g_hbuf[0][i];
}

// ------------- launch -------------
extern "C" void kernel_launch(void* const* d_in, const int* in_sizes, int n_in,
                              void* d_out, int out_size) {
    (void)in_sizes; (void)n_in; (void)out_size;
    const float* x      = (const float*)d_in[0];
    const float* hidden = (const float*)d_in[1];
    const int*   tsamp  = (const int*)d_in[3];
    const float* w1     = (const float*)d_in[4];
    const float* w2     = (const float*)d_in[5];
    const float* w345   = (const float*)d_in[6];
    const float* gamma  = (const float*)d_in[7];
    const float* beta   = (const float*)d_in[8];
    const float* wih    = (const float*)d_in[9];
    const float* whh    = (const float*)d_in[10];
    const float* bih    = (const float*)d_in[11];
    const float* bhh    = (const float*)d_in[12];
    const float* wk     = (const float*)d_in[13];
    const float* wkb    = (const float*)d_in[14];
    float* out = (float*)d_out;

    float *p_c1, *p_c2, *p_c3, *p_c4, *p_c5, *p_sc, *p_sh;
    cudaGetSymbolAddress((void**)&p_c1, g_c1);
    cudaGetSymbolAddress((void**)&p_c2, g_c2);
    cudaGetSymbolAddress((void**)&p_c3, g_c3);
    cudaGetSymbolAddress((void**)&p_c4, g_c4);
    cudaGetSymbolAddress((void**)&p_c5, g_c5);
    cudaGetSymbolAddress((void**)&p_sc, g_scale);
    cudaGetSymbolAddress((void**)&p_sh, g_shift);

    init_kernel<<<16, 256>>>(hidden);

    conv1_kernel<<<dim3(63, BB), 256>>>(x, w1);
    stats_kernel<<<CC, 256>>>(p_c1, gamma + 0*CC, beta + 0*CC, p_sc + 0*CC, p_sh + 0*CC, L1);

    conv_bn_kernel<8,4,2><<<dim3(63, 4, BB), 256>>>(p_c1, w2, p_sc + 0*CC, p_sh + 0*CC, p_c2, L1, L2);
    stats_kernel<<<CC, 256>>>(p_c2, gamma + 1*CC, beta + 1*CC, p_sc + 1*CC, p_sh + 1*CC, L2);

    conv_bn_kernel<4,2,1><<<dim3(32, 4, BB), 256>>>(p_c2, w345 + 0*CC*CC*4, p_sc + 1*CC, p_sh + 1*CC, p_c3, L2, L3);
    stats_kernel<<<CC, 256>>>(p_c3, gamma + 2*CC, beta + 2*CC, p_sc + 2*CC, p_sh + 2*CC, L3);

    conv_bn_kernel<4,2,1><<<dim3(16, 4, BB), 256>>>(p_c3, w345 + 1*CC*CC*4, p_sc + 2*CC, p_sh + 2*CC, p_c4, L3, L4);
    stats_kernel<<<CC, 256>>>(p_c4, gamma + 3*CC, beta + 3*CC, p_sc + 3*CC, p_sh + 3*CC, L4);

    conv_bn_kernel<4,2,1><<<dim3(8, 4, BB), 256>>>(p_c4, w345 + 2*CC*CC*4, p_sc + 3*CC, p_sh + 3*CC, p_c5, L4, L5);
    stats_kernel<<<CC, 256>>>(p_c5, gamma + 4*CC, beta + 4*CC, p_sc + 4*CC, p_sh + 4*CC, L5);

    buildz_kernel<<<dim3(TT, BB), CC>>>(tsamp, p_sc + 4*CC, p_sh + 4*CC);
    gi_gemm_kernel<<<dim3(125, 12), 256>>>(wih);
    gru_kernel<<<32, 256>>>(whh, bih, bhh, tsamp);

    enc_kernel<<<dim3(KCPC, BB), CC>>>(tsamp, p_sc + 4*CC, p_sh + 4*CC);
    pred_kernel<<<dim3(KCPC, BB), CC>>>(wk, wkb);
    total_kernel<<<KCPC, 256>>>();
    final_kernel<<<1, 256>>>(out);
}

// round 5
// speedup vs baseline: 1.1913x; 1.1913x over previous
#include <cuda_runtime.h>
#include <math.h>
#include <stdint.h>

#define BB 16
#define CC 512
#define L0 80000
#define L1 16000
#define L2 4000
#define L3 2000
#define L4 1000
#define L5 500
#define TT 500
#define HID 256
#define KCPC 12

// ================= device scratch =================
__device__ float g_c1[BB*CC*L1];
__device__ float g_c2[BB*CC*L2];
__device__ float g_c3[BB*CC*L3];
__device__ float g_c4[BB*CC*L4];
__device__ float g_c5[BB*CC*L5];
__device__ float g_scale[5*CC];
__device__ float g_shift[5*CC];
__device__ float g_z[TT*BB*CC];
__device__ float g_gi[TT*BB*768];
__device__ float g_hbuf[2][BB*HID];
__device__ float g_ct[BB*HID];
__device__ float g_enc[KCPC*BB*CC];
__device__ float g_pred[KCPC*BB*CC];
__device__ float g_total[KCPC*BB*BB];
__device__ unsigned g_bar_cnt;

// ================= helpers =================
__device__ __forceinline__ uint32_t f2tf32(float x) {
    uint32_t r;
    asm("cvt.rna.tf32.f32 %0, %1;" : "=r"(r) : "f"(x));
    return r;
}
__device__ __forceinline__ void split_tf32(float v, uint32_t& big, uint32_t& sml) {
    big = f2tf32(v);
    float s = v - __uint_as_float(big);
    sml = f2tf32(s);
}
__device__ __forceinline__ void mma_tf32(float* d, const uint32_t* a, const uint32_t* bfr) {
    asm volatile(
        "mma.sync.aligned.m16n8k8.row.col.f32.tf32.tf32.f32 "
        "{%0,%1,%2,%3}, {%4,%5,%6,%7}, {%8,%9}, {%0,%1,%2,%3};"
        : "+f"(d[0]), "+f"(d[1]), "+f"(d[2]), "+f"(d[3])
        : "r"(a[0]), "r"(a[1]), "r"(a[2]), "r"(a[3]), "r"(bfr[0]), "r"(bfr[1]));
}

// ================= init =================
__global__ void init_kernel(const float* __restrict__ hidden) {
    if (blockIdx.x == 0 && threadIdx.x == 0) g_bar_cnt = 0u;
    int i = blockIdx.x * blockDim.x + threadIdx.x;
    if (i < BB*HID) g_hbuf[0][i] = hidden[i];
}

// ================= conv1: 1->512, k=10, s=5, pad=3 =================
__global__ void conv1_kernel(const float* __restrict__ x, const float* __restrict__ w) {
    __shared__ float wsm[CC*10];
    __shared__ float xs[256*5 + 10];
    int b = blockIdx.y;
    int o0 = blockIdx.x * 256;
    int tid = threadIdx.x;
    for (int i = tid; i < CC*10; i += 256) wsm[i] = w[i];
    int p0 = o0*5 - 3;
    for (int i = tid; i < 256*5 + 10; i += 256) {
        int p = p0 + i;
        xs[i] = (p >= 0 && p < L0) ? x[b*L0 + p] : 0.f;
    }
    __syncthreads();
    int o = o0 + tid;
    if (o >= L1) return;
    float xr[10];
#pragma unroll
    for (int j = 0; j < 10; j++) xr[j] = xs[tid*5 + j];
    for (int co = 0; co < CC; co++) {
        float acc = 0.f;
#pragma unroll
        for (int j = 0; j < 10; j++) acc = fmaf(wsm[co*10 + j], xr[j], acc);
        g_c1[(b*CC + co)*L1 + o] = acc;
    }
}

// ================= per-channel batch stats =================
__global__ void stats_kernel(const float* __restrict__ raw, const float* __restrict__ gamma,
                             const float* __restrict__ beta, float* __restrict__ scale,
                             float* __restrict__ shift, int L) {
    int c = blockIdx.x;
    int tid = threadIdx.x;
    double s = 0.0, s2 = 0.0;
    for (int b = 0; b < BB; b++) {
        const float* p = raw + (size_t)(b*CC + c)*L;
        for (int l = tid; l < L; l += 256) { float v = p[l]; s += v; s2 += (double)v*v; }
    }
    __shared__ double rs[256], rs2[256];
    rs[tid] = s; rs2[tid] = s2; __syncthreads();
    for (int st = 128; st > 0; st >>= 1) {
        if (tid < st) { rs[tid] += rs[tid+st]; rs2[tid] += rs2[tid+st]; }
        __syncthreads();
    }
    if (tid == 0) {
        double n = (double)BB * (double)L;
        double mean = rs[0]/n;
        double var  = rs2[0]/n - mean*mean;
        double sc = (double)gamma[c] / sqrt(var + 1e-5);
        scale[c] = (float)sc;
        shift[c] = (float)((double)beta[c] - mean*sc);
    }
}

// ================= tf32 mma.sync implicit-GEMM conv (3xTF32) =================
// out[b][co][n] = sum_{ci,j} w[co][ci*KW+j] * relu(in[b][ci][n*S-PAD+j]*scale+shift)
// Block: 128 co x 64 n, K chunk 32. 8 warps (4m x 2n), warp tile 32x32.
#define CMM_AS_F (128*36)
#define CMM_BS_F (64*36)
#define CMM_STG_F (CMM_AS_F + CMM_BS_F)
#define CMM_SMEM_BYTES (2*CMM_STG_F*4)

template<int KW, int S, int PAD, int KTOT>
__global__ void __launch_bounds__(256, 2)
conv_mma_kernel(const float* __restrict__ in, const float* __restrict__ w,
                const float* __restrict__ scale, const float* __restrict__ shift,
                float* __restrict__ out, int Lin, int Lout) {
    extern __shared__ float sm[];
    int tid = threadIdx.x;
    int wid = tid >> 5, lane = tid & 31;
    int g = lane >> 2, tig = lane & 3;
    int warp_m = wid >> 1, warp_n = wid & 1;
    int n0 = blockIdx.x * 64;
    int m0 = blockIdx.y * 128;
    int b  = blockIdx.z;

    float acc[2][4][4];
#pragma unroll
    for (int mt = 0; mt < 2; mt++)
#pragma unroll
        for (int nt = 0; nt < 4; nt++)
#pragma unroll
            for (int q = 0; q < 4; q++) acc[mt][nt][q] = 0.f;

    constexpr int NC = KTOT / 32;

    // prefetch chunk 0 into stage 0
    {
#pragma unroll
        for (int it = 0; it < 4; it++) {
            int idx = tid + it*256;
            int row = idx >> 3, q = idx & 7;
            float4 v = *(const float4*)&w[(size_t)(m0+row)*KTOT + q*4];
            *(float4*)&sm[row*36 + q*4] = v;
        }
#pragma unroll
        for (int it = 0; it < 8; it++) {
            int i = tid + it*256;
            int k = i >> 6, nl = i & 63;
            int ci = k / KW, j = k % KW;
            int p = (n0+nl)*S - PAD + j;
            float v = 0.f;
            if (p >= 0 && p < Lin) {
                float raw = in[(size_t)(b*CC + ci)*Lin + p];
                v = fmaxf(fmaf(raw, __ldg(&scale[ci]), __ldg(&shift[ci])), 0.f);
            }
            sm[CMM_AS_F + nl*36 + k] = v;
        }
    }
    __syncthreads();

    float4 stA[4];
    float  stB[8];

    for (int c = 0; c < NC; c++) {
        int s = c & 1;
        if (c + 1 < NC) {
            int kb = (c+1)*32;
#pragma unroll
            for (int it = 0; it < 4; it++) {
                int idx = tid + it*256;
                int row = idx >> 3, q = idx & 7;
                stA[it] = *(const float4*)&w[(size_t)(m0+row)*KTOT + kb + q*4];
            }
#pragma unroll
            for (int it = 0; it < 8; it++) {
                int i = tid + it*256;
                int k = i >> 6, nl = i & 63;
                int kk2 = kb + k;
                int ci = kk2 / KW, j = kk2 % KW;
                int p = (n0+nl)*S - PAD + j;
                float v = 0.f;
                if (p >= 0 && p < Lin) {
                    float raw = in[(size_t)(b*CC + ci)*Lin + p];
                    v = fmaxf(fmaf(raw, __ldg(&scale[ci]), __ldg(&shift[ci])), 0.f);
                }
                stB[it] = v;
            }
        }
        const float* As = &sm[s*CMM_STG_F];
        const float* Bs = &sm[s*CMM_STG_F + CMM_AS_F];
#pragma unroll
        for (int ks = 0; ks < 4; ks++) {
            int k0 = ks*8;
            uint32_t ab[2][4], asl[2][4];
#pragma unroll
            for (int mt = 0; mt < 2; mt++) {
                int mb = warp_m*32 + mt*16;
                float v0 = As[(mb+g  )*36 + k0 + tig];
                float v1 = As[(mb+g+8)*36 + k0 + tig];
                float v2 = As[(mb+g  )*36 + k0 + tig + 4];
                float v3 = As[(mb+g+8)*36 + k0 + tig + 4];
                split_tf32(v0, ab[mt][0], asl[mt][0]);
                split_tf32(v1, ab[mt][1], asl[mt][1]);
                split_tf32(v2, ab[mt][2], asl[mt][2]);
                split_tf32(v3, ab[mt][3], asl[mt][3]);
            }
            uint32_t bb[4][2], bsl[4][2];
#pragma unroll
            for (int nt = 0; nt < 4; nt++) {
                int nb = warp_n*32 + nt*8;
                float u0 = Bs[(nb+g)*36 + k0 + tig];
                float u1 = Bs[(nb+g)*36 + k0 + tig + 4];
                split_tf32(u0, bb[nt][0], bsl[nt][0]);
                split_tf32(u1, bb[nt][1], bsl[nt][1]);
            }
#pragma unroll
            for (int mt = 0; mt < 2; mt++)
#pragma unroll
                for (int nt = 0; nt < 4; nt++) {
                    mma_tf32(acc[mt][nt], ab[mt], bb[nt]);
                    mma_tf32(acc[mt][nt], ab[mt], bsl[nt]);
                    mma_tf32(acc[mt][nt], asl[mt], bb[nt]);
                }
        }
        if (c + 1 < NC) {
            float* Ad = &sm[(s^1)*CMM_STG_F];
            float* Bd = Ad + CMM_AS_F;
#pragma unroll
            for (int it = 0; it < 4; it++) {
                int idx = tid + it*256;
                int row = idx >> 3, q = idx & 7;
                *(float4*)&Ad[row*36 + q*4] = stA[it];
            }
#pragma unroll
            for (int it = 0; it < 8; it++) {
                int i = tid + it*256;
                int k = i >> 6, nl = i & 63;
                Bd[nl*36 + k] = stB[it];
            }
        }
        __syncthreads();
    }

    // epilogue
#pragma unroll
    for (int mt = 0; mt < 2; mt++) {
        int co0 = m0 + warp_m*32 + mt*16 + g;
#pragma unroll
        for (int nt = 0; nt < 4; nt++) {
            int n = n0 + warp_n*32 + nt*8 + 2*tig;
            if (n < Lout) {
                float2 v0 = make_float2(acc[mt][nt][0], acc[mt][nt][1]);
                float2 v1 = make_float2(acc[mt][nt][2], acc[mt][nt][3]);
                *(float2*)&out[(size_t)(b*CC + co0    )*Lout + n] = v0;
                *(float2*)&out[(size_t)(b*CC + co0 + 8)*Lout + n] = v1;
            }
        }
    }
}

// ================= z build =================
__global__ void buildz_kernel(const int* __restrict__ ts, const float* __restrict__ sc,
                              const float* __restrict__ sh) {
    int t = blockIdx.x, b = blockIdx.y, d = threadIdx.x;
    float v = 0.f;
    if (t <= ts[b]) {
        float r = g_c5[(b*CC + d)*L5 + t];
        v = fmaxf(fmaf(r, sc[d], sh[d]), 0.f);
    }
    g_z[(t*BB + b)*CC + d] = v;
}

// ================= GI = z @ Wih^T (8000 x 768, K=512) =================
__global__ void gi_gemm_kernel(const float* __restrict__ wih) {
    __shared__ float As[16*65];
    __shared__ float Bs[16*65];
    int tid = threadIdx.x;
    int tx = tid & 15, ty = tid >> 4;
    int r0 = blockIdx.x * 64, g0 = blockIdx.y * 64;
    float acc[4][4] = {};
    for (int k0 = 0; k0 < CC; k0 += 16) {
        for (int i = tid; i < 1024; i += 256) {
            int rl = i >> 4, kk = i & 15;
            As[kk*65 + rl] = g_z[(r0+rl)*CC + k0 + kk];
            Bs[kk*65 + rl] = wih[(g0+rl)*CC + k0 + kk];
        }
        __syncthreads();
#pragma unroll
        for (int kk = 0; kk < 16; kk++) {
            float av[4], bv[4];
#pragma unroll
            for (int i = 0; i < 4; i++) av[i] = As[kk*65 + ty*4 + i];
#pragma unroll
            for (int j = 0; j < 4; j++) bv[j] = Bs[kk*65 + tx*4 + j];
#pragma unroll
            for (int i = 0; i < 4; i++)
#pragma unroll
                for (int j = 0; j < 4; j++)
                    acc[i][j] = fmaf(av[i], bv[j], acc[i][j]);
        }
        __syncthreads();
    }
#pragma unroll
    for (int i = 0; i < 4; i++)
#pragma unroll
        for (int j = 0; j < 4; j++)
            g_gi[(r0 + ty*4 + i)*768 + g0 + tx*4 + j] = acc[i][j];
}

// ================= persistent GRU =================
__global__ void gru_kernel(const float* __restrict__ whh, const float* __restrict__ bih,
                           const float* __restrict__ bhh, const int* __restrict__ ts) {
    __shared__ float ws[3*8*256];
    __shared__ float h_s[BB*HID];
    __shared__ float part[BB*8*2*3];
    __shared__ float bih_s[24], bhh_s[24];
    __shared__ int ts_s[BB];
    int tid = threadIdx.x;
    int j0 = blockIdx.x * 8;
    int b = tid >> 4;
    int jl = (tid >> 1) & 7;
    int half = tid & 1;

    for (int i = tid; i < 6144; i += 256) {
        int g = i >> 11, rest = i & 2047;
        int jj = rest >> 8, k = rest & 255;
        ws[i] = whh[(g*256 + j0 + jj)*256 + k];
    }
    if (tid < 24) {
        int g = tid / 8, jj = tid % 8;
        bih_s[tid] = bih[g*256 + j0 + jj];
        bhh_s[tid] = bhh[g*256 + j0 + jj];
    }
    if (tid < BB) ts_s[tid] = ts[tid];
    __syncthreads();

    for (int t = 0; t < TT; t++) {
        const float* hin = g_hbuf[t & 1];
        for (int i = tid; i < BB*HID; i += 256) h_s[i] = __ldcg(&hin[i]);
        __syncthreads();

        float ar = 0.f, az = 0.f, an = 0.f;
        const float4* h4  = (const float4*)&h_s[b*256 + half*128];
        const float4* wr4 = (const float4*)&ws[(0*8 + jl)*256 + half*128];
        const float4* wz4 = (const float4*)&ws[(1*8 + jl)*256 + half*128];
        const float4* wn4 = (const float4*)&ws[(2*8 + jl)*256 + half*128];
#pragma unroll 8
        for (int k = 0; k < 32; k++) {
            float4 hv = h4[k];
            float4 a = wr4[k]; ar += a.x*hv.x + a.y*hv.y + a.z*hv.z + a.w*hv.w;
            float4 c = wz4[k]; az += c.x*hv.x + c.y*hv.y + c.z*hv.z + c.w*hv.w;
            float4 d = wn4[k]; an += d.x*hv.x + d.y*hv.y + d.z*hv.z + d.w*hv.w;
        }
        int pb = ((b*8 + jl)*2 + half)*3;
        part[pb+0] = ar; part[pb+1] = az; part[pb+2] = an;
        __syncthreads();

        if (half == 0) {
            int p2 = ((b*8 + jl)*2)*3;
            float hr = part[p2+0] + part[p2+3] + bhh_s[jl];
            float hz = part[p2+1] + part[p2+4] + bhh_s[8+jl];
            float hn = part[p2+2] + part[p2+5] + bhh_s[16+jl];
            const float* gi = &g_gi[(t*BB + b)*768];
            float ir  = gi[j0+jl]       + bih_s[jl];
            float iz  = gi[256 + j0+jl] + bih_s[8+jl];
            float in_ = gi[512 + j0+jl] + bih_s[16+jl];
            float r  = 1.f / (1.f + expf(-(ir + hr)));
            float zg = 1.f / (1.f + expf(-(iz + hz)));
            float n  = tanhf(in_ + r*hn);
            float hprev = h_s[b*256 + j0 + jl];
            float hnew = (1.f - zg)*n + zg*hprev;
            __stcg(&g_hbuf[(t+1) & 1][b*256 + j0 + jl], hnew);
            if (t == ts_s[b]) g_ct[b*256 + j0 + jl] = hnew;
            __threadfence();
        }
        __syncthreads();
        if (tid == 0) {
            atomicAdd(&g_bar_cnt, 1u);
            unsigned target = 32u * (unsigned)(t + 1);
            while (*((volatile unsigned*)&g_bar_cnt) < target) { }
        }
        __syncthreads();
    }
}

// ================= enc gather =================
__global__ void enc_kernel(const int* __restrict__ ts, const float* __restrict__ sc,
                           const float* __restrict__ sh) {
    int k = blockIdx.x, b = blockIdx.y, d = threadIdx.x;
    int t = ts[b] + k + 1;
    float r = g_c5[(b*CC + d)*L5 + t];
    g_enc[(k*BB + b)*CC + d] = fmaxf(fmaf(r, sc[d], sh[d]), 0.f);
}

// ================= pred =================
__global__ void pred_kernel(const float* __restrict__ wk, const float* __restrict__ wkb) {
    int k = blockIdx.x, b = blockIdx.y, d = threadIdx.x;
    __shared__ float ct[HID];
    if (d < HID) ct[d] = g_ct[b*HID + d];
    __syncthreads();
    float acc = wkb[k*CC + d];
    const float4* w4 = (const float4*)&wk[(k*CC + d)*HID];
#pragma unroll 4
    for (int h = 0; h < HID/4; h++) {
        float4 w = w4[h];
        const float* c = &ct[h*4];
        acc += w.x*c[0] + w.y*c[1] + w.z*c[2] + w.w*c[3];
    }
    g_pred[(k*BB + b)*CC + d] = acc;
}

// ================= total =================
__global__ void total_kernel() {
    int k = blockIdx.x, tid = threadIdx.x;
    int b = tid >> 4, c = tid & 15;
    const float* e = &g_enc[(k*BB + b)*CC];
    const float* p = &g_pred[(k*BB + c)*CC];
    float acc = 0.f;
    for (int d = 0; d < CC; d++) acc += e[d] * p[d];
    g_total[(k*BB + b)*BB + c] = acc;
}

// ================= final =================
__global__ void final_kernel(float* __restrict__ out) {
    __shared__ float lse_s[KCPC*BB];
    __shared__ float contrib[KCPC*BB];
    __shared__ int corr[BB];
    int tid = threadIdx.x;
    if (tid < KCPC*BB) {
        int b = tid & 15;
        const float* row = &g_total[tid*BB];
        float m = row[0];
        for (int c = 1; c < BB; c++) m = fmaxf(m, row[c]);
        float s = 0.f;
        for (int c = 0; c < BB; c++) s += expf(row[c] - m);
        float lse = m + logf(s);
        lse_s[tid] = lse;
        contrib[tid] = row[b] - lse;
    }
    __syncthreads();
    if (tid == 0) {
        float s = 0.f;
        for (int i = 0; i < KCPC*BB; i++) s += contrib[i];
        out[1] = s / (-(float)(BB*KCPC));
    }
    if (tid < BB) {
        int c = tid;
        float best = -1e30f; int bi = -1;
        for (int b = 0; b < BB; b++) {
            float v = g_total[((KCPC-1)*BB + b)*BB + c] - lse_s[(KCPC-1)*BB + b];
            if (v > best) { best = v; bi = b; }
        }
        corr[tid] = (bi == c) ? 1 : 0;
    }
    __syncthreads();
    if (tid == 0) {
        int cs = 0;
        for (int i = 0; i < BB; i++) cs += corr[i];
        out[0] = (float)cs / (float)BB;
    }
    for (int i = tid; i < BB*HID; i += blockDim.x) out[2 + i] = g_hbuf[0][i];
}

// ================= launch =================
extern "C" void kernel_launch(void* const* d_in, const int* in_sizes, int n_in,
                              void* d_out, int out_size) {
    (void)in_sizes; (void)n_in; (void)out_size;
    const float* x      = (const float*)d_in[0];
    const float* hidden = (const float*)d_in[1];
    const int*   tsamp  = (const int*)d_in[3];
    const float* w1     = (const float*)d_in[4];
    const float* w2     = (const float*)d_in[5];
    const float* w345   = (const float*)d_in[6];
    const float* gamma  = (const float*)d_in[7];
    const float* beta   = (const float*)d_in[8];
    const float* wih    = (const float*)d_in[9];
    const float* whh    = (const float*)d_in[10];
    const float* bih    = (const float*)d_in[11];
    const float* bhh    = (const float*)d_in[12];
    const float* wk     = (const float*)d_in[13];
    const float* wkb    = (const float*)d_in[14];
    float* out = (float*)d_out;

    float *p_c1, *p_c2, *p_c3, *p_c4, *p_c5, *p_sc, *p_sh;
    cudaGetSymbolAddress((void**)&p_c1, g_c1);
    cudaGetSymbolAddress((void**)&p_c2, g_c2);
    cudaGetSymbolAddress((void**)&p_c3, g_c3);
    cudaGetSymbolAddress((void**)&p_c4, g_c4);
    cudaGetSymbolAddress((void**)&p_c5, g_c5);
    cudaGetSymbolAddress((void**)&p_sc, g_scale);
    cudaGetSymbolAddress((void**)&p_sh, g_shift);

    cudaFuncSetAttribute(conv_mma_kernel<8,4,2,4096>,
                         cudaFuncAttributeMaxDynamicSharedMemorySize, CMM_SMEM_BYTES);
    cudaFuncSetAttribute(conv_mma_kernel<4,2,1,2048>,
                         cudaFuncAttributeMaxDynamicSharedMemorySize, CMM_SMEM_BYTES);

    init_kernel<<<16, 256>>>(hidden);

    conv1_kernel<<<dim3(63, BB), 256>>>(x, w1);
    stats_kernel<<<CC, 256>>>(p_c1, gamma + 0*CC, beta + 0*CC, p_sc + 0*CC, p_sh + 0*CC, L1);

    conv_mma_kernel<8,4,2,4096><<<dim3(63, 4, BB), 256, CMM_SMEM_BYTES>>>(
        p_c1, w2, p_sc + 0*CC, p_sh + 0*CC, p_c2, L1, L2);
    stats_kernel<<<CC, 256>>>(p_c2, gamma + 1*CC, beta + 1*CC, p_sc + 1*CC, p_sh + 1*CC, L2);

    conv_mma_kernel<4,2,1,2048><<<dim3(32, 4, BB), 256, CMM_SMEM_BYTES>>>(
        p_c2, w345 + 0*CC*2048, p_sc + 1*CC, p_sh + 1*CC, p_c3, L2, L3);
    stats_kernel<<<CC, 256>>>(p_c3, gamma + 2*CC, beta + 2*CC, p_sc + 2*CC, p_sh + 2*CC, L3);

    conv_mma_kernel<4,2,1,2048><<<dim3(16, 4, BB), 256, CMM_SMEM_BYTES>>>(
        p_c3, w345 + 1*CC*2048, p_sc + 2*CC, p_sh + 2*CC, p_c4, L3, L4);
    stats_kernel<<<CC, 256>>>(p_c4, gamma + 3*CC, beta + 3*CC, p_sc + 3*CC, p_sh + 3*CC, L4);

    conv_mma_kernel<4,2,1,2048><<<dim3(8, 4, BB), 256, CMM_SMEM_BYTES>>>(
        p_c4, w345 + 2*CC*2048, p_sc + 3*CC, p_sh + 3*CC, p_c5, L4, L5);
    stats_kernel<<<CC, 256>>>(p_c5, gamma + 4*CC, beta + 4*CC, p_sc + 4*CC, p_sh + 4*CC, L5);

    buildz_kernel<<<dim3(TT, BB), CC>>>(tsamp, p_sc + 4*CC, p_sh + 4*CC);
    gi_gemm_kernel<<<dim3(125, 12), 256>>>(wih);
    gru_kernel<<<32, 256>>>(whh, bih, bhh, tsamp);

    enc_kernel<<<dim3(KCPC, BB), CC>>>(tsamp, p_sc + 4*CC, p_sh + 4*CC);
    pred_kernel<<<dim3(KCPC, BB), CC>>>(wk, wkb);
    total_kernel<<<KCPC, 256>>>();
    final_kernel<<<1, 256>>>(out);
}

// round 6
// speedup vs baseline: 1.4136x; 1.1866x over previous
#include <cuda_runtime.h>
#include <math.h>
#include <stdint.h>

#define BB 16
#define CC 512
#define L0 80000
#define L1 16000
#define L2 4000
#define L3 2000
#define L4 1000
#define L5 500
#define TT 500
#define HID 256
#define KCPC 12

// ================= device scratch =================
__device__ float g_c1[BB*CC*L1];
__device__ float g_c2[BB*CC*L2];
__device__ float g_c3[BB*CC*L3];
__device__ float g_c4[BB*CC*L4];
__device__ float g_c5[BB*CC*L5];
__device__ float g_scale[5*CC];
__device__ float g_shift[5*CC];
__device__ uint32_t g_w2b[CC*2048];      // conv2 weights, packed bf16 pairs (big)
__device__ uint32_t g_w2s[CC*2048];      // (small)
__device__ uint32_t g_w345b[3*CC*1024];
__device__ uint32_t g_w345s[3*CC*1024];
__device__ float g_z[TT*BB*CC];
__device__ float g_gi[TT*BB*768];
__device__ float g_hbuf[2][BB*HID];
__device__ float g_ct[BB*HID];
__device__ float g_enc[KCPC*BB*CC];
__device__ float g_pred[KCPC*BB*CC];
__device__ float g_total[KCPC*BB*BB];
__device__ unsigned g_bar_cnt;

// ================= helpers =================
__device__ __forceinline__ uint32_t pack_bf16x2(float hi, float lo) {
    uint32_t r;
    asm("cvt.rn.bf16x2.f32 %0, %1, %2;" : "=r"(r) : "f"(hi), "f"(lo));
    return r;
}
// split v0,v1 into packed big + packed small bf16x2 words (lo = v0)
__device__ __forceinline__ void split_pack(float v0, float v1, uint32_t& bw, uint32_t& sw) {
    bw = pack_bf16x2(v1, v0);
    float b0 = __uint_as_float(bw << 16);
    float b1 = __uint_as_float(bw & 0xffff0000u);
    sw = pack_bf16x2(v1 - b1, v0 - b0);
}
__device__ __forceinline__ void mma_bf16(float* d, const uint32_t* a, const uint32_t* bfr) {
    asm volatile(
        "mma.sync.aligned.m16n8k16.row.col.f32.bf16.bf16.f32 "
        "{%0,%1,%2,%3}, {%4,%5,%6,%7}, {%8,%9}, {%0,%1,%2,%3};"
        : "+f"(d[0]), "+f"(d[1]), "+f"(d[2]), "+f"(d[3])
        : "r"(a[0]), "r"(a[1]), "r"(a[2]), "r"(a[3]), "r"(bfr[0]), "r"(bfr[1]));
}

// ================= init =================
__global__ void init_kernel(const float* __restrict__ hidden) {
    if (blockIdx.x == 0 && threadIdx.x == 0) g_bar_cnt = 0u;
    int i = blockIdx.x * blockDim.x + threadIdx.x;
    if (i < BB*HID) g_hbuf[0][i] = hidden[i];
}

// ================= weight split: fp32 -> packed bf16 big/small =================
__global__ void splitw_kernel(const float* __restrict__ w, uint32_t* __restrict__ wb,
                              uint32_t* __restrict__ ws, int npairs) {
    int i = blockIdx.x * blockDim.x + threadIdx.x;
    if (i < npairs) {
        float v0 = w[2*i], v1 = w[2*i+1];
        uint32_t bw, sw;
        split_pack(v0, v1, bw, sw);
        wb[i] = bw;
        ws[i] = sw;
    }
}

// ================= conv1: 1->512, k=10, s=5, pad=3 =================
__global__ void conv1_kernel(const float* __restrict__ x, const float* __restrict__ w) {
    __shared__ float wsm[CC*10];
    __shared__ float xs[256*5 + 10];
    int b = blockIdx.y;
    int o0 = blockIdx.x * 256;
    int tid = threadIdx.x;
    for (int i = tid; i < CC*10; i += 256) wsm[i] = w[i];
    int p0 = o0*5 - 3;
    for (int i = tid; i < 256*5 + 10; i += 256) {
        int p = p0 + i;
        xs[i] = (p >= 0 && p < L0) ? x[b*L0 + p] : 0.f;
    }
    __syncthreads();
    int o = o0 + tid;
    if (o >= L1) return;
    float xr[10];
#pragma unroll
    for (int j = 0; j < 10; j++) xr[j] = xs[tid*5 + j];
    for (int co = 0; co < CC; co++) {
        float acc = 0.f;
#pragma unroll
        for (int j = 0; j < 10; j++) acc = fmaf(wsm[co*10 + j], xr[j], acc);
        g_c1[(b*CC + co)*L1 + o] = acc;
    }
}

// ================= per-channel batch stats =================
__global__ void stats_kernel(const float* __restrict__ raw, const float* __restrict__ gamma,
                             const float* __restrict__ beta, float* __restrict__ scale,
                             float* __restrict__ shift, int L) {
    int c = blockIdx.x;
    int tid = threadIdx.x;
    double s = 0.0, s2 = 0.0;
    for (int b = 0; b < BB; b++) {
        const float* p = raw + (size_t)(b*CC + c)*L;
        for (int l = tid; l < L; l += 256) { float v = p[l]; s += v; s2 += (double)v*v; }
    }
    __shared__ double rs[256], rs2[256];
    rs[tid] = s; rs2[tid] = s2; __syncthreads();
    for (int st = 128; st > 0; st >>= 1) {
        if (tid < st) { rs[tid] += rs[tid+st]; rs2[tid] += rs2[tid+st]; }
        __syncthreads();
    }
    if (tid == 0) {
        double n = (double)BB * (double)L;
        double mean = rs[0]/n;
        double var  = rs2[0]/n - mean*mean;
        double sc = (double)gamma[c] / sqrt(var + 1e-5);
        scale[c] = (float)sc;
        shift[c] = (float)((double)beta[c] - mean*sc);
    }
}

// ================= 3xBF16 mma.sync implicit-GEMM conv =================
// out[b][co][n] = sum_{ci,j} w[co][ci*KW+j] * relu(in[b][ci][n*S-PAD+j]*scale+shift)
// Block: 128 co x 64 n, K chunk 32 fp32 (=16 packed words). 8 warps (4m x 2n), warp tile 32x32.
// SMEM rows: 16 data words at stride 20 (conflict-free frag loads).
#define CST 20
#define OFF_AB 0
#define OFF_AS 2560
#define OFF_BB 5120
#define OFF_BS 6400
#define STG    7680
#define CMM_SMEM_BYTES (2*STG*4)

template<int KW, int S, int PAD, int KTOT>
__global__ void __launch_bounds__(256, 2)
conv_mma_kernel(const float* __restrict__ in,
                const uint32_t* __restrict__ wb, const uint32_t* __restrict__ wsp,
                const float* __restrict__ scale, const float* __restrict__ shift,
                float* __restrict__ out, int Lin, int Lout) {
    extern __shared__ uint32_t smw[];
    int tid = threadIdx.x;
    int wid = tid >> 5, lane = tid & 31;
    int g = lane >> 2, tig = lane & 3;
    int warp_m = wid >> 1, warp_n = wid & 1;
    int n0 = blockIdx.x * 64;
    int m0 = blockIdx.y * 128;
    int b  = blockIdx.z;
    constexpr int KW2 = KTOT/2;
    constexpr int NC = KTOT/32;

    float acc[2][4][4];
#pragma unroll
    for (int mt = 0; mt < 2; mt++)
#pragma unroll
        for (int nt = 0; nt < 4; nt++)
#pragma unroll
            for (int q = 0; q < 4; q++) acc[mt][nt][q] = 0.f;

    // ---- prologue: fill chunk 0 into stage 0 ----
    {
#pragma unroll
        for (int it = 0; it < 2; it++) {
            int idx = tid + it*256;
            int row = idx >> 2, q4 = idx & 3;
            size_t base4 = ((size_t)(m0+row)*KW2) >> 2;
            *(uint4*)&smw[OFF_AB + row*CST + q4*4] = ((const uint4*)wb)[base4 + q4];
            *(uint4*)&smw[OFF_AS + row*CST + q4*4] = ((const uint4*)wsp)[base4 + q4];
        }
#pragma unroll
        for (int it = 0; it < 4; it++) {
            int i = tid + it*256;
            int q = i & 15, nl = i >> 4;
            int k0 = 2*q;
            int ci = k0 / KW, j = k0 - ci*KW;
            int p = (n0+nl)*S - PAD + j;
            const float* src = in + (size_t)(b*CC + ci)*Lin;
            float sc = __ldg(&scale[ci]), sh = __ldg(&shift[ci]);
            float v0 = (p >= 0 && p < Lin) ? fmaxf(fmaf(src[p], sc, sh), 0.f) : 0.f;
            float v1 = (p+1 >= 0 && p+1 < Lin) ? fmaxf(fmaf(src[p+1], sc, sh), 0.f) : 0.f;
            uint32_t bw, sw;
            split_pack(v0, v1, bw, sw);
            smw[OFF_BB + nl*CST + q] = bw;
            smw[OFF_BS + nl*CST + q] = sw;
        }
    }
    __syncthreads();

    uint4 stAb[2], stAs[2];
    uint32_t stBb[4], stBs[4];

    for (int c = 0; c < NC; c++) {
        int s = c & 1;
        if (c + 1 < NC) {
            int kb2 = (c+1)*16;
#pragma unroll
            for (int it = 0; it < 2; it++) {
                int idx = tid + it*256;
                int row = idx >> 2, q4 = idx & 3;
                size_t base4 = ((size_t)(m0+row)*KW2 + kb2) >> 2;
                stAb[it] = ((const uint4*)wb)[base4 + q4];
                stAs[it] = ((const uint4*)wsp)[base4 + q4];
            }
            int kbase = (c+1)*32;
#pragma unroll
            for (int it = 0; it < 4; it++) {
                int i = tid + it*256;
                int q = i & 15, nl = i >> 4;
                int k0 = kbase + 2*q;
                int ci = k0 / KW, j = k0 - ci*KW;
                int p = (n0+nl)*S - PAD + j;
                const float* src = in + (size_t)(b*CC + ci)*Lin;
                float sc = __ldg(&scale[ci]), sh = __ldg(&shift[ci]);
                float v0 = (p >= 0 && p < Lin) ? fmaxf(fmaf(src[p], sc, sh), 0.f) : 0.f;
                float v1 = (p+1 >= 0 && p+1 < Lin) ? fmaxf(fmaf(src[p+1], sc, sh), 0.f) : 0.f;
                split_pack(v0, v1, stBb[it], stBs[it]);
            }
        }
        const uint32_t* Ab = smw + s*STG + OFF_AB;
        const uint32_t* As = smw + s*STG + OFF_AS;
        const uint32_t* Bbp = smw + s*STG + OFF_BB;
        const uint32_t* Bsp = smw + s*STG + OFF_BS;
#pragma unroll
        for (int ks = 0; ks < 2; ks++) {
            int kw = ks*8;
            uint32_t ab[2][4], asf[2][4];
#pragma unroll
            for (int mt = 0; mt < 2; mt++) {
                int r = warp_m*32 + mt*16 + g;
                ab[mt][0] = Ab[r*CST + kw + tig];
                ab[mt][1] = Ab[(r+8)*CST + kw + tig];
                ab[mt][2] = Ab[r*CST + kw + tig + 4];
                ab[mt][3] = Ab[(r+8)*CST + kw + tig + 4];
                asf[mt][0] = As[r*CST + kw + tig];
                asf[mt][1] = As[(r+8)*CST + kw + tig];
                asf[mt][2] = As[r*CST + kw + tig + 4];
                asf[mt][3] = As[(r+8)*CST + kw + tig + 4];
            }
            uint32_t bbf[4][2], bsf[4][2];
#pragma unroll
            for (int nt = 0; nt < 4; nt++) {
                int n = warp_n*32 + nt*8 + g;
                bbf[nt][0] = Bbp[n*CST + kw + tig];
                bbf[nt][1] = Bbp[n*CST + kw + tig + 4];
                bsf[nt][0] = Bsp[n*CST + kw + tig];
                bsf[nt][1] = Bsp[n*CST + kw + tig + 4];
            }
#pragma unroll
            for (int mt = 0; mt < 2; mt++)
#pragma unroll
                for (int nt = 0; nt < 4; nt++) {
                    mma_bf16(acc[mt][nt], ab[mt], bbf[nt]);
                    mma_bf16(acc[mt][nt], ab[mt], bsf[nt]);
                    mma_bf16(acc[mt][nt], asf[mt], bbf[nt]);
                }
        }
        if (c + 1 < NC) {
            uint32_t* dst = smw + (s^1)*STG;
#pragma unroll
            for (int it = 0; it < 2; it++) {
                int idx = tid + it*256;
                int row = idx >> 2, q4 = idx & 3;
                *(uint4*)&dst[OFF_AB + row*CST + q4*4] = stAb[it];
                *(uint4*)&dst[OFF_AS + row*CST + q4*4] = stAs[it];
            }
#pragma unroll
            for (int it = 0; it < 4; it++) {
                int i = tid + it*256;
                int q = i & 15, nl = i >> 4;
                dst[OFF_BB + nl*CST + q] = stBb[it];
                dst[OFF_BS + nl*CST + q] = stBs[it];
            }
        }
        __syncthreads();
    }

    // ---- epilogue ----
#pragma unroll
    for (int mt = 0; mt < 2; mt++) {
        int co0 = m0 + warp_m*32 + mt*16 + g;
#pragma unroll
        for (int nt = 0; nt < 4; nt++) {
            int n = n0 + warp_n*32 + nt*8 + 2*tig;
            if (n < Lout) {
                float2 v0 = make_float2(acc[mt][nt][0], acc[mt][nt][1]);
                float2 v1 = make_float2(acc[mt][nt][2], acc[mt][nt][3]);
                *(float2*)&out[(size_t)(b*CC + co0    )*Lout + n] = v0;
                *(float2*)&out[(size_t)(b*CC + co0 + 8)*Lout + n] = v1;
            }
        }
    }
}

// ================= z build =================
__global__ void buildz_kernel(const int* __restrict__ ts, const float* __restrict__ sc,
                              const float* __restrict__ sh) {
    int t = blockIdx.x, b = blockIdx.y, d = threadIdx.x;
    float v = 0.f;
    if (t <= ts[b]) {
        float r = g_c5[(b*CC + d)*L5 + t];
        v = fmaxf(fmaf(r, sc[d], sh[d]), 0.f);
    }
    g_z[(t*BB + b)*CC + d] = v;
}

// ================= GI = z @ Wih^T (8000 x 768, K=512) =================
__global__ void gi_gemm_kernel(const float* __restrict__ wih) {
    __shared__ float As[16*65];
    __shared__ float Bs[16*65];
    int tid = threadIdx.x;
    int tx = tid & 15, ty = tid >> 4;
    int r0 = blockIdx.x * 64, g0 = blockIdx.y * 64;
    float acc[4][4] = {};
    for (int k0 = 0; k0 < CC; k0 += 16) {
        for (int i = tid; i < 1024; i += 256) {
            int rl = i >> 4, kk = i & 15;
            As[kk*65 + rl] = g_z[(r0+rl)*CC + k0 + kk];
            Bs[kk*65 + rl] = wih[(g0+rl)*CC + k0 + kk];
        }
        __syncthreads();
#pragma unroll
        for (int kk = 0; kk < 16; kk++) {
            float av[4], bv[4];
#pragma unroll
            for (int i = 0; i < 4; i++) av[i] = As[kk*65 + ty*4 + i];
#pragma unroll
            for (int j = 0; j < 4; j++) bv[j] = Bs[kk*65 + tx*4 + j];
#pragma unroll
            for (int i = 0; i < 4; i++)
#pragma unroll
                for (int j = 0; j < 4; j++)
                    acc[i][j] = fmaf(av[i], bv[j], acc[i][j]);
        }
        __syncthreads();
    }
#pragma unroll
    for (int i = 0; i < 4; i++)
#pragma unroll
        for (int j = 0; j < 4; j++)
            g_gi[(r0 + ty*4 + i)*768 + g0 + tx*4 + j] = acc[i][j];
}

// ================= persistent GRU =================
__global__ void gru_kernel(const float* __restrict__ whh, const float* __restrict__ bih,
                           const float* __restrict__ bhh, const int* __restrict__ ts) {
    __shared__ float ws[3*8*256];
    __shared__ float h_s[BB*HID];
    __shared__ float part[BB*8*2*3];
    __shared__ float bih_s[24], bhh_s[24];
    __shared__ int ts_s[BB];
    int tid = threadIdx.x;
    int j0 = blockIdx.x * 8;
    int b = tid >> 4;
    int jl = (tid >> 1) & 7;
    int half = tid & 1;

    for (int i = tid; i < 6144; i += 256) {
        int g = i >> 11, rest = i & 2047;
        int jj = rest >> 8, k = rest & 255;
        ws[i] = whh[(g*256 + j0 + jj)*256 + k];
    }
    if (tid < 24) {
        int g = tid / 8, jj = tid % 8;
        bih_s[tid] = bih[g*256 + j0 + jj];
        bhh_s[tid] = bhh[g*256 + j0 + jj];
    }
    if (tid < BB) ts_s[tid] = ts[tid];
    __syncthreads();

    for (int t = 0; t < TT; t++) {
        const float* hin = g_hbuf[t & 1];
        for (int i = tid; i < BB*HID; i += 256) h_s[i] = __ldcg(&hin[i]);
        __syncthreads();

        float ar = 0.f, az = 0.f, an = 0.f;
        const float4* h4  = (const float4*)&h_s[b*256 + half*128];
        const float4* wr4 = (const float4*)&ws[(0*8 + jl)*256 + half*128];
        const float4* wz4 = (const float4*)&ws[(1*8 + jl)*256 + half*128];
        const float4* wn4 = (const float4*)&ws[(2*8 + jl)*256 + half*128];
#pragma unroll 8
        for (int k = 0; k < 32; k++) {
            float4 hv = h4[k];
            float4 a = wr4[k]; ar += a.x*hv.x + a.y*hv.y + a.z*hv.z + a.w*hv.w;
            float4 c = wz4[k]; az += c.x*hv.x + c.y*hv.y + c.z*hv.z + c.w*hv.w;
            float4 d = wn4[k]; an += d.x*hv.x + d.y*hv.y + d.z*hv.z + d.w*hv.w;
        }
        int pb = ((b*8 + jl)*2 + half)*3;
        part[pb+0] = ar; part[pb+1] = az; part[pb+2] = an;
        __syncthreads();

        if (half == 0) {
            int p2 = ((b*8 + jl)*2)*3;
            float hr = part[p2+0] + part[p2+3] + bhh_s[jl];
            float hz = part[p2+1] + part[p2+4] + bhh_s[8+jl];
            float hn = part[p2+2] + part[p2+5] + bhh_s[16+jl];
            const float* gi = &g_gi[(t*BB + b)*768];
            float ir  = gi[j0+jl]       + bih_s[jl];
            float iz  = gi[256 + j0+jl] + bih_s[8+jl];
            float in_ = gi[512 + j0+jl] + bih_s[16+jl];
            float r  = 1.f / (1.f + expf(-(ir + hr)));
            float zg = 1.f / (1.f + expf(-(iz + hz)));
            float n  = tanhf(in_ + r*hn);
            float hprev = h_s[b*256 + j0 + jl];
            float hnew = (1.f - zg)*n + zg*hprev;
            __stcg(&g_hbuf[(t+1) & 1][b*256 + j0 + jl], hnew);
            if (t == ts_s[b]) g_ct[b*256 + j0 + jl] = hnew;
            __threadfence();
        }
        __syncthreads();
        if (tid == 0) {
            atomicAdd(&g_bar_cnt, 1u);
            unsigned target = 32u * (unsigned)(t + 1);
            while (*((volatile unsigned*)&g_bar_cnt) < target) { }
        }
        __syncthreads();
    }
}

// ================= enc gather =================
__global__ void enc_kernel(const int* __restrict__ ts, const float* __restrict__ sc,
                           const float* __restrict__ sh) {
    int k = blockIdx.x, b = blockIdx.y, d = threadIdx.x;
    int t = ts[b] + k + 1;
    float r = g_c5[(b*CC + d)*L5 + t];
    g_enc[(k*BB + b)*CC + d] = fmaxf(fmaf(r, sc[d], sh[d]), 0.f);
}

// ================= pred =================
__global__ void pred_kernel(const float* __restrict__ wk, const float* __restrict__ wkb) {
    int k = blockIdx.x, b = blockIdx.y, d = threadIdx.x;
    __shared__ float ct[HID];
    if (d < HID) ct[d] = g_ct[b*HID + d];
    __syncthreads();
    float acc = wkb[k*CC + d];
    const float4* w4 = (const float4*)&wk[(k*CC + d)*HID];
#pragma unroll 4
    for (int h = 0; h < HID/4; h++) {
        float4 w = w4[h];
        const float* c = &ct[h*4];
        acc += w.x*c[0] + w.y*c[1] + w.z*c[2] + w.w*c[3];
    }
    g_pred[(k*BB + b)*CC + d] = acc;
}

// ================= total =================
__global__ void total_kernel() {
    int k = blockIdx.x, tid = threadIdx.x;
    int b = tid >> 4, c = tid & 15;
    const float* e = &g_enc[(k*BB + b)*CC];
    const float* p = &g_pred[(k*BB + c)*CC];
    float acc = 0.f;
    for (int d = 0; d < CC; d++) acc += e[d] * p[d];
    g_total[(k*BB + b)*BB + c] = acc;
}

// ================= final =================
__global__ void final_kernel(float* __restrict__ out) {
    __shared__ float lse_s[KCPC*BB];
    __shared__ float contrib[KCPC*BB];
    __shared__ int corr[BB];
    int tid = threadIdx.x;
    if (tid < KCPC*BB) {
        int b = tid & 15;
        const float* row = &g_total[tid*BB];
        float m = row[0];
        for (int c = 1; c < BB; c++) m = fmaxf(m, row[c]);
        float s = 0.f;
        for (int c = 0; c < BB; c++) s += expf(row[c] - m);
        float lse = m + logf(s);
        lse_s[tid] = lse;
        contrib[tid] = row[b] - lse;
    }
    __syncthreads();
    if (tid == 0) {
        float s = 0.f;
        for (int i = 0; i < KCPC*BB; i++) s += contrib[i];
        out[1] = s / (-(float)(BB*KCPC));
    }
    if (tid < BB) {
        int c = tid;
        float best = -1e30f; int bi = -1;
        for (int b = 0; b < BB; b++) {
            float v = g_total[((KCPC-1)*BB + b)*BB + c] - lse_s[(KCPC-1)*BB + b];
            if (v > best) { best = v; bi = b; }
        }
        corr[tid] = (bi == c) ? 1 : 0;
    }
    __syncthreads();
    if (tid == 0) {
        int cs = 0;
        for (int i = 0; i < BB; i++) cs += corr[i];
        out[0] = (float)cs / (float)BB;
    }
    for (int i = tid; i < BB*HID; i += blockDim.x) out[2 + i] = g_hbuf[0][i];
}

// ================= launch =================
extern "C" void kernel_launch(void* const* d_in, const int* in_sizes, int n_in,
                              void* d_out, int out_size) {
    (void)in_sizes; (void)n_in; (void)out_size;
    const float* x      = (const float*)d_in[0];
    const float* hidden = (const float*)d_in[1];
    const int*   tsamp  = (const int*)d_in[3];
    const float* w1     = (const float*)d_in[4];
    const float* w2     = (const float*)d_in[5];
    const float* w345   = (const float*)d_in[6];
    const float* gamma  = (const float*)d_in[7];
    const float* beta   = (const float*)d_in[8];
    const float* wih    = (const float*)d_in[9];
    const float* whh    = (const float*)d_in[10];
    const float* bih    = (const float*)d_in[11];
    const float* bhh    = (const float*)d_in[12];
    const float* wk     = (const float*)d_in[13];
    const float* wkb    = (const float*)d_in[14];
    float* out = (float*)d_out;

    float *p_c1, *p_c2, *p_c3, *p_c4, *p_c5, *p_sc, *p_sh;
    uint32_t *p_w2b, *p_w2s, *p_w345b, *p_w345s;
    cudaGetSymbolAddress((void**)&p_c1, g_c1);
    cudaGetSymbolAddress((void**)&p_c2, g_c2);
    cudaGetSymbolAddress((void**)&p_c3, g_c3);
    cudaGetSymbolAddress((void**)&p_c4, g_c4);
    cudaGetSymbolAddress((void**)&p_c5, g_c5);
    cudaGetSymbolAddress((void**)&p_sc, g_scale);
    cudaGetSymbolAddress((void**)&p_sh, g_shift);
    cudaGetSymbolAddress((void**)&p_w2b, g_w2b);
    cudaGetSymbolAddress((void**)&p_w2s, g_w2s);
    cudaGetSymbolAddress((void**)&p_w345b, g_w345b);
    cudaGetSymbolAddress((void**)&p_w345s, g_w345s);

    cudaFuncSetAttribute(conv_mma_kernel<8,4,2,4096>,
                         cudaFuncAttributeMaxDynamicSharedMemorySize, CMM_SMEM_BYTES);
    cudaFuncSetAttribute(conv_mma_kernel<4,2,1,2048>,
                         cudaFuncAttributeMaxDynamicSharedMemorySize, CMM_SMEM_BYTES);

    init_kernel<<<16, 256>>>(hidden);
    splitw_kernel<<<(CC*2048 + 255)/256, 256>>>(w2, p_w2b, p_w2s, CC*2048);
    splitw_kernel<<<(3*CC*1024 + 255)/256, 256>>>(w345, p_w345b, p_w345s, 3*CC*1024);

    conv1_kernel<<<dim3(63, BB), 256>>>(x, w1);
    stats_kernel<<<CC, 256>>>(p_c1, gamma + 0*CC, beta + 0*CC, p_sc + 0*CC, p_sh + 0*CC, L1);

    conv_mma_kernel<8,4,2,4096><<<dim3(63, 4, BB), 256, CMM_SMEM_BYTES>>>(
        p_c1, p_w2b, p_w2s, p_sc + 0*CC, p_sh + 0*CC, p_c2, L1, L2);
    stats_kernel<<<CC, 256>>>(p_c2, gamma + 1*CC, beta + 1*CC, p_sc + 1*CC, p_sh + 1*CC, L2);

    conv_mma_kernel<4,2,1,2048><<<dim3(32, 4, BB), 256, CMM_SMEM_BYTES>>>(
        p_c2, p_w345b + 0*CC*1024, p_w345s + 0*CC*1024, p_sc + 1*CC, p_sh + 1*CC, p_c3, L2, L3);
    stats_kernel<<<CC, 256>>>(p_c3, gamma + 2*CC, beta + 2*CC, p_sc + 2*CC, p_sh + 2*CC, L3);

    conv_mma_kernel<4,2,1,2048><<<dim3(16, 4, BB), 256, CMM_SMEM_BYTES>>>(
        p_c3, p_w345b + 1*CC*1024, p_w345s + 1*CC*1024, p_sc + 2*CC, p_sh + 2*CC, p_c4, L3, L4);
    stats_kernel<<<CC, 256>>>(p_c4, gamma + 3*CC, beta + 3*CC, p_sc + 3*CC, p_sh + 3*CC, L4);

    conv_mma_kernel<4,2,1,2048><<<dim3(8, 4, BB), 256, CMM_SMEM_BYTES>>>(
        p_c4, p_w345b + 2*CC*1024, p_w345s + 2*CC*1024, p_sc + 3*CC, p_sh + 3*CC, p_c5, L4, L5);
    stats_kernel<<<CC, 256>>>(p_c5, gamma + 4*CC, beta + 4*CC, p_sc + 4*CC, p_sh + 4*CC, L5);

    buildz_kernel<<<dim3(TT, BB), CC>>>(tsamp, p_sc + 4*CC, p_sh + 4*CC);
    gi_gemm_kernel<<<dim3(125, 12), 256>>>(wih);
    gru_kernel<<<32, 256>>>(whh, bih, bhh, tsamp);

    enc_kernel<<<dim3(KCPC, BB), CC>>>(tsamp, p_sc + 4*CC, p_sh + 4*CC);
    pred_kernel<<<dim3(KCPC, BB), CC>>>(wk, wkb);
    total_kernel<<<KCPC, 256>>>();
    final_kernel<<<1, 256>>>(out);
}

// round 7
// speedup vs baseline: 1.4149x; 1.0009x over previous
#include <cuda_runtime.h>
#include <math.h>
#include <stdint.h>

#define BB 16
#define CC 512
#define L0 80000
#define L1 16000
#define L2 4000
#define L3 2000
#define L4 1000
#define L5 500
#define TT 500
#define HID 256
#define KCPC 12

// ================= device scratch =================
__device__ float g_c1[BB*CC*L1];
__device__ float g_c2[BB*CC*L2];
__device__ float g_c3[BB*CC*L3];
__device__ float g_c4[BB*CC*L4];
__device__ float g_c5[BB*CC*L5];
__device__ float g_scale[5*CC];
__device__ float g_shift[5*CC];
__device__ uint32_t g_w2b[CC*2048];      // conv2 weights, packed bf16 pairs (big)
__device__ uint32_t g_w2s[CC*2048];      // (small)
__device__ uint32_t g_w345b[3*CC*1024];
__device__ uint32_t g_w345s[3*CC*1024];
__device__ float g_z[TT*BB*CC];
__device__ float g_gi[TT*BB*768];
__device__ float g_hbuf[2][BB*HID];
__device__ float g_ct[BB*HID];
__device__ float g_enc[KCPC*BB*CC];
__device__ float g_pred[KCPC*BB*CC];
__device__ float g_total[KCPC*BB*BB];
__device__ unsigned g_bar_cnt;

// ================= helpers =================
__device__ __forceinline__ uint32_t pack_bf16x2(float hi, float lo) {
    uint32_t r;
    asm("cvt.rn.bf16x2.f32 %0, %1, %2;" : "=r"(r) : "f"(hi), "f"(lo));
    return r;
}
// split v0,v1 into packed big + packed small bf16x2 words (lo = v0)
__device__ __forceinline__ void split_pack(float v0, float v1, uint32_t& bw, uint32_t& sw) {
    bw = pack_bf16x2(v1, v0);
    float b0 = __uint_as_float(bw << 16);
    float b1 = __uint_as_float(bw & 0xffff0000u);
    sw = pack_bf16x2(v1 - b1, v0 - b0);
}
__device__ __forceinline__ void mma_bf16(float* d, const uint32_t* a, const uint32_t* bfr) {
    asm volatile(
        "mma.sync.aligned.m16n8k16.row.col.f32.bf16.bf16.f32 "
        "{%0,%1,%2,%3}, {%4,%5,%6,%7}, {%8,%9}, {%0,%1,%2,%3};"
        : "+f"(d[0]), "+f"(d[1]), "+f"(d[2]), "+f"(d[3])
        : "r"(a[0]), "r"(a[1]), "r"(a[2]), "r"(a[3]), "r"(bfr[0]), "r"(bfr[1]));
}

// ================= init =================
__global__ void init_kernel(const float* __restrict__ hidden) {
    if (blockIdx.x == 0 && threadIdx.x == 0) g_bar_cnt = 0u;
    int i = blockIdx.x * blockDim.x + threadIdx.x;
    if (i < BB*HID) g_hbuf[0][i] = hidden[i];
}

// ================= weight split: fp32 -> packed bf16 big/small =================
__global__ void splitw_kernel(const float* __restrict__ w, uint32_t* __restrict__ wb,
                              uint32_t* __restrict__ ws, int npairs) {
    int i = blockIdx.x * blockDim.x + threadIdx.x;
    if (i < npairs) {
        float v0 = w[2*i], v1 = w[2*i+1];
        uint32_t bw, sw;
        split_pack(v0, v1, bw, sw);
        wb[i] = bw;
        ws[i] = sw;
    }
}

// ================= conv1: 1->512, k=10, s=5, pad=3 =================
__global__ void conv1_kernel(const float* __restrict__ x, const float* __restrict__ w) {
    __shared__ float wsm[CC*10];
    __shared__ float xs[256*5 + 10];
    int b = blockIdx.y;
    int o0 = blockIdx.x * 256;
    int tid = threadIdx.x;
    for (int i = tid; i < CC*10; i += 256) wsm[i] = w[i];
    int p0 = o0*5 - 3;
    for (int i = tid; i < 256*5 + 10; i += 256) {
        int p = p0 + i;
        xs[i] = (p >= 0 && p < L0) ? x[b*L0 + p] : 0.f;
    }
    __syncthreads();
    int o = o0 + tid;
    if (o >= L1) return;
    float xr[10];
#pragma unroll
    for (int j = 0; j < 10; j++) xr[j] = xs[tid*5 + j];
    for (int co = 0; co < CC; co++) {
        float acc = 0.f;
#pragma unroll
        for (int j = 0; j < 10; j++) acc = fmaf(wsm[co*10 + j], xr[j], acc);
        g_c1[(b*CC + co)*L1 + o] = acc;
    }
}

// ================= per-channel batch stats =================
__global__ void stats_kernel(const float* __restrict__ raw, const float* __restrict__ gamma,
                             const float* __restrict__ beta, float* __restrict__ scale,
                             float* __restrict__ shift, int L) {
    int c = blockIdx.x;
    int tid = threadIdx.x;
    double s = 0.0, s2 = 0.0;
    for (int b = 0; b < BB; b++) {
        const float* p = raw + (size_t)(b*CC + c)*L;
        for (int l = tid; l < L; l += 256) { float v = p[l]; s += v; s2 += (double)v*v; }
    }
    __shared__ double rs[256], rs2[256];
    rs[tid] = s; rs2[tid] = s2; __syncthreads();
    for (int st = 128; st > 0; st >>= 1) {
        if (tid < st) { rs[tid] += rs[tid+st]; rs2[tid] += rs2[tid+st]; }
        __syncthreads();
    }
    if (tid == 0) {
        double n = (double)BB * (double)L;
        double mean = rs[0]/n;
        double var  = rs2[0]/n - mean*mean;
        double sc = (double)gamma[c] / sqrt(var + 1e-5);
        scale[c] = (float)sc;
        shift[c] = (float)((double)beta[c] - mean*sc);
    }
}

// ================= 3xBF16 mma.sync implicit-GEMM conv =================
// out[b][co][n] = sum_{ci,j} w[co][ci*KW+j] * relu(in[b][ci][n*S-PAD+j]*scale+shift)
// Block: 128 co x 64 n, K chunk 32 fp32 (=16 packed words). 8 warps (4m x 2n), warp tile 32x32.
// SMEM rows: 16 data words at stride 20 (conflict-free frag loads).
#define CST 20
#define OFF_AB 0
#define OFF_AS 2560
#define OFF_BB 5120
#define OFF_BS 6400
#define STG    7680
#define CMM_SMEM_BYTES (2*STG*4)

template<int KW, int S, int PAD, int KTOT>
__global__ void __launch_bounds__(256, 2)
conv_mma_kernel(const float* __restrict__ in,
                const uint32_t* __restrict__ wb, const uint32_t* __restrict__ wsp,
                const float* __restrict__ scale, const float* __restrict__ shift,
                float* __restrict__ out, int Lin, int Lout) {
    extern __shared__ uint32_t smw[];
    int tid = threadIdx.x;
    int wid = tid >> 5, lane = tid & 31;
    int g = lane >> 2, tig = lane & 3;
    int warp_m = wid >> 1, warp_n = wid & 1;
    int n0 = blockIdx.x * 64;
    int m0 = blockIdx.y * 128;
    int b  = blockIdx.z;
    constexpr int KW2 = KTOT/2;
    constexpr int NC = KTOT/32;

    float acc[2][4][4];
#pragma unroll
    for (int mt = 0; mt < 2; mt++)
#pragma unroll
        for (int nt = 0; nt < 4; nt++)
#pragma unroll
            for (int q = 0; q < 4; q++) acc[mt][nt][q] = 0.f;

    // ---- prologue: fill chunk 0 into stage 0 ----
    {
#pragma unroll
        for (int it = 0; it < 2; it++) {
            int idx = tid + it*256;
            int row = idx >> 2, q4 = idx & 3;
            size_t base4 = ((size_t)(m0+row)*KW2) >> 2;
            *(uint4*)&smw[OFF_AB + row*CST + q4*4] = ((const uint4*)wb)[base4 + q4];
            *(uint4*)&smw[OFF_AS + row*CST + q4*4] = ((const uint4*)wsp)[base4 + q4];
        }
#pragma unroll
        for (int it = 0; it < 4; it++) {
            int i = tid + it*256;
            int q = i & 15, nl = i >> 4;
            int k0 = 2*q;
            int ci = k0 / KW, j = k0 - ci*KW;
            int p = (n0+nl)*S - PAD + j;
            const float* src = in + (size_t)(b*CC + ci)*Lin;
            float sc = __ldg(&scale[ci]), sh = __ldg(&shift[ci]);
            float v0 = (p >= 0 && p < Lin) ? fmaxf(fmaf(src[p], sc, sh), 0.f) : 0.f;
            float v1 = (p+1 >= 0 && p+1 < Lin) ? fmaxf(fmaf(src[p+1], sc, sh), 0.f) : 0.f;
            uint32_t bw, sw;
            split_pack(v0, v1, bw, sw);
            smw[OFF_BB + nl*CST + q] = bw;
            smw[OFF_BS + nl*CST + q] = sw;
        }
    }
    __syncthreads();

    uint4 stAb[2], stAs[2];
    uint32_t stBb[4], stBs[4];

    for (int c = 0; c < NC; c++) {
        int s = c & 1;
        if (c + 1 < NC) {
            int kb2 = (c+1)*16;
#pragma unroll
            for (int it = 0; it < 2; it++) {
                int idx = tid + it*256;
                int row = idx >> 2, q4 = idx & 3;
                size_t base4 = ((size_t)(m0+row)*KW2 + kb2) >> 2;
                stAb[it] = ((const uint4*)wb)[base4 + q4];
                stAs[it] = ((const uint4*)wsp)[base4 + q4];
            }
            int kbase = (c+1)*32;
#pragma unroll
            for (int it = 0; it < 4; it++) {
                int i = tid + it*256;
                int q = i & 15, nl = i >> 4;
                int k0 = kbase + 2*q;
                int ci = k0 / KW, j = k0 - ci*KW;
                int p = (n0+nl)*S - PAD + j;
                const float* src = in + (size_t)(b*CC + ci)*Lin;
                float sc = __ldg(&scale[ci]), sh = __ldg(&shift[ci]);
                float v0 = (p >= 0 && p < Lin) ? fmaxf(fmaf(src[p], sc, sh), 0.f) : 0.f;
                float v1 = (p+1 >= 0 && p+1 < Lin) ? fmaxf(fmaf(src[p+1], sc, sh), 0.f) : 0.f;
                split_pack(v0, v1, stBb[it], stBs[it]);
            }
        }
        const uint32_t* Ab = smw + s*STG + OFF_AB;
        const uint32_t* As = smw + s*STG + OFF_AS;
        const uint32_t* Bbp = smw + s*STG + OFF_BB;
        const uint32_t* Bsp = smw + s*STG + OFF_BS;
#pragma unroll
        for (int ks = 0; ks < 2; ks++) {
            int kw = ks*8;
            uint32_t ab[2][4], asf[2][4];
#pragma unroll
            for (int mt = 0; mt < 2; mt++) {
                int r = warp_m*32 + mt*16 + g;
                ab[mt][0] = Ab[r*CST + kw + tig];
                ab[mt][1] = Ab[(r+8)*CST + kw + tig];
                ab[mt][2] = Ab[r*CST + kw + tig + 4];
                ab[mt][3] = Ab[(r+8)*CST + kw + tig + 4];
                asf[mt][0] = As[r*CST + kw + tig];
                asf[mt][1] = As[(r+8)*CST + kw + tig];
                asf[mt][2] = As[r*CST + kw + tig + 4];
                asf[mt][3] = As[(r+8)*CST + kw + tig + 4];
            }
            uint32_t bbf[4][2], bsf[4][2];
#pragma unroll
            for (int nt = 0; nt < 4; nt++) {
                int n = warp_n*32 + nt*8 + g;
                bbf[nt][0] = Bbp[n*CST + kw + tig];
                bbf[nt][1] = Bbp[n*CST + kw + tig + 4];
                bsf[nt][0] = Bsp[n*CST + kw + tig];
                bsf[nt][1] = Bsp[n*CST + kw + tig + 4];
            }
#pragma unroll
            for (int mt = 0; mt < 2; mt++)
#pragma unroll
                for (int nt = 0; nt < 4; nt++) {
                    mma_bf16(acc[mt][nt], ab[mt], bbf[nt]);
                    mma_bf16(acc[mt][nt], ab[mt], bsf[nt]);
                    mma_bf16(acc[mt][nt], asf[mt], bbf[nt]);
                }
        }
        if (c + 1 < NC) {
            uint32_t* dst = smw + (s^1)*STG;
#pragma unroll
            for (int it = 0; it < 2; it++) {
                int idx = tid + it*256;
                int row = idx >> 2, q4 = idx & 3;
                *(uint4*)&dst[OFF_AB + row*CST + q4*4] = stAb[it];
                *(uint4*)&dst[OFF_AS + row*CST + q4*4] = stAs[it];
            }
#pragma unroll
            for (int it = 0; it < 4; it++) {
                int i = tid + it*256;
                int q = i & 15, nl = i >> 4;
                dst[OFF_BB + nl*CST + q] = stBb[it];
                dst[OFF_BS + nl*CST + q] = stBs[it];
            }
        }
        __syncthreads();
    }

    // ---- epilogue ----
#pragma unroll
    for (int mt = 0; mt < 2; mt++) {
        int co0 = m0 + warp_m*32 + mt*16 + g;
#pragma unroll
        for (int nt = 0; nt < 4; nt++) {
            int n = n0 + warp_n*32 + nt*8 + 2*tig;
            if (n < Lout) {
                float2 v0 = make_float2(acc[mt][nt][0], acc[mt][nt][1]);
                float2 v1 = make_float2(acc[mt][nt][2], acc[mt][nt][3]);
                *(float2*)&out[(size_t)(b*CC + co0    )*Lout + n] = v0;
                *(float2*)&out[(size_t)(b*CC + co0 + 8)*Lout + n] = v1;
            }
        }
    }
}

// ================= z build =================
__global__ void buildz_kernel(const int* __restrict__ ts, const float* __restrict__ sc,
                              const float* __restrict__ sh) {
    int t = blockIdx.x, b = blockIdx.y, d = threadIdx.x;
    float v = 0.f;
    if (t <= ts[b]) {
        float r = g_c5[(b*CC + d)*L5 + t];
        v = fmaxf(fmaf(r, sc[d], sh[d]), 0.f);
    }
    g_z[(t*BB + b)*CC + d] = v;
}

// ================= GI = z @ Wih^T (8000 x 768, K=512) =================
__global__ void gi_gemm_kernel(const float* __restrict__ wih) {
    __shared__ float As[16*65];
    __shared__ float Bs[16*65];
    int tid = threadIdx.x;
    int tx = tid & 15, ty = tid >> 4;
    int r0 = blockIdx.x * 64, g0 = blockIdx.y * 64;
    float acc[4][4] = {};
    for (int k0 = 0; k0 < CC; k0 += 16) {
        for (int i = tid; i < 1024; i += 256) {
            int rl = i >> 4, kk = i & 15;
            As[kk*65 + rl] = g_z[(r0+rl)*CC + k0 + kk];
            Bs[kk*65 + rl] = wih[(g0+rl)*CC + k0 + kk];
        }
        __syncthreads();
#pragma unroll
        for (int kk = 0; kk < 16; kk++) {
            float av[4], bv[4];
#pragma unroll
            for (int i = 0; i < 4; i++) av[i] = As[kk*65 + ty*4 + i];
#pragma unroll
            for (int j = 0; j < 4; j++) bv[j] = Bs[kk*65 + tx*4 + j];
#pragma unroll
            for (int i = 0; i < 4; i++)
#pragma unroll
                for (int j = 0; j < 4; j++)
                    acc[i][j] = fmaf(av[i], bv[j], acc[i][j]);
        }
        __syncthreads();
    }
#pragma unroll
    for (int i = 0; i < 4; i++)
#pragma unroll
        for (int j = 0; j < 4; j++)
            g_gi[(r0 + ty*4 + i)*768 + g0 + tx*4 + j] = acc[i][j];
}

// ================= persistent GRU =================
__global__ void gru_kernel(const float* __restrict__ whh, const float* __restrict__ bih,
                           const float* __restrict__ bhh, const int* __restrict__ ts) {
    __shared__ float ws[3*8*256];
    __shared__ float h_s[BB*HID];
    __shared__ float part[BB*8*2*3];
    __shared__ float bih_s[24], bhh_s[24];
    __shared__ int ts_s[BB];
    int tid = threadIdx.x;
    int j0 = blockIdx.x * 8;
    int b = tid >> 4;
    int jl = (tid >> 1) & 7;
    int half = tid & 1;

    for (int i = tid; i < 6144; i += 256) {
        int g = i >> 11, rest = i & 2047;
        int jj = rest >> 8, k = rest & 255;
        ws[i] = whh[(g*256 + j0 + jj)*256 + k];
    }
    if (tid < 24) {
        int g = tid / 8, jj = tid % 8;
        bih_s[tid] = bih[g*256 + j0 + jj];
        bhh_s[tid] = bhh[g*256 + j0 + jj];
    }
    if (tid < BB) ts_s[tid] = ts[tid];
    __syncthreads();

    for (int t = 0; t < TT; t++) {
        const float* hin = g_hbuf[t & 1];
        for (int i = tid; i < BB*HID; i += 256) h_s[i] = __ldcg(&hin[i]);
        __syncthreads();

        float ar = 0.f, az = 0.f, an = 0.f;
        const float4* h4  = (const float4*)&h_s[b*256 + half*128];
        const float4* wr4 = (const float4*)&ws[(0*8 + jl)*256 + half*128];
        const float4* wz4 = (const float4*)&ws[(1*8 + jl)*256 + half*128];
        const float4* wn4 = (const float4*)&ws[(2*8 + jl)*256 + half*128];
#pragma unroll 8
        for (int k = 0; k < 32; k++) {
            float4 hv = h4[k];
            float4 a = wr4[k]; ar += a.x*hv.x + a.y*hv.y + a.z*hv.z + a.w*hv.w;
            float4 c = wz4[k]; az += c.x*hv.x + c.y*hv.y + c.z*hv.z + c.w*hv.w;
            float4 d = wn4[k]; an += d.x*hv.x + d.y*hv.y + d.z*hv.z + d.w*hv.w;
        }
        int pb = ((b*8 + jl)*2 + half)*3;
        part[pb+0] = ar; part[pb+1] = az; part[pb+2] = an;
        __syncthreads();

        if (half == 0) {
            int p2 = ((b*8 + jl)*2)*3;
            float hr = part[p2+0] + part[p2+3] + bhh_s[jl];
            float hz = part[p2+1] + part[p2+4] + bhh_s[8+jl];
            float hn = part[p2+2] + part[p2+5] + bhh_s[16+jl];
            const float* gi = &g_gi[(t*BB + b)*768];
            float ir  = gi[j0+jl]       + bih_s[jl];
            float iz  = gi[256 + j0+jl] + bih_s[8+jl];
            float in_ = gi[512 + j0+jl] + bih_s[16+jl];
            float r  = 1.f / (1.f + expf(-(ir + hr)));
            float zg = 1.f / (1.f + expf(-(iz + hz)));
            float n  = tanhf(in_ + r*hn);
            float hprev = h_s[b*256 + j0 + jl];
            float hnew = (1.f - zg)*n + zg*hprev;
            __stcg(&g_hbuf[(t+1) & 1][b*256 + j0 + jl], hnew);
            if (t == ts_s[b]) g_ct[b*256 + j0 + jl] = hnew;
            __threadfence();
        }
        __syncthreads();
        if (tid == 0) {
            atomicAdd(&g_bar_cnt, 1u);
            unsigned target = 32u * (unsigned)(t + 1);
            while (*((volatile unsigned*)&g_bar_cnt) < target) { }
        }
        __syncthreads();
    }
}

// ================= enc gather =================
__global__ void enc_kernel(const int* __restrict__ ts, const float* __restrict__ sc,
                           const float* __restrict__ sh) {
    int k = blockIdx.x, b = blockIdx.y, d = threadIdx.x;
    int t = ts[b] + k + 1;
    float r = g_c5[(b*CC + d)*L5 + t];
    g_enc[(k*BB + b)*CC + d] = fmaxf(fmaf(r, sc[d], sh[d]), 0.f);
}

// ================= pred =================
__global__ void pred_kernel(const float* __restrict__ wk, const float* __restrict__ wkb) {
    int k = blockIdx.x, b = blockIdx.y, d = threadIdx.x;
    __shared__ float ct[HID];
    if (d < HID) ct[d] = g_ct[b*HID + d];
    __syncthreads();
    float acc = wkb[k*CC + d];
    const float4* w4 = (const float4*)&wk[(k*CC + d)*HID];
#pragma unroll 4
    for (int h = 0; h < HID/4; h++) {
        float4 w = w4[h];
        const float* c = &ct[h*4];
        acc += w.x*c[0] + w.y*c[1] + w.z*c[2] + w.w*c[3];
    }
    g_pred[(k*BB + b)*CC + d] = acc;
}

// ================= total =================
__global__ void total_kernel() {
    int k = blockIdx.x, tid = threadIdx.x;
    int b = tid >> 4, c = tid & 15;
    const float* e = &g_enc[(k*BB + b)*CC];
    const float* p = &g_pred[(k*BB + c)*CC];
    float acc = 0.f;
    for (int d = 0; d < CC; d++) acc += e[d] * p[d];
    g_total[(k*BB + b)*BB + c] = acc;
}

// ================= final =================
__global__ void final_kernel(float* __restrict__ out) {
    __shared__ float lse_s[KCPC*BB];
    __shared__ float contrib[KCPC*BB];
    __shared__ int corr[BB];
    int tid = threadIdx.x;
    if (tid < KCPC*BB) {
        int b = tid & 15;
        const float* row = &g_total[tid*BB];
        float m = row[0];
        for (int c = 1; c < BB; c++) m = fmaxf(m, row[c]);
        float s = 0.f;
        for (int c = 0; c < BB; c++) s += expf(row[c] - m);
        float lse = m + logf(s);
        lse_s[tid] = lse;
        contrib[tid] = row[b] - lse;
    }
    __syncthreads();
    if (tid == 0) {
        float s = 0.f;
        for (int i = 0; i < KCPC*BB; i++) s += contrib[i];
        out[1] = s / (-(float)(BB*KCPC));
    }
    if (tid < BB) {
        int c = tid;
        float best = -1e30f; int bi = -1;
        for (int b = 0; b < BB; b++) {
            float v = g_total[((KCPC-1)*BB + b)*BB + c] - lse_s[(KCPC-1)*BB + b];
            if (v > best) { best = v; bi = b; }
        }
        corr[tid] = (bi == c) ? 1 : 0;
    }
    __syncthreads();
    if (tid == 0) {
        int cs = 0;
        for (int i = 0; i < BB; i++) cs += corr[i];
        out[0] = (float)cs / (float)BB;
    }
    for (int i = tid; i < BB*HID; i += blockDim.x) out[2 + i] = g_hbuf[0][i];
}

// ================= launch =================
extern "C" void kernel_launch(void* const* d_in, const int* in_sizes, int n_in,
                              void* d_out, int out_size) {
    (void)in_sizes; (void)n_in; (void)out_size;
    const float* x      = (const float*)d_in[0];
    const float* hidden = (const float*)d_in[1];
    const int*   tsamp  = (const int*)d_in[3];
    const float* w1     = (const float*)d_in[4];
    const float* w2     = (const float*)d_in[5];
    const float* w345   = (const float*)d_in[6];
    const float* gamma  = (const float*)d_in[7];
    const float* beta   = (const float*)d_in[8];
    const float* wih    = (const float*)d_in[9];
    const float* whh    = (const float*)d_in[10];
    const float* bih    = (const float*)d_in[11];
    const float* bhh    = (const float*)d_in[12];
    const float* wk     = (const float*)d_in[13];
    const float* wkb    = (const float*)d_in[14];
    float* out = (float*)d_out;

    float *p_c1, *p_c2, *p_c3, *p_c4, *p_c5, *p_sc, *p_sh;
    uint32_t *p_w2b, *p_w2s, *p_w345b, *p_w345s;
    cudaGetSymbolAddress((void**)&p_c1, g_c1);
    cudaGetSymbolAddress((void**)&p_c2, g_c2);
    cudaGetSymbolAddress((void**)&p_c3, g_c3);
    cudaGetSymbolAddress((void**)&p_c4, g_c4);
    cudaGetSymbolAddress((void**)&p_c5, g_c5);
    cudaGetSymbolAddress((void**)&p_sc, g_scale);
    cudaGetSymbolAddress((void**)&p_sh, g_shift);
    cudaGetSymbolAddress((void**)&p_w2b, g_w2b);
    cudaGetSymbolAddress((void**)&p_w2s, g_w2s);
    cudaGetSymbolAddress((void**)&p_w345b, g_w345b);
    cudaGetSymbolAddress((void**)&p_w345s, g_w345s);

    cudaFuncSetAttribute(conv_mma_kernel<8,4,2,4096>,
                         cudaFuncAttributeMaxDynamicSharedMemorySize, CMM_SMEM_BYTES);
    cudaFuncSetAttribute(conv_mma_kernel<4,2,1,2048>,
                         cudaFuncAttributeMaxDynamicSharedMemorySize, CMM_SMEM_BYTES);

    init_kernel<<<16, 256>>>(hidden);
    splitw_kernel<<<(CC*2048 + 255)/256, 256>>>(w2, p_w2b, p_w2s, CC*2048);
    splitw_kernel<<<(3*CC*1024 + 255)/256, 256>>>(w345, p_w345b, p_w345s, 3*CC*1024);

    conv1_kernel<<<dim3(63, BB), 256>>>(x, w1);
    stats_kernel<<<CC, 256>>>(p_c1, gamma + 0*CC, beta + 0*CC, p_sc + 0*CC, p_sh + 0*CC, L1);

    conv_mma_kernel<8,4,2,4096><<<dim3(63, 4, BB), 256, CMM_SMEM_BYTES>>>(
        p_c1, p_w2b, p_w2s, p_sc + 0*CC, p_sh + 0*CC, p_c2, L1, L2);
    stats_kernel<<<CC, 256>>>(p_c2, gamma + 1*CC, beta + 1*CC, p_sc + 1*CC, p_sh + 1*CC, L2);

    conv_mma_kernel<4,2,1,2048><<<dim3(32, 4, BB), 256, CMM_SMEM_BYTES>>>(
        p_c2, p_w345b + 0*CC*1024, p_w345s + 0*CC*1024, p_sc + 1*CC, p_sh + 1*CC, p_c3, L2, L3);
    stats_kernel<<<CC, 256>>>(p_c3, gamma + 2*CC, beta + 2*CC, p_sc + 2*CC, p_sh + 2*CC, L3);

    conv_mma_kernel<4,2,1,2048><<<dim3(16, 4, BB), 256, CMM_SMEM_BYTES>>>(
        p_c3, p_w345b + 1*CC*1024, p_w345s + 1*CC*1024, p_sc + 2*CC, p_sh + 2*CC, p_c4, L3, L4);
    stats_kernel<<<CC, 256>>>(p_c4, gamma + 3*CC, beta + 3*CC, p_sc + 3*CC, p_sh + 3*CC, L4);

    conv_mma_kernel<4,2,1,2048><<<dim3(8, 4, BB), 256, CMM_SMEM_BYTES>>>(
        p_c4, p_w345b + 2*CC*1024, p_w345s + 2*CC*1024, p_sc + 3*CC, p_sh + 3*CC, p_c5, L4, L5);
    stats_kernel<<<CC, 256>>>(p_c5, gamma + 4*CC, beta + 4*CC, p_sc + 4*CC, p_sh + 4*CC, L5);

    buildz_kernel<<<dim3(TT, BB), CC>>>(tsamp, p_sc + 4*CC, p_sh + 4*CC);
    gi_gemm_kernel<<<dim3(125, 12), 256>>>(wih);
    gru_kernel<<<32, 256>>>(whh, bih, bhh, tsamp);

    enc_kernel<<<dim3(KCPC, BB), CC>>>(tsamp, p_sc + 4*CC, p_sh + 4*CC);
    pred_kernel<<<dim3(KCPC, BB), CC>>>(wk, wkb);
    total_kernel<<<KCPC, 256>>>();
    final_kernel<<<1, 256>>>(out);
}

// round 8
// speedup vs baseline: 1.6231x; 1.1472x over previous
#include <cuda_runtime.h>
#include <math.h>
#include <stdint.h>

#define BB 16
#define CC 512
#define L0 80000
#define L1 16000
#define L2 4000
#define L3 2000
#define L4 1000
#define L5 500
#define TT 500
#define HID 256
#define KCPC 12

__device__ float g_c1[BB*CC*L1];
__device__ float g_c2[BB*CC*L2];
__device__ float g_c3[BB*CC*L3];
__device__ float g_c4[BB*CC*L4];
__device__ float g_c5[BB*CC*L5];
__device__ float g_scale[5*CC];
__device__ float g_shift[5*CC];
__device__ uint32_t g_w2b[CC*2048];
__device__ uint32_t g_w2s[CC*2048];
__device__ uint32_t g_w345b[3*CC*1024];
__device__ uint32_t g_w345s[3*CC*1024];
__device__ uint32_t g_apb[(size_t)BB*CC*8200];   // packed bf16x2 activations (big)
__device__ uint32_t g_aps[(size_t)BB*CC*8200];   // (small)
__device__ float g_z[TT*BB*CC];
__device__ float g_gi[TT*BB*768];
__device__ float g_hbuf[2][BB*HID];
__device__ float g_ct[BB*HID];
__device__ float g_enc[KCPC*BB*CC];
__device__ float g_pred[KCPC*BB*CC];
__device__ float g_total[KCPC*BB*BB];
__device__ unsigned g_bar_cnt;

__device__ __forceinline__ uint32_t smem_to_u32(const void* p) {
    uint32_t a;
    asm("{ .reg .u64 t; cvta.to.shared.u64 t, %1; cvt.u32.u64 %0, t; }" : "=r"(a) : "l"(p));
    return a;
}
__device__ __forceinline__ uint32_t pack_bf16x2(float hi, float lo) {
    uint32_t r;
    asm("cvt.rn.bf16x2.f32 %0, %1, %2;" : "=r"(r) : "f"(hi), "f"(lo));
    return r;
}
__device__ __forceinline__ void split_pack(float v0, float v1, uint32_t& bw, uint32_t& sw) {
    bw = pack_bf16x2(v1, v0);
    float b0 = __uint_as_float(bw << 16);
    float b1 = __uint_as_float(bw & 0xffff0000u);
    sw = pack_bf16x2(v1 - b1, v0 - b0);
}
__device__ __forceinline__ void mma_bf16(float* d, const uint32_t* a, const uint32_t* bfr) {
    asm volatile(
        "mma.sync.aligned.m16n8k16.row.col.f32.bf16.bf16.f32 "
        "{%0,%1,%2,%3}, {%4,%5,%6,%7}, {%8,%9}, {%0,%1,%2,%3};"
        : "+f"(d[0]), "+f"(d[1]), "+f"(d[2]), "+f"(d[3])
        : "r"(a[0]), "r"(a[1]), "r"(a[2]), "r"(a[3]), "r"(bfr[0]), "r"(bfr[1]));
}
#define MBARRIER_INIT(addr, cnt) \
    asm volatile("mbarrier.init.shared.b64 [%0], %1;" :: "r"((uint32_t)(addr)), "r"((uint32_t)(cnt)) : "memory")
#define MBARRIER_EXPECT_TX(addr, bytes) \
    asm volatile("mbarrier.arrive.expect_tx.shared.b64 _, [%0], %1;" :: "r"((uint32_t)(addr)), "r"((uint32_t)(bytes)) : "memory")
#define MBARRIER_WAIT_PARITY(addr, par) do { \
    uint32_t _m = (uint32_t)(addr); uint32_t _p = (uint32_t)(par); uint32_t _d; \
    asm volatile("{\n\t.reg .pred p;\n\tmbarrier.try_wait.parity.shared.b64 p, [%1], %2;\n\tselp.b32 %0, 1, 0, p;\n\t}" \
        : "=r"(_d) : "r"(_m), "r"(_p) : "memory"); \
    if (!_d) { \
        asm volatile("{\n\t.reg .pred P1;\n\tWL_%=:\n\tmbarrier.try_wait.parity.shared.b64 P1, [%0], %1;\n\t@P1 bra.uni WD_%=;\n\tbra.uni WL_%=;\n\tWD_%=:\n\t}" \
            :: "r"(_m), "r"(_p) : "memory"); \
    } \
} while (0)
#define BULK_G2S(dst, src, bytes, mb) \
    asm volatile("cp.async.bulk.shared::cluster.global.mbarrier::complete_tx::bytes [%0], [%1], %2, [%3];" \
        :: "r"((uint32_t)(dst)), "l"(src), "r"((uint32_t)(bytes)), "r"((uint32_t)(mb)) : "memory")

__global__ void init_kernel(const float* __restrict__ hidden) {
    if (blockIdx.x == 0 && threadIdx.x == 0) g_bar_cnt = 0u;
    int i = blockIdx.x * blockDim.x + threadIdx.x;
    if (i < BB*HID) g_hbuf[0][i] = hidden[i];
}

__global__ void splitw_kernel(const float* __restrict__ w, uint32_t* __restrict__ wb,
                              uint32_t* __restrict__ ws, int npairs) {
    int i = blockIdx.x * blockDim.x + threadIdx.x;
    if (i < npairs) {
        uint32_t bw, sw;
        split_pack(w[2*i], w[2*i+1], bw, sw);
        wb[i] = bw; ws[i] = sw;
    }
}

// activation prep: bn_relu + split into packed words; word w = elements (2w-SH, 2w-SH+1)
template<int LIN, int LPW, int SH>
__global__ void prepa_kernel(const float* __restrict__ raw, const float* __restrict__ sc,
                             const float* __restrict__ shf) {
    int ci = blockIdx.x, b = blockIdx.y;
    float s = sc[ci], t = shf[ci];
    const float* src = raw + ((size_t)b*CC + ci)*LIN;
    uint32_t* db = g_apb + ((size_t)(b*CC) + ci)*LPW;
    uint32_t* ds = g_aps + ((size_t)(b*CC) + ci)*LPW;
    for (int w = threadIdx.x; w < LPW; w += 256) {
        int p0 = 2*w - SH;
        float v0 = (p0 >= 0 && p0 < LIN) ? fmaxf(fmaf(src[p0], s, t), 0.f) : 0.f;
        float v1 = (p0+1 >= 0 && p0+1 < LIN) ? fmaxf(fmaf(src[p0+1], s, t), 0.f) : 0.f;
        uint32_t bw, sw;
        split_pack(v0, v1, bw, sw);
        db[w] = bw; ds[w] = sw;
    }
}

__global__ void conv1_kernel(const float* __restrict__ x, const float* __restrict__ w) {
    __shared__ float wsm[CC*10];
    __shared__ float xs[256*5 + 10];
    int b = blockIdx.y, o0 = blockIdx.x * 256, tid = threadIdx.x;
    for (int i = tid; i < CC*10; i += 256) wsm[i] = w[i];
    int p0 = o0*5 - 3;
    for (int i = tid; i < 256*5 + 10; i += 256) {
        int p = p0 + i;
        xs[i] = (p >= 0 && p < L0) ? x[b*L0 + p] : 0.f;
    }
    __syncthreads();
    int o = o0 + tid;
    if (o >= L1) return;
    float xr[10];
#pragma unroll
    for (int j = 0; j < 10; j++) xr[j] = xs[tid*5 + j];
    for (int co = 0; co < CC; co++) {
        float acc = 0.f;
#pragma unroll
        for (int j = 0; j < 10; j++) acc = fmaf(wsm[co*10 + j], xr[j], acc);
        g_c1[(b*CC + co)*L1 + o] = acc;
    }
}

__global__ void stats_kernel(const float* __restrict__ raw, const float* __restrict__ gamma,
                             const float* __restrict__ beta, float* __restrict__ scale,
                             float* __restrict__ shift, int L) {
    int c = blockIdx.x, tid = threadIdx.x;
    double s = 0.0, s2 = 0.0;
    for (int b = 0; b < BB; b++) {
        const float* p = raw + (size_t)(b*CC + c)*L;
        for (int l = tid; l < L; l += 256) { float v = p[l]; s += v; s2 += (double)v*v; }
    }
    __shared__ double rs[256], rs2[256];
    rs[tid] = s; rs2[tid] = s2; __syncthreads();
    for (int st = 128; st > 0; st >>= 1) {
        if (tid < st) { rs[tid] += rs[tid+st]; rs2[tid] += rs2[tid+st]; }
        __syncthreads();
    }
    if (tid == 0) {
        double n = (double)BB * (double)L;
        double mean = rs[0]/n, var = rs2[0]/n - mean*mean;
        double sc = (double)gamma[c] / sqrt(var + 1e-5);
        scale[c] = (float)sc;
        shift[c] = (float)((double)beta[c] - mean*sc);
    }
}

// ===== TMA-B 3xBF16 conv: 128co x 128n tile, 512 thr (4m x 4n warps, 32x32 warp tile) =====
template<int KW, int S, int PAD, int KTOT, int LPW, int SH, int NW>
__global__ void __launch_bounds__(512, 1)
conv_tma_kernel(const uint32_t* __restrict__ pb, const uint32_t* __restrict__ ps,
                const uint32_t* __restrict__ wb, const uint32_t* __restrict__ wsp,
                float* __restrict__ out, int Lout) {
    constexpr int CI = 32/KW, NC = KTOT/32, KW2 = KTOT/2;
    constexpr int ABUFW = 128*20, ASTW = 2*ABUFW, BSTW = 2*CI*NW, STGW = ASTW + BSTW;
    constexpr int SPANW = (127*S + KW)/2 + 1;
    extern __shared__ __align__(128) uint32_t smw[];
    uint32_t sbase = smem_to_u32(smw);
    int tid = threadIdx.x, wid = tid >> 5, lane = tid & 31;
    int g = lane >> 2, tig = lane & 3;
    int warp_m = wid >> 2, warp_n = wid & 3;
    int n0 = blockIdx.x*128, m0 = blockIdx.y*128, b = blockIdx.z;
    int p0 = n0*S - PAD;
    int w0 = (p0 + SH) >> 1, wa = w0 & ~3, lead = w0 - wa;
    int nw = (lead + SPANW + 3) & ~3;
    uint32_t txb = (uint32_t)(2*CI*nw*4);

    if (tid == 0) { MBARRIER_INIT(sbase, 1); MBARRIER_INIT(sbase + 8, 1); }
    __syncthreads();
    asm volatile("fence.proxy.async;" ::: "memory");

    auto issueB = [&](int c, int s) {
        uint32_t mb = sbase + s*8;
        uint32_t st = sbase + 128 + (uint32_t)(s*STGW + ASTW)*4;
        MBARRIER_EXPECT_TX(mb, txb);
        for (int r = 0; r < CI; r++) {
            size_t so = ((size_t)(b*CC) + (size_t)c*CI + r)*LPW + (size_t)wa;
            BULK_G2S(st + (uint32_t)(r*NW)*4,        pb + so, nw*4, mb);
            BULK_G2S(st + (uint32_t)((CI+r)*NW)*4,   ps + so, nw*4, mb);
        }
    };
    if (tid == 0) { issueB(0, 0); issueB(1, 1); }

    // A chunk 0 direct: row=tid>>2, q4=tid&3
    {
        int row = tid >> 2, q4 = tid & 3;
        size_t b4 = ((size_t)(m0+row)*KW2) >> 2;
        uint4 vb = ((const uint4*)wb)[b4 + q4];
        uint4 vs = ((const uint4*)wsp)[b4 + q4];
        *(uint4*)&smw[32 + row*20 + q4*4] = vb;
        *(uint4*)&smw[32 + ABUFW + row*20 + q4*4] = vs;
    }
    __syncthreads();

    float acc[2][4][4];
#pragma unroll
    for (int mt = 0; mt < 2; mt++)
#pragma unroll
        for (int nt = 0; nt < 4; nt++)
#pragma unroll
            for (int q = 0; q < 4; q++) acc[mt][nt][q] = 0.f;

    uint4 stAb, stAs;
    int ph[2] = {0, 0};
    int row = tid >> 2, q4 = tid & 3;

    for (int c = 0; c < NC; c++) {
        int s = c & 1;
        if (c + 1 < NC) {
            size_t b4 = ((size_t)(m0+row)*KW2 + (size_t)(c+1)*16) >> 2;
            stAb = ((const uint4*)wb)[b4 + q4];
            stAs = ((const uint4*)wsp)[b4 + q4];
        }
        MBARRIER_WAIT_PARITY(sbase + s*8, ph[s]); ph[s] ^= 1;
        int Ab = 32 + s*STGW;
        int Bb = 32 + s*STGW + ASTW;
#pragma unroll
        for (int ks = 0; ks < 2; ks++) {
            int kw = ks*8;
            uint32_t ab[2][4], af[2][4];
#pragma unroll
            for (int mt = 0; mt < 2; mt++) {
                int r = warp_m*32 + mt*16 + g;
                ab[mt][0] = smw[Ab + r*20 + kw + tig];
                ab[mt][1] = smw[Ab + (r+8)*20 + kw + tig];
                ab[mt][2] = smw[Ab + r*20 + kw + tig + 4];
                ab[mt][3] = smw[Ab + (r+8)*20 + kw + tig + 4];
                af[mt][0] = smw[Ab + ABUFW + r*20 + kw + tig];
                af[mt][1] = smw[Ab + ABUFW + (r+8)*20 + kw + tig];
                af[mt][2] = smw[Ab + ABUFW + r*20 + kw + tig + 4];
                af[mt][3] = smw[Ab + ABUFW + (r+8)*20 + kw + tig + 4];
            }
            uint32_t bbf[4][2], bsf[4][2];
#pragma unroll
            for (int nt = 0; nt < 4; nt++) {
                int nl = warp_n*32 + nt*8 + g;
#pragma unroll
                for (int j = 0; j < 2; j++) {
                    int kk = ks*16 + 8*j + 2*tig;
                    int cil = kk / KW, jj = kk - cil*KW;
                    int wd = Bb + cil*NW + lead + nl*(S/2) + (jj >> 1);
                    bbf[nt][j] = smw[wd];
                    bsf[nt][j] = smw[wd + CI*NW];
                }
            }
#pragma unroll
            for (int mt = 0; mt < 2; mt++)
#pragma unroll
                for (int nt = 0; nt < 4; nt++) {
                    mma_bf16(acc[mt][nt], ab[mt], bbf[nt]);
                    mma_bf16(acc[mt][nt], ab[mt], bsf[nt]);
                    mma_bf16(acc[mt][nt], af[mt], bbf[nt]);
                }
        }
        if (c + 1 < NC) {
            int d = 32 + (s^1)*STGW;
            *(uint4*)&smw[d + row*20 + q4*4] = stAb;
            *(uint4*)&smw[d + ABUFW + row*20 + q4*4] = stAs;
        }
        __syncthreads();
        if (tid == 0 && c + 2 < NC) issueB(c + 2, s);
    }

#pragma unroll
    for (int mt = 0; mt < 2; mt++) {
        int co0 = m0 + warp_m*32 + mt*16 + g;
#pragma unroll
        for (int nt = 0; nt < 4; nt++) {
            int n = n0 + warp_n*32 + nt*8 + 2*tig;
            if (n < Lout) {
                *(float2*)&out[(size_t)(b*CC + co0)*Lout + n]     = make_float2(acc[mt][nt][0], acc[mt][nt][1]);
                *(float2*)&out[(size_t)(b*CC + co0 + 8)*Lout + n] = make_float2(acc[mt][nt][2], acc[mt][nt][3]);
            }
        }
    }
}

__global__ void buildz_kernel(const int* __restrict__ ts, const float* __restrict__ sc,
                              const float* __restrict__ sh) {
    int t = blockIdx.x, b = blockIdx.y, d = threadIdx.x;
    float v = 0.f;
    if (t <= ts[b]) {
        float r = g_c5[(b*CC + d)*L5 + t];
        v = fmaxf(fmaf(r, sc[d], sh[d]), 0.f);
    }
    g_z[(t*BB + b)*CC + d] = v;
}

__global__ void gi_gemm_kernel(const float* __restrict__ wih) {
    __shared__ float As[16*65];
    __shared__ float Bs[16*65];
    int tid = threadIdx.x, tx = tid & 15, ty = tid >> 4;
    int r0 = blockIdx.x * 64, g0 = blockIdx.y * 64;
    float acc[4][4] = {};
    for (int k0 = 0; k0 < CC; k0 += 16) {
        for (int i = tid; i < 1024; i += 256) {
            int rl = i >> 4, kk = i & 15;
            As[kk*65 + rl] = g_z[(r0+rl)*CC + k0 + kk];
            Bs[kk*65 + rl] = wih[(g0+rl)*CC + k0 + kk];
        }
        __syncthreads();
#pragma unroll
        for (int kk = 0; kk < 16; kk++) {
            float av[4], bv[4];
#pragma unroll
            for (int i = 0; i < 4; i++) av[i] = As[kk*65 + ty*4 + i];
#pragma unroll
            for (int j = 0; j < 4; j++) bv[j] = Bs[kk*65 + tx*4 + j];
#pragma unroll
            for (int i = 0; i < 4; i++)
#pragma unroll
                for (int j = 0; j < 4; j++)
                    acc[i][j] = fmaf(av[i], bv[j], acc[i][j]);
        }
        __syncthreads();
    }
#pragma unroll
    for (int i = 0; i < 4; i++)
#pragma unroll
        for (int j = 0; j < 4; j++)
            g_gi[(r0 + ty*4 + i)*768 + g0 + tx*4 + j] = acc[i][j];
}

__global__ void gru_kernel(const float* __restrict__ whh, const float* __restrict__ bih,
                           const float* __restrict__ bhh, const int* __restrict__ ts) {
    __shared__ float ws[3*8*256];
    __shared__ float h_s[BB*HID];
    __shared__ float part[BB*8*2*3];
    __shared__ float bih_s[24], bhh_s[24];
    __shared__ int ts_s[BB];
    int tid = threadIdx.x, j0 = blockIdx.x * 8;
    int b = tid >> 4, jl = (tid >> 1) & 7, half = tid & 1;
    for (int i = tid; i < 6144; i += 256) {
        int g = i >> 11, rest = i & 2047, jj = rest >> 8, k = rest & 255;
        ws[i] = whh[(g*256 + j0 + jj)*256 + k];
    }
    if (tid < 24) {
        int g = tid / 8, jj = tid % 8;
        bih_s[tid] = bih[g*256 + j0 + jj];
        bhh_s[tid] = bhh[g*256 + j0 + jj];
    }
    if (tid < BB) ts_s[tid] = ts[tid];
    __syncthreads();
    for (int t = 0; t < TT; t++) {
        const float* hin = g_hbuf[t & 1];
        for (int i = tid; i < BB*HID; i += 256) h_s[i] = __ldcg(&hin[i]);
        __syncthreads();
        float ar = 0.f, az = 0.f, an = 0.f;
        const float4* h4  = (const float4*)&h_s[b*256 + half*128];
        const float4* wr4 = (const float4*)&ws[(0*8 + jl)*256 + half*128];
        const float4* wz4 = (const float4*)&ws[(1*8 + jl)*256 + half*128];
        const float4* wn4 = (const float4*)&ws[(2*8 + jl)*256 + half*128];
#pragma unroll 8
        for (int k = 0; k < 32; k++) {
            float4 hv = h4[k];
            float4 a = wr4[k]; ar += a.x*hv.x + a.y*hv.y + a.z*hv.z + a.w*hv.w;
            float4 c = wz4[k]; az += c.x*hv.x + c.y*hv.y + c.z*hv.z + c.w*hv.w;
            float4 d = wn4[k]; an += d.x*hv.x + d.y*hv.y + d.z*hv.z + d.w*hv.w;
        }
        int pb = ((b*8 + jl)*2 + half)*3;
        part[pb+0] = ar; part[pb+1] = az; part[pb+2] = an;
        __syncthreads();
        if (half == 0) {
            int p2 = ((b*8 + jl)*2)*3;
            float hr = part[p2+0] + part[p2+3] + bhh_s[jl];
            float hz = part[p2+1] + part[p2+4] + bhh_s[8+jl];
            float hn = part[p2+2] + part[p2+5] + bhh_s[16+jl];
            const float* gi = &g_gi[(t*BB + b)*768];
            float ir  = gi[j0+jl]       + bih_s[jl];
            float iz  = gi[256 + j0+jl] + bih_s[8+jl];
            float in_ = gi[512 + j0+jl] + bih_s[16+jl];
            float r  = 1.f / (1.f + expf(-(ir + hr)));
            float zg = 1.f / (1.f + expf(-(iz + hz)));
            float n  = tanhf(in_ + r*hn);
            float hprev = h_s[b*256 + j0 + jl];
            float hnew = (1.f - zg)*n + zg*hprev;
            __stcg(&g_hbuf[(t+1) & 1][b*256 + j0 + jl], hnew);
            if (t == ts_s[b]) g_ct[b*256 + j0 + jl] = hnew;
            __threadfence();
        }
        __syncthreads();
        if (tid == 0) {
            atomicAdd(&g_bar_cnt, 1u);
            unsigned target = 32u * (unsigned)(t + 1);
            while (*((volatile unsigned*)&g_bar_cnt) < target) { }
        }
        __syncthreads();
    }
}

__global__ void enc_kernel(const int* __restrict__ ts, const float* __restrict__ sc,
                           const float* __restrict__ sh) {
    int k = blockIdx.x, b = blockIdx.y, d = threadIdx.x;
    int t = ts[b] + k + 1;
    float r = g_c5[(b*CC + d)*L5 + t];
    g_enc[(k*BB + b)*CC + d] = fmaxf(fmaf(r, sc[d], sh[d]), 0.f);
}

__global__ void pred_kernel(const float* __restrict__ wk, const float* __restrict__ wkb) {
    int k = blockIdx.x, b = blockIdx.y, d = threadIdx.x;
    __shared__ float ct[HID];
    if (d < HID) ct[d] = g_ct[b*HID + d];
    __syncthreads();
    float acc = wkb[k*CC + d];
    const float4* w4 = (const float4*)&wk[(k*CC + d)*HID];
#pragma unroll 4
    for (int h = 0; h < HID/4; h++) {
        float4 w = w4[h];
        const float* c = &ct[h*4];
        acc += w.x*c[0] + w.y*c[1] + w.z*c[2] + w.w*c[3];
    }
    g_pred[(k*BB + b)*CC + d] = acc;
}

__global__ void total_kernel() {
    int k = blockIdx.x, tid = threadIdx.x;
    int b = tid >> 4, c = tid & 15;
    const float* e = &g_enc[(k*BB + b)*CC];
    const float* p = &g_pred[(k*BB + c)*CC];
    float acc = 0.f;
    for (int d = 0; d < CC; d++) acc += e[d] * p[d];
    g_total[(k*BB + b)*BB + c] = acc;
}

__global__ void final_kernel(float* __restrict__ out) {
    __shared__ float lse_s[KCPC*BB];
    __shared__ float contrib[KCPC*BB];
    __shared__ int corr[BB];
    int tid = threadIdx.x;
    if (tid < KCPC*BB) {
        int b = tid & 15;
        const float* row = &g_total[tid*BB];
        float m = row[0];
        for (int c = 1; c < BB; c++) m = fmaxf(m, row[c]);
        float s = 0.f;
        for (int c = 0; c < BB; c++) s += expf(row[c] - m);
        float lse = m + logf(s);
        lse_s[tid] = lse;
        contrib[tid] = row[b] - lse;
    }
    __syncthreads();
    if (tid == 0) {
        float s = 0.f;
        for (int i = 0; i < KCPC*BB; i++) s += contrib[i];
        out[1] = s / (-(float)(BB*KCPC));
    }
    if (tid < BB) {
        int c = tid;
        float best = -1e30f; int bi = -1;
        for (int b = 0; b < BB; b++) {
            float v = g_total[((KCPC-1)*BB + b)*BB + c] - lse_s[(KCPC-1)*BB + b];
            if (v > best) { best = v; bi = b; }
        }
        corr[tid] = (bi == c) ? 1 : 0;
    }
    __syncthreads();
    if (tid == 0) {
        int cs = 0;
        for (int i = 0; i < BB; i++) cs += corr[i];
        out[0] = (float)cs / (float)BB;
    }
    for (int i = tid; i < BB*HID; i += blockDim.x) out[2 + i] = g_hbuf[0][i];
}

extern "C" void kernel_launch(void* const* d_in, const int* in_sizes, int n_in,
                              void* d_out, int out_size) {
    (void)in_sizes; (void)n_in; (void)out_size;
    const float* x      = (const float*)d_in[0];
    const float* hidden = (const float*)d_in[1];
    const int*   tsamp  = (const int*)d_in[3];
    const float* w1     = (const float*)d_in[4];
    const float* w2     = (const float*)d_in[5];
    const float* w345   = (const float*)d_in[6];
    const float* gamma  = (const float*)d_in[7];
    const float* beta   = (const float*)d_in[8];
    const float* wih    = (const float*)d_in[9];
    const float* whh    = (const float*)d_in[10];
    const float* bih    = (const float*)d_in[11];
    const float* bhh    = (const float*)d_in[12];
    const float* wk     = (const float*)d_in[13];
    const float* wkb    = (const float*)d_in[14];
    float* out = (float*)d_out;

    float *p_c1, *p_c2, *p_c3, *p_c4, *p_c5, *p_sc, *p_sh;
    uint32_t *p_w2b, *p_w2s, *p_w345b, *p_w345s, *p_apb, *p_aps;
    cudaGetSymbolAddress((void**)&p_c1, g_c1);
    cudaGetSymbolAddress((void**)&p_c2, g_c2);
    cudaGetSymbolAddress((void**)&p_c3, g_c3);
    cudaGetSymbolAddress((void**)&p_c4, g_c4);
    cudaGetSymbolAddress((void**)&p_c5, g_c5);
    cudaGetSymbolAddress((void**)&p_sc, g_scale);
    cudaGetSymbolAddress((void**)&p_sh, g_shift);
    cudaGetSymbolAddress((void**)&p_w2b, g_w2b);
    cudaGetSymbolAddress((void**)&p_w2s, g_w2s);
    cudaGetSymbolAddress((void**)&p_w345b, g_w345b);
    cudaGetSymbolAddress((void**)&p_w345s, g_w345s);
    cudaGetSymbolAddress((void**)&p_apb, g_apb);
    cudaGetSymbolAddress((void**)&p_aps, g_aps);

    const int SM_L2 = (32 + 2*(2*128*20 + 2*4*264))*4;   // 57984
    const int SM_L345 = (32 + 2*(2*128*20 + 2*8*136))*4; // 58496
    cudaFuncSetAttribute(conv_tma_kernel<8,4,2,4096,8200,2,264>,
                         cudaFuncAttributeMaxDynamicSharedMemorySize, SM_L2);
    cudaFuncSetAttribute(conv_tma_kernel<4,2,1,2048,2056,1,136>,
                         cudaFuncAttributeMaxDynamicSharedMemorySize, SM_L345);
    cudaFuncSetAttribute(conv_tma_kernel<4,2,1,2048,1032,1,136>,
                         cudaFuncAttributeMaxDynamicSharedMemorySize, SM_L345);
    cudaFuncSetAttribute(conv_tma_kernel<4,2,1,2048,520,1,136>,
                         cudaFuncAttributeMaxDynamicSharedMemorySize, SM_L345);

    init_kernel<<<16, 256>>>(hidden);
    splitw_kernel<<<(CC*2048 + 255)/256, 256>>>(w2, p_w2b, p_w2s, CC*2048);
    splitw_kernel<<<(3*CC*1024 + 255)/256, 256>>>(w345, p_w345b, p_w345s, 3*CC*1024);

    conv1_kernel<<<dim3(63, BB), 256>>>(x, w1);
    stats_kernel<<<CC, 256>>>(p_c1, gamma, beta, p_sc, p_sh, L1);
    prepa_kernel<L1,8200,2><<<dim3(CC, BB), 256>>>(p_c1, p_sc, p_sh);

    conv_tma_kernel<8,4,2,4096,8200,2,264><<<dim3(32, 4, BB), 512, SM_L2>>>(
        p_apb, p_aps, p_w2b, p_w2s, p_c2, L2);
    stats_kernel<<<CC, 256>>>(p_c2, gamma + CC, beta + CC, p_sc + CC, p_sh + CC, L2);
    prepa_kernel<L2,2056,1><<<dim3(CC, BB), 256>>>(p_c2, p_sc + CC, p_sh + CC);

    conv_tma_kernel<4,2,1,2048,2056,1,136><<<dim3(16, 4, BB), 512, SM_L345>>>(
        p_apb, p_aps, p_w345b + 0*CC*1024, p_w345s + 0*CC*1024, p_c3, L3);
    stats_kernel<<<CC, 256>>>(p_c3, gamma + 2*CC, beta + 2*CC, p_sc + 2*CC, p_sh + 2*CC, L3);
    prepa_kernel<L3,1032,1><<<dim3(CC, BB), 256>>>(p_c3, p_sc + 2*CC, p_sh + 2*CC);

    conv_tma_kernel<4,2,1,2048,1032,1,136><<<dim3(8, 4, BB), 512, SM_L345>>>(
        p_apb, p_aps, p_w345b + 1*CC*1024, p_w345s + 1*CC*1024, p_c4, L4);
    stats_kernel<<<CC, 256>>>(p_c4, gamma + 3*CC, beta + 3*CC, p_sc + 3*CC, p_sh + 3*CC, L4);
    prepa_kernel<L4,520,1><<<dim3(CC, BB), 256>>>(p_c4, p_sc + 3*CC, p_sh + 3*CC);

    conv_tma_kernel<4,2,1,2048,520,1,136><<<dim3(4, 4, BB), 512, SM_L345>>>(
        p_apb, p_aps, p_w345b + 2*CC*1024, p_w345s + 2*CC*1024, p_c5, L5);
    stats_kernel<<<CC, 256>>>(p_c5, gamma + 4*CC, beta + 4*CC, p_sc + 4*CC, p_sh + 4*CC, L5);

    buildz_kernel<<<dim3(TT, BB), CC>>>(tsamp, p_sc + 4*CC, p_sh + 4*CC);
    gi_gemm_kernel<<<dim3(125, 12), 256>>>(wih);
    gru_kernel<<<32, 256>>>(whh, bih, bhh, tsamp);

    enc_kernel<<<dim3(KCPC, BB), CC>>>(tsamp, p_sc + 4*CC, p_sh + 4*CC);
    pred_kernel<<<dim3(KCPC, BB), CC>>>(wk, wkb);
    total_kernel<<<KCPC, 256>>>();
    final_kernel<<<1, 256>>>(out);
}

// round 10
// speedup vs baseline: 1.7600x; 1.0843x over previous
#include <cuda_runtime.h>
#include <math.h>
#include <stdint.h>

#define BB 16
#define CC 512
#define L0 80000
#define L1 16000
#define L2 4000
#define L3 2000
#define L4 1000
#define L5 500
#define TT 500
#define HID 256
#define KCPC 12

__device__ float g_c1[BB*CC*L1];
__device__ float g_c2[BB*CC*L2];
__device__ float g_c3[BB*CC*L3];
__device__ float g_c4[BB*CC*L4];
__device__ float g_c5[BB*CC*L5];
__device__ float g_scale[5*CC];
__device__ float g_shift[5*CC];
__device__ uint32_t g_w2b[1310720];     // padded chunk-major weights: [128ch][4mt][128][20]
__device__ uint32_t g_w2s[1310720];
__device__ uint32_t g_w345b[3*655360];  // [64ch][4mt][128][20] per layer
__device__ uint32_t g_w345s[3*655360];
__device__ uint32_t g_apb[(size_t)BB*CC*8200];
__device__ uint32_t g_aps[(size_t)BB*CC*8200];
__device__ float g_z[TT*BB*CC];
__device__ float g_gi[TT*BB*768];
__device__ float g_hbuf[2][BB*HID];
__device__ float g_ct[BB*HID];
__device__ float g_enc[KCPC*BB*CC];
__device__ float g_pred[KCPC*BB*CC];
__device__ float g_total[KCPC*BB*BB];
__device__ unsigned g_bar_cnt;

__device__ __forceinline__ uint32_t smem_to_u32(const void* p) {
    uint32_t a;
    asm("{ .reg .u64 t; cvta.to.shared.u64 t, %1; cvt.u32.u64 %0, t; }" : "=r"(a) : "l"(p));
    return a;
}
__device__ __forceinline__ uint32_t pack_bf16x2(float hi, float lo) {
    uint32_t r;
    asm("cvt.rn.bf16x2.f32 %0, %1, %2;" : "=r"(r) : "f"(hi), "f"(lo));
    return r;
}
__device__ __forceinline__ void split_pack(float v0, float v1, uint32_t& bw, uint32_t& sw) {
    bw = pack_bf16x2(v1, v0);
    float b0 = __uint_as_float(bw << 16);
    float b1 = __uint_as_float(bw & 0xffff0000u);
    sw = pack_bf16x2(v1 - b1, v0 - b0);
}
__device__ __forceinline__ void mma_bf16(float* d, const uint32_t* a, const uint32_t* bfr) {
    asm volatile(
        "mma.sync.aligned.m16n8k16.row.col.f32.bf16.bf16.f32 "
        "{%0,%1,%2,%3}, {%4,%5,%6,%7}, {%8,%9}, {%0,%1,%2,%3};"
        : "+f"(d[0]), "+f"(d[1]), "+f"(d[2]), "+f"(d[3])
        : "r"(a[0]), "r"(a[1]), "r"(a[2]), "r"(a[3]), "r"(bfr[0]), "r"(bfr[1]));
}
#define MBARRIER_INIT(addr, cnt) \
    asm volatile("mbarrier.init.shared.b64 [%0], %1;" :: "r"((uint32_t)(addr)), "r"((uint32_t)(cnt)) : "memory")
#define MBARRIER_EXPECT_TX(addr, bytes) \
    asm volatile("mbarrier.arrive.expect_tx.shared.b64 _, [%0], %1;" :: "r"((uint32_t)(addr)), "r"((uint32_t)(bytes)) : "memory")
#define MBARRIER_WAIT_PARITY(addr, par) do { \
    uint32_t _m = (uint32_t)(addr); uint32_t _p = (uint32_t)(par); uint32_t _d; \
    asm volatile("{\n\t.reg .pred p;\n\tmbarrier.try_wait.parity.shared.b64 p, [%1], %2;\n\tselp.b32 %0, 1, 0, p;\n\t}" \
        : "=r"(_d) : "r"(_m), "r"(_p) : "memory"); \
    if (!_d) { \
        asm volatile("{\n\t.reg .pred P1;\n\tWL_%=:\n\tmbarrier.try_wait.parity.shared.b64 P1, [%0], %1;\n\t@P1 bra.uni WD_%=;\n\tbra.uni WL_%=;\n\tWD_%=:\n\t}" \
            :: "r"(_m), "r"(_p) : "memory"); \
    } \
} while (0)
#define BULK_G2S(dst, src, bytes, mb) \
    asm volatile("cp.async.bulk.shared::cluster.global.mbarrier::complete_tx::bytes [%0], [%1], %2, [%3];" \
        :: "r"((uint32_t)(dst)), "l"(src), "r"((uint32_t)(bytes)), "r"((uint32_t)(mb)) : "memory")

__global__ void init_kernel(const float* __restrict__ hidden) {
    if (blockIdx.x == 0 && threadIdx.x == 0) g_bar_cnt = 0u;
    int i = blockIdx.x * blockDim.x + threadIdx.x;
    if (i < BB*HID) g_hbuf[0][i] = hidden[i];
}

// weights -> padded chunk-major smem image: dst[((chunk*4+mt)*128+row)*20+word]
template<int KTOT>
__global__ void prepw_kernel(const float* __restrict__ w, uint32_t* __restrict__ wb,
                             uint32_t* __restrict__ ws) {
    int i = blockIdx.x*256 + threadIdx.x;
    if (i >= 512*(KTOT/2)) return;
    int co = i / (KTOT/2), wp = i % (KTOT/2);
    int chunk = wp >> 4, word = wp & 15;
    uint32_t bw, sw;
    split_pack(w[(size_t)co*KTOT + 2*wp], w[(size_t)co*KTOT + 2*wp + 1], bw, sw);
    size_t d = (((size_t)chunk*4 + (co>>7))*128 + (co&127))*20 + word;
    wb[d] = bw; ws[d] = sw;
}

template<int LIN, int LPW, int SH>
__global__ void prepa_kernel(const float* __restrict__ raw, const float* __restrict__ sc,
                             const float* __restrict__ shf) {
    int ci = blockIdx.x, b = blockIdx.y;
    float s = sc[ci], t = shf[ci];
    const float* src = raw + ((size_t)b*CC + ci)*LIN;
    uint32_t* db = g_apb + ((size_t)(b*CC) + ci)*LPW;
    uint32_t* ds = g_aps + ((size_t)(b*CC) + ci)*LPW;
    for (int w = threadIdx.x; w < LPW; w += 256) {
        int p0 = 2*w - SH;
        float v0 = (p0 >= 0 && p0 < LIN) ? fmaxf(fmaf(src[p0], s, t), 0.f) : 0.f;
        float v1 = (p0+1 >= 0 && p0+1 < LIN) ? fmaxf(fmaf(src[p0+1], s, t), 0.f) : 0.f;
        uint32_t bw, sw;
        split_pack(v0, v1, bw, sw);
        db[w] = bw; ds[w] = sw;
    }
}

__global__ void conv1_kernel(const float* __restrict__ x, const float* __restrict__ w) {
    __shared__ float wsm[CC*10];
    __shared__ float xs[256*5 + 10];
    int b = blockIdx.y, o0 = blockIdx.x * 256, tid = threadIdx.x;
    for (int i = tid; i < CC*10; i += 256) wsm[i] = w[i];
    int p0 = o0*5 - 3;
    for (int i = tid; i < 256*5 + 10; i += 256) {
        int p = p0 + i;
        xs[i] = (p >= 0 && p < L0) ? x[b*L0 + p] : 0.f;
    }
    __syncthreads();
    int o = o0 + tid;
    if (o >= L1) return;
    float xr[10];
#pragma unroll
    for (int j = 0; j < 10; j++) xr[j] = xs[tid*5 + j];
    for (int co = 0; co < CC; co++) {
        float acc = 0.f;
#pragma unroll
        for (int j = 0; j < 10; j++) acc = fmaf(wsm[co*10 + j], xr[j], acc);
        g_c1[(b*CC + co)*L1 + o] = acc;
    }
}

__global__ void stats_kernel(const float* __restrict__ raw, const float* __restrict__ gamma,
                             const float* __restrict__ beta, float* __restrict__ scale,
                             float* __restrict__ shift, int L) {
    int c = blockIdx.x, tid = threadIdx.x;
    double s = 0.0, s2 = 0.0;
    for (int b = 0; b < BB; b++) {
        const float* p = raw + (size_t)(b*CC + c)*L;
        for (int l = tid; l < L; l += 256) { float v = p[l]; s += v; s2 += (double)v*v; }
    }
    __shared__ double rs[256], rs2[256];
    rs[tid] = s; rs2[tid] = s2; __syncthreads();
    for (int st = 128; st > 0; st >>= 1) {
        if (tid < st) { rs[tid] += rs[tid+st]; rs2[tid] += rs2[tid+st]; }
        __syncthreads();
    }
    if (tid == 0) {
        double n = (double)BB * (double)L;
        double mean = rs[0]/n, var = rs2[0]/n - mean*mean;
        double sc = (double)gamma[c] / sqrt(var + 1e-5);
        scale[c] = (float)sc;
        shift[c] = (float)((double)beta[c] - mean*sc);
    }
}

// ===== all-TMA 3xBF16 conv: 128co x 64n tile, 256 thr, 2 CTA/SM =====
template<int KW, int S, int KTOT, int LPW, int NW>
__global__ void __launch_bounds__(256, 2)
conv_tc_kernel(const uint32_t* __restrict__ pb, const uint32_t* __restrict__ ps,
               const uint32_t* __restrict__ wb, const uint32_t* __restrict__ wsp,
               float* __restrict__ out, int Lout) {
    constexpr int CI = 32/KW, NC = KTOT/32;
    constexpr int AW = 2560;                 // 128 rows x 20 words
    constexpr int ASTW = 2*AW;
    constexpr int BSTW = 2*CI*NW;
    constexpr int STGW = ASTW + BSTW;
    constexpr int HDR = 32;
    extern __shared__ __align__(128) uint32_t smw[];
    uint32_t sbase = smem_to_u32(smw);
    int tid = threadIdx.x, wid = tid >> 5, lane = tid & 31;
    int g = lane >> 2, tig = lane & 3;
    int warp_m = wid >> 1, warp_n = wid & 1;
    int n0 = blockIdx.x*64, b = blockIdx.z;
    uint32_t txb = (uint32_t)(2*10240 + 2*CI*NW*4);

    if (tid == 0) { MBARRIER_INIT(sbase, 1); MBARRIER_INIT(sbase + 8, 1); }
    __syncthreads();
    asm volatile("fence.proxy.async;" ::: "memory");

    auto issue = [&](int c, int s) {
        uint32_t mb = sbase + s*8;
        uint32_t ast = sbase + (uint32_t)(HDR + s*STGW)*4;
        uint32_t bst = ast + ASTW*4;
        MBARRIER_EXPECT_TX(mb, txb);
        size_t aoff = ((size_t)c*4 + blockIdx.y)*AW;
        BULK_G2S(ast,          wb  + aoff, 10240, mb);
        BULK_G2S(ast + AW*4,   wsp + aoff, 10240, mb);
        int base = n0*(S/2);
        for (int r = 0; r < CI; r++) {
            size_t so = ((size_t)(b*CC) + (size_t)c*CI + r)*LPW + base;
            BULK_G2S(bst + (uint32_t)(r*NW)*4,      pb + so, NW*4, mb);
            BULK_G2S(bst + (uint32_t)((CI+r)*NW)*4, ps + so, NW*4, mb);
        }
    };
    if (tid == 0) { issue(0, 0); issue(1, 1); }

    float acc[2][4][4];
#pragma unroll
    for (int mt = 0; mt < 2; mt++)
#pragma unroll
        for (int nt = 0; nt < 4; nt++)
#pragma unroll
            for (int q = 0; q < 4; q++) acc[mt][nt][q] = 0.f;

    int ph[2] = {0, 0};
    for (int c = 0; c < NC; c++) {
        int s = c & 1;
        MBARRIER_WAIT_PARITY(sbase + s*8, ph[s]); ph[s] ^= 1;
        int Ab = HDR + s*STGW;
        int Bb = Ab + ASTW;
#pragma unroll
        for (int ks = 0; ks < 2; ks++) {
            int kw = ks*8;
            uint32_t ab[2][4], af[2][4];
#pragma unroll
            for (int mt = 0; mt < 2; mt++) {
                int r = warp_m*32 + mt*16 + g;
                ab[mt][0] = smw[Ab + r*20 + kw + tig];
                ab[mt][1] = smw[Ab + (r+8)*20 + kw + tig];
                ab[mt][2] = smw[Ab + r*20 + kw + tig + 4];
                ab[mt][3] = smw[Ab + (r+8)*20 + kw + tig + 4];
                af[mt][0] = smw[Ab + AW + r*20 + kw + tig];
                af[mt][1] = smw[Ab + AW + (r+8)*20 + kw + tig];
                af[mt][2] = smw[Ab + AW + r*20 + kw + tig + 4];
                af[mt][3] = smw[Ab + AW + (r+8)*20 + kw + tig + 4];
            }
            uint32_t bbf[4][2], bsf[4][2];
#pragma unroll
            for (int nt = 0; nt < 4; nt++) {
                int nl = warp_n*32 + nt*8 + g;
#pragma unroll
                for (int j = 0; j < 2; j++) {
                    int kk = ks*16 + 8*j + 2*tig;
                    int cil = kk / KW, jj = kk - cil*KW;
                    int wd = Bb + cil*NW + nl*(S/2) + (jj >> 1);
                    bbf[nt][j] = smw[wd];
                    bsf[nt][j] = smw[wd + CI*NW];
                }
            }
#pragma unroll
            for (int mt = 0; mt < 2; mt++)
#pragma unroll
                for (int nt = 0; nt < 4; nt++) {
                    mma_bf16(acc[mt][nt], ab[mt], bbf[nt]);
                    mma_bf16(acc[mt][nt], ab[mt], bsf[nt]);
                    mma_bf16(acc[mt][nt], af[mt], bbf[nt]);
                }
        }
        __syncthreads();
        if (tid == 0 && c + 2 < NC) issue(c + 2, s);
    }

#pragma unroll
    for (int mt = 0; mt < 2; mt++) {
        int co0 = blockIdx.y*128 + warp_m*32 + mt*16 + g;
#pragma unroll
        for (int nt = 0; nt < 4; nt++) {
            int n = n0 + warp_n*32 + nt*8 + 2*tig;
            if (n < Lout) {
                *(float2*)&out[(size_t)(b*CC + co0)*Lout + n]     = make_float2(acc[mt][nt][0], acc[mt][nt][1]);
                *(float2*)&out[(size_t)(b*CC + co0 + 8)*Lout + n] = make_float2(acc[mt][nt][2], acc[mt][nt][3]);
            }
        }
    }
}

__global__ void buildz_kernel(const int* __restrict__ ts, const float* __restrict__ sc,
                              const float* __restrict__ sh) {
    int t = blockIdx.x, b = blockIdx.y, d = threadIdx.x;
    float v = 0.f;
    if (t <= ts[b]) {
        float r = g_c5[(b*CC + d)*L5 + t];
        v = fmaxf(fmaf(r, sc[d], sh[d]), 0.f);
    }
    g_z[(t*BB + b)*CC + d] = v;
}

__global__ void gi_gemm_kernel(const float* __restrict__ wih) {
    __shared__ float As[16*65];
    __shared__ float Bs[16*65];
    int tid = threadIdx.x, tx = tid & 15, ty = tid >> 4;
    int r0 = blockIdx.x * 64, g0 = blockIdx.y * 64;
    float acc[4][4] = {};
    for (int k0 = 0; k0 < CC; k0 += 16) {
        for (int i = tid; i < 1024; i += 256) {
            int rl = i >> 4, kk = i & 15;
            As[kk*65 + rl] = g_z[(r0+rl)*CC + k0 + kk];
            Bs[kk*65 + rl] = wih[(g0+rl)*CC + k0 + kk];
        }
        __syncthreads();
#pragma unroll
        for (int kk = 0; kk < 16; kk++) {
            float av[4], bv[4];
#pragma unroll
            for (int i = 0; i < 4; i++) av[i] = As[kk*65 + ty*4 + i];
#pragma unroll
            for (int j = 0; j < 4; j++) bv[j] = Bs[kk*65 + tx*4 + j];
#pragma unroll
            for (int i = 0; i < 4; i++)
#pragma unroll
                for (int j = 0; j < 4; j++)
                    acc[i][j] = fmaf(av[i], bv[j], acc[i][j]);
        }
        __syncthreads();
    }
#pragma unroll
    for (int i = 0; i < 4; i++)
#pragma unroll
        for (int j = 0; j < 4; j++)
            g_gi[(r0 + ty*4 + i)*768 + g0 + tx*4 + j] = acc[i][j];
}

__global__ void gru_kernel(const float* __restrict__ whh, const float* __restrict__ bih,
                           const float* __restrict__ bhh, const int* __restrict__ ts) {
    __shared__ float ws[3*8*256];
    __shared__ float h_s[BB*HID];
    __shared__ float part[BB*8*2*3];
    __shared__ float bih_s[24], bhh_s[24];
    __shared__ int ts_s[BB];
    int tid = threadIdx.x, j0 = blockIdx.x * 8;
    int b = tid >> 4, jl = (tid >> 1) & 7, half = tid & 1;
    for (int i = tid; i < 6144; i += 256) {
        int g = i >> 11, rest = i & 2047, jj = rest >> 8, k = rest & 255;
        ws[i] = whh[(g*256 + j0 + jj)*256 + k];
    }
    if (tid < 24) {
        int g = tid / 8, jj = tid % 8;
        bih_s[tid] = bih[g*256 + j0 + jj];
        bhh_s[tid] = bhh[g*256 + j0 + jj];
    }
    if (tid < BB) ts_s[tid] = ts[tid];
    __syncthreads();
    for (int t = 0; t < TT; t++) {
        const float* hin = g_hbuf[t & 1];
        for (int i = tid; i < BB*HID; i += 256) h_s[i] = __ldcg(&hin[i]);
        __syncthreads();
        float ar = 0.f, az = 0.f, an = 0.f;
        const float4* h4  = (const float4*)&h_s[b*256 + half*128];
        const float4* wr4 = (const float4*)&ws[(0*8 + jl)*256 + half*128];
        const float4* wz4 = (const float4*)&ws[(1*8 + jl)*256 + half*128];
        const float4* wn4 = (const float4*)&ws[(2*8 + jl)*256 + half*128];
#pragma unroll 8
        for (int k = 0; k < 32; k++) {
            float4 hv = h4[k];
            float4 a = wr4[k]; ar += a.x*hv.x + a.y*hv.y + a.z*hv.z + a.w*hv.w;
            float4 c = wz4[k]; az += c.x*hv.x + c.y*hv.y + c.z*hv.z + c.w*hv.w;
            float4 d = wn4[k]; an += d.x*hv.x + d.y*hv.y + d.z*hv.z + d.w*hv.w;
        }
        int pb = ((b*8 + jl)*2 + half)*3;
        part[pb+0] = ar; part[pb+1] = az; part[pb+2] = an;
        __syncthreads();
        if (half == 0) {
            int p2 = ((b*8 + jl)*2)*3;
            float hr = part[p2+0] + part[p2+3] + bhh_s[jl];
            float hz = part[p2+1] + part[p2+4] + bhh_s[8+jl];
            float hn = part[p2+2] + part[p2+5] + bhh_s[16+jl];
            const float* gi = &g_gi[(t*BB + b)*768];
            float ir  = gi[j0+jl]       + bih_s[jl];
            float iz  = gi[256 + j0+jl] + bih_s[8+jl];
            float in_ = gi[512 + j0+jl] + bih_s[16+jl];
            float r  = 1.f / (1.f + expf(-(ir + hr)));
            float zg = 1.f / (1.f + expf(-(iz + hz)));
            float n  = tanhf(in_ + r*hn);
            float hprev = h_s[b*256 + j0 + jl];
            float hnew = (1.f - zg)*n + zg*hprev;
            __stcg(&g_hbuf[(t+1) & 1][b*256 + j0 + jl], hnew);
            if (t == ts_s[b]) g_ct[b*256 + j0 + jl] = hnew;
            __threadfence();
        }
        __syncthreads();
        if (tid == 0) {
            atomicAdd(&g_bar_cnt, 1u);
            unsigned target = 32u * (unsigned)(t + 1);
            while (*((volatile unsigned*)&g_bar_cnt) < target) { }
        }
        __syncthreads();
    }
}

__global__ void enc_kernel(const int* __restrict__ ts, const float* __restrict__ sc,
                           const float* __restrict__ sh) {
    int k = blockIdx.x, b = blockIdx.y, d = threadIdx.x;
    int t = ts[b] + k + 1;
    float r = g_c5[(b*CC + d)*L5 + t];
    g_enc[(k*BB + b)*CC + d] = fmaxf(fmaf(r, sc[d], sh[d]), 0.f);
}

__global__ void pred_kernel(const float* __restrict__ wk, const float* __restrict__ wkb) {
    int k = blockIdx.x, b = blockIdx.y, d = threadIdx.x;
    __shared__ float ct[HID];
    if (d < HID) ct[d] = g_ct[b*HID + d];
    __syncthreads();
    float acc = wkb[k*CC + d];
    const float4* w4 = (const float4*)&wk[(k*CC + d)*HID];
#pragma unroll 4
    for (int h = 0; h < HID/4; h++) {
        float4 w = w4[h];
        const float* c = &ct[h*4];
        acc += w.x*c[0] + w.y*c[1] + w.z*c[2] + w.w*c[3];
    }
    g_pred[(k*BB + b)*CC + d] = acc;
}

__global__ void total_kernel() {
    int k = blockIdx.x, tid = threadIdx.x;
    int b = tid >> 4, c = tid & 15;
    const float* e = &g_enc[(k*BB + b)*CC];
    const float* p = &g_pred[(k*BB + c)*CC];
    float acc = 0.f;
    for (int d = 0; d < CC; d++) acc += e[d] * p[d];
    g_total[(k*BB + b)*BB + c] = acc;
}

__global__ void final_kernel(float* __restrict__ out) {
    __shared__ float lse_s[KCPC*BB];
    __shared__ float contrib[KCPC*BB];
    __shared__ int corr[BB];
    int tid = threadIdx.x;
    if (tid < KCPC*BB) {
        int b = tid & 15;
        const float* row = &g_total[tid*BB];
        float m = row[0];
        for (int c = 1; c < BB; c++) m = fmaxf(m, row[c]);
        float s = 0.f;
        for (int c = 0; c < BB; c++) s += expf(row[c] - m);
        float lse = m + logf(s);
        lse_s[tid] = lse;
        contrib[tid] = row[b] - lse;
    }
    __syncthreads();
    if (tid == 0) {
        float s = 0.f;
        for (int i = 0; i < KCPC*BB; i++) s += contrib[i];
        out[1] = s / (-(float)(BB*KCPC));
    }
    if (tid < BB) {
        int c = tid;
        float best = -1e30f; int bi = -1;
        for (int b = 0; b < BB; b++) {
            float v = g_total[((KCPC-1)*BB + b)*BB + c] - lse_s[(KCPC-1)*BB + b];
            if (v > best) { best = v; bi = b; }
        }
        corr[tid] = (bi == c) ? 1 : 0;
    }
    __syncthreads();
    if (tid == 0) {
        int cs = 0;
        for (int i = 0; i < BB; i++) cs += corr[i];
        out[0] = (float)cs / (float)BB;
    }
    for (int i = tid; i < BB*HID; i += blockDim.x) out[2 + i] = g_hbuf[0][i];
}

extern "C" void kernel_launch(void* const* d_in, const int* in_sizes, int n_in,
                              void* d_out, int out_size) {
    (void)in_sizes; (void)n_in; (void)out_size;
    const float* x      = (const float*)d_in[0];
    const float* hidden = (const float*)d_in[1];
    const int*   tsamp  = (const int*)d_in[3];
    const float* w1     = (const float*)d_in[4];
    const float* w2     = (const float*)d_in[5];
    const float* w345   = (const float*)d_in[6];
    const float* gamma  = (const float*)d_in[7];
    const float* beta   = (const float*)d_in[8];
    const float* wih    = (const float*)d_in[9];
    const float* whh    = (const float*)d_in[10];
    const float* bih    = (const float*)d_in[11];
    const float* bhh    = (const float*)d_in[12];
    const float* wk     = (const float*)d_in[13];
    const float* wkb    = (const float*)d_in[14];
    float* out = (float*)d_out;

    float *p_c1, *p_c2, *p_c3, *p_c4, *p_c5, *p_sc, *p_sh;
    uint32_t *p_w2b, *p_w2s, *p_w345b, *p_w345s, *p_apb, *p_aps;
    cudaGetSymbolAddress((void**)&p_c1, g_c1);
    cudaGetSymbolAddress((void**)&p_c2, g_c2);
    cudaGetSymbolAddress((void**)&p_c3, g_c3);
    cudaGetSymbolAddress((void**)&p_c4, g_c4);
    cudaGetSymbolAddress((void**)&p_c5, g_c5);
    cudaGetSymbolAddress((void**)&p_sc, g_scale);
    cudaGetSymbolAddress((void**)&p_sh, g_shift);
    cudaGetSymbolAddress((void**)&p_w2b, g_w2b);
    cudaGetSymbolAddress((void**)&p_w2s, g_w2s);
    cudaGetSymbolAddress((void**)&p_w345b, g_w345b);
    cudaGetSymbolAddress((void**)&p_w345s, g_w345s);
    cudaGetSymbolAddress((void**)&p_apb, g_apb);
    cudaGetSymbolAddress((void**)&p_aps, g_aps);

    const int SM_L2   = (32 + 2*(2*2560 + 2*4*132))*4;   // 49536
    const int SM_L345 = (32 + 2*(2*2560 + 2*8*68))*4;    // 49792
    cudaFuncSetAttribute(conv_tc_kernel<8,4,4096,8200,132>,
                         cudaFuncAttributeMaxDynamicSharedMemorySize, SM_L2);
    cudaFuncSetAttribute(conv_tc_kernel<4,2,2048,2056,68>,
                         cudaFuncAttributeMaxDynamicSharedMemorySize, SM_L345);
    cudaFuncSetAttribute(conv_tc_kernel<4,2,2048,1032,68>,
                         cudaFuncAttributeMaxDynamicSharedMemorySize, SM_L345);
    cudaFuncSetAttribute(conv_tc_kernel<4,2,2048,520,68>,
                         cudaFuncAttributeMaxDynamicSharedMemorySize, SM_L345);

    init_kernel<<<16, 256>>>(hidden);
    prepw_kernel<4096><<<(512*2048 + 255)/256, 256>>>(w2, p_w2b, p_w2s);
    prepw_kernel<2048><<<(512*1024 + 255)/256, 256>>>(w345 + 0*512*2048, p_w345b + 0*655360, p_w345s + 0*655360);
    prepw_kernel<2048><<<(512*1024 + 255)/256, 256>>>(w345 + 1*512*2048, p_w345b + 1*655360, p_w345s + 1*655360);
    prepw_kernel<2048><<<(512*1024 + 255)/256, 256>>>(w345 + 2*512*2048, p_w345b + 2*655360, p_w345s + 2*655360);

    conv1_kernel<<<dim3(63, BB), 256>>>(x, w1);
    stats_kernel<<<CC, 256>>>(p_c1, gamma, beta, p_sc, p_sh, L1);
    prepa_kernel<L1,8200,2><<<dim3(CC, BB), 256>>>(p_c1, p_sc, p_sh);

    conv_tc_kernel<8,4,4096,8200,132><<<dim3(63, 4, BB), 256, SM_L2>>>(
        p_apb, p_aps, p_w2b, p_w2s, p_c2, L2);
    stats_kernel<<<CC, 256>>>(p_c2, gamma + CC, beta + CC, p_sc + CC, p_sh + CC, L2);
    prepa_kernel<L2,2056,1><<<dim3(CC, BB), 256>>>(p_c2, p_sc + CC, p_sh + CC);

    conv_tc_kernel<4,2,2048,2056,68><<<dim3(32, 4, BB), 256, SM_L345>>>(
        p_apb, p_aps, p_w345b + 0*655360, p_w345s + 0*655360, p_c3, L3);
    stats_kernel<<<CC, 256>>>(p_c3, gamma + 2*CC, beta + 2*CC, p_sc + 2*CC, p_sh + 2*CC, L3);
    prepa_kernel<L3,1032,1><<<dim3(CC, BB), 256>>>(p_c3, p_sc + 2*CC, p_sh + 2*CC);

    conv_tc_kernel<4,2,2048,1032,68><<<dim3(16, 4, BB), 256, SM_L345>>>(
        p_apb, p_aps, p_w345b + 1*655360, p_w345s + 1*655360, p_c4, L4);
    stats_kernel<<<CC, 256>>>(p_c4, gamma + 3*CC, beta + 3*CC, p_sc + 3*CC, p_sh + 3*CC, L4);
    prepa_kernel<L4,520,1><<<dim3(CC, BB), 256>>>(p_c4, p_sc + 3*CC, p_sh + 3*CC);

    conv_tc_kernel<4,2,2048,520,68><<<dim3(8, 4, BB), 256, SM_L345>>>(
        p_apb, p_aps, p_w345b + 2*655360, p_w345s + 2*655360, p_c5, L5);
    stats_kernel<<<CC, 256>>>(p_c5, gamma + 4*CC, beta + 4*CC, p_sc + 4*CC, p_sh + 4*CC, L5);

    buildz_kernel<<<dim3(TT, BB), CC>>>(tsamp, p_sc + 4*CC, p_sh + 4*CC);
    gi_gemm_kernel<<<dim3(125, 12), 256>>>(wih);
    gru_kernel<<<32, 256>>>(whh, bih, bhh, tsamp);

    enc_kernel<<<dim3(KCPC, BB), CC>>>(tsamp, p_sc + 4*CC, p_sh + 4*CC);
    pred_kernel<<<dim3(KCPC, BB), CC>>>(wk, wkb);
    total_kernel<<<KCPC, 256>>>();
    final_kernel<<<1, 256>>>(out);
}

// round 11
// speedup vs baseline: 1.7956x; 1.0202x over previous
#include <cuda_runtime.h>
#include <math.h>
#include <stdint.h>

#define BB 16
#define CC 512
#define L0 80000
#define L1 16000
#define L2 4000
#define L3 2000
#define L4 1000
#define L5 500
#define TT 500
#define HID 256
#define KCPC 12

__device__ float g_c1[BB*CC*L1];
__device__ float g_c2[BB*CC*L2];
__device__ float g_c3[BB*CC*L3];
__device__ float g_c4[BB*CC*L4];
__device__ float g_c5[BB*CC*L5];
__device__ float g_scale[5*CC];
__device__ float g_shift[5*CC];
__device__ uint32_t g_w2b[1310720];     // padded chunk-major weights: [128ch][4mt][128][20]
__device__ uint32_t g_w2s[1310720];
__device__ uint32_t g_w345b[3*655360];  // [64ch][4mt][128][20] per layer
__device__ uint32_t g_w345s[3*655360];
__device__ uint32_t g_apb[(size_t)BB*CC*8200];
__device__ uint32_t g_aps[(size_t)BB*CC*8200];
__device__ float g_z[TT*BB*CC];
__device__ float g_gi[TT*BB*768];
__device__ float g_hbuf[2][BB*HID];
__device__ float g_ct[BB*HID];
__device__ float g_enc[KCPC*BB*CC];
__device__ float g_pred[KCPC*BB*CC];
__device__ float g_total[KCPC*BB*BB];
__device__ unsigned g_bar_cnt;

__device__ __forceinline__ uint32_t smem_to_u32(const void* p) {
    uint32_t a;
    asm("{ .reg .u64 t; cvta.to.shared.u64 t, %1; cvt.u32.u64 %0, t; }" : "=r"(a) : "l"(p));
    return a;
}
__device__ __forceinline__ uint32_t pack_bf16x2(float hi, float lo) {
    uint32_t r;
    asm("cvt.rn.bf16x2.f32 %0, %1, %2;" : "=r"(r) : "f"(hi), "f"(lo));
    return r;
}
__device__ __forceinline__ void split_pack(float v0, float v1, uint32_t& bw, uint32_t& sw) {
    bw = pack_bf16x2(v1, v0);
    float b0 = __uint_as_float(bw << 16);
    float b1 = __uint_as_float(bw & 0xffff0000u);
    sw = pack_bf16x2(v1 - b1, v0 - b0);
}
__device__ __forceinline__ void mma_bf16(float* d, const uint32_t* a, const uint32_t* bfr) {
    asm volatile(
        "mma.sync.aligned.m16n8k16.row.col.f32.bf16.bf16.f32 "
        "{%0,%1,%2,%3}, {%4,%5,%6,%7}, {%8,%9}, {%0,%1,%2,%3};"
        : "+f"(d[0]), "+f"(d[1]), "+f"(d[2]), "+f"(d[3])
        : "r"(a[0]), "r"(a[1]), "r"(a[2]), "r"(a[3]), "r"(bfr[0]), "r"(bfr[1]));
}
#define MBARRIER_INIT(addr, cnt) \
    asm volatile("mbarrier.init.shared.b64 [%0], %1;" :: "r"((uint32_t)(addr)), "r"((uint32_t)(cnt)) : "memory")
#define MBARRIER_EXPECT_TX(addr, bytes) \
    asm volatile("mbarrier.arrive.expect_tx.shared.b64 _, [%0], %1;" :: "r"((uint32_t)(addr)), "r"((uint32_t)(bytes)) : "memory")
#define MBARRIER_WAIT_PARITY(addr, par) do { \
    uint32_t _m = (uint32_t)(addr); uint32_t _p = (uint32_t)(par); uint32_t _d; \
    asm volatile("{\n\t.reg .pred p;\n\tmbarrier.try_wait.parity.shared.b64 p, [%1], %2;\n\tselp.b32 %0, 1, 0, p;\n\t}" \
        : "=r"(_d) : "r"(_m), "r"(_p) : "memory"); \
    if (!_d) { \
        asm volatile("{\n\t.reg .pred P1;\n\tWL_%=:\n\tmbarrier.try_wait.parity.shared.b64 P1, [%0], %1;\n\t@P1 bra.uni WD_%=;\n\tbra.uni WL_%=;\n\tWD_%=:\n\t}" \
            :: "r"(_m), "r"(_p) : "memory"); \
    } \
} while (0)
#define BULK_G2S(dst, src, bytes, mb) \
    asm volatile("cp.async.bulk.shared::cluster.global.mbarrier::complete_tx::bytes [%0], [%1], %2, [%3];" \
        :: "r"((uint32_t)(dst)), "l"(src), "r"((uint32_t)(bytes)), "r"((uint32_t)(mb)) : "memory")

__global__ void init_kernel(const float* __restrict__ hidden) {
    if (blockIdx.x == 0 && threadIdx.x == 0) g_bar_cnt = 0u;
    int i = blockIdx.x * blockDim.x + threadIdx.x;
    if (i < BB*HID) g_hbuf[0][i] = hidden[i];
}

template<int KTOT>
__global__ void prepw_kernel(const float* __restrict__ w, uint32_t* __restrict__ wb,
                             uint32_t* __restrict__ ws) {
    int i = blockIdx.x*256 + threadIdx.x;
    if (i >= 512*(KTOT/2)) return;
    int co = i / (KTOT/2), wp = i % (KTOT/2);
    int chunk = wp >> 4, word = wp & 15;
    uint32_t bw, sw;
    split_pack(w[(size_t)co*KTOT + 2*wp], w[(size_t)co*KTOT + 2*wp + 1], bw, sw);
    size_t d = (((size_t)chunk*4 + (co>>7))*128 + (co&127))*20 + word;
    wb[d] = bw; ws[d] = sw;
}

template<int LIN, int LPW, int SH>
__global__ void prepa_kernel(const float* __restrict__ raw, const float* __restrict__ sc,
                             const float* __restrict__ shf) {
    int ci = blockIdx.x, b = blockIdx.y;
    float s = sc[ci], t = shf[ci];
    const float* src = raw + ((size_t)b*CC + ci)*LIN;
    uint32_t* db = g_apb + ((size_t)(b*CC) + ci)*LPW;
    uint32_t* ds = g_aps + ((size_t)(b*CC) + ci)*LPW;
    for (int w = threadIdx.x; w < LPW; w += 256) {
        int p0 = 2*w - SH;
        float v0 = (p0 >= 0 && p0 < LIN) ? fmaxf(fmaf(src[p0], s, t), 0.f) : 0.f;
        float v1 = (p0+1 >= 0 && p0+1 < LIN) ? fmaxf(fmaf(src[p0+1], s, t), 0.f) : 0.f;
        uint32_t bw, sw;
        split_pack(v0, v1, bw, sw);
        db[w] = bw; ds[w] = sw;
    }
}

__global__ void conv1_kernel(const float* __restrict__ x, const float* __restrict__ w) {
    __shared__ float wsm[CC*10];
    __shared__ float xs[256*5 + 10];
    int b = blockIdx.y, o0 = blockIdx.x * 256, tid = threadIdx.x;
    for (int i = tid; i < CC*10; i += 256) wsm[i] = w[i];
    int p0 = o0*5 - 3;
    for (int i = tid; i < 256*5 + 10; i += 256) {
        int p = p0 + i;
        xs[i] = (p >= 0 && p < L0) ? x[b*L0 + p] : 0.f;
    }
    __syncthreads();
    int o = o0 + tid;
    if (o >= L1) return;
    float xr[10];
#pragma unroll
    for (int j = 0; j < 10; j++) xr[j] = xs[tid*5 + j];
    for (int co = 0; co < CC; co++) {
        float acc = 0.f;
#pragma unroll
        for (int j = 0; j < 10; j++) acc = fmaf(wsm[co*10 + j], xr[j], acc);
        g_c1[(b*CC + co)*L1 + o] = acc;
    }
}

__global__ void stats_kernel(const float* __restrict__ raw, const float* __restrict__ gamma,
                             const float* __restrict__ beta, float* __restrict__ scale,
                             float* __restrict__ shift, int L) {
    int c = blockIdx.x, tid = threadIdx.x;
    double s = 0.0, s2 = 0.0;
    for (int b = 0; b < BB; b++) {
        const float* p = raw + (size_t)(b*CC + c)*L;
        for (int l = tid; l < L; l += 256) { float v = p[l]; s += v; s2 += (double)v*v; }
    }
    __shared__ double rs[256], rs2[256];
    rs[tid] = s; rs2[tid] = s2; __syncthreads();
    for (int st = 128; st > 0; st >>= 1) {
        if (tid < st) { rs[tid] += rs[tid+st]; rs2[tid] += rs2[tid+st]; }
        __syncthreads();
    }
    if (tid == 0) {
        double n = (double)BB * (double)L;
        double mean = rs[0]/n, var = rs2[0]/n - mean*mean;
        double sc = (double)gamma[c] / sqrt(var + 1e-5);
        scale[c] = (float)sc;
        shift[c] = (float)((double)beta[c] - mean*sc);
    }
}

// ===== all-TMA 3xBF16 conv: 128co x 128n tile, 256 thr, 2 CTA/SM, 3 stages =====
template<int KW, int S, int KTOT, int LPW, int NW>
__global__ void __launch_bounds__(256, 2)
conv_tc_kernel(const uint32_t* __restrict__ pb, const uint32_t* __restrict__ ps,
               const uint32_t* __restrict__ wb, const uint32_t* __restrict__ wsp,
               float* __restrict__ out, int Lout) {
    constexpr int CI = 32/KW, NC = KTOT/32;
    constexpr int AW = 2560;                 // 128 rows x 20 words
    constexpr int ASTW = 2*AW;
    constexpr int BSTW = 2*CI*NW;
    constexpr int STGW = ASTW + BSTW;
    constexpr int HDR = 32;
    extern __shared__ __align__(128) uint32_t smw[];
    uint32_t sbase = smem_to_u32(smw);
    int tid = threadIdx.x, wid = tid >> 5, lane = tid & 31;
    int g = lane >> 2, tig = lane & 3;
    int warp_m = wid >> 1, warp_n = wid & 1;
    int n0 = blockIdx.x*128, b = blockIdx.z;
    uint32_t txb = (uint32_t)(2*10240 + 2*CI*NW*4);

    if (tid == 0) { MBARRIER_INIT(sbase, 1); MBARRIER_INIT(sbase + 8, 1); MBARRIER_INIT(sbase + 16, 1); }
    __syncthreads();
    asm volatile("fence.proxy.async;" ::: "memory");

    auto issue = [&](int c, int s) {
        uint32_t mb = sbase + s*8;
        uint32_t ast = sbase + (uint32_t)(HDR + s*STGW)*4;
        uint32_t bst = ast + ASTW*4;
        MBARRIER_EXPECT_TX(mb, txb);
        size_t aoff = ((size_t)c*4 + blockIdx.y)*AW;
        BULK_G2S(ast,          wb  + aoff, 10240, mb);
        BULK_G2S(ast + AW*4,   wsp + aoff, 10240, mb);
        int base = n0*(S/2);
        for (int r = 0; r < CI; r++) {
            size_t so = ((size_t)(b*CC) + (size_t)c*CI + r)*LPW + base;
            BULK_G2S(bst + (uint32_t)(r*NW)*4,      pb + so, NW*4, mb);
            BULK_G2S(bst + (uint32_t)((CI+r)*NW)*4, ps + so, NW*4, mb);
        }
    };
    if (tid == 0) { issue(0, 0); issue(1, 1); issue(2, 2); }

    float acc[2][8][4];
#pragma unroll
    for (int mt = 0; mt < 2; mt++)
#pragma unroll
        for (int nt = 0; nt < 8; nt++)
#pragma unroll
            for (int q = 0; q < 4; q++) acc[mt][nt][q] = 0.f;

    int ph[3] = {0, 0, 0};
    int s = 0;
    for (int c = 0; c < NC; c++) {
        MBARRIER_WAIT_PARITY(sbase + s*8, ph[s]); ph[s] ^= 1;
        int Ab = HDR + s*STGW;
        int Bb = Ab + ASTW;
#pragma unroll
        for (int ks = 0; ks < 2; ks++) {
            int kw = ks*8;
            uint32_t ab[2][4], af[2][4];
#pragma unroll
            for (int mt = 0; mt < 2; mt++) {
                int r = warp_m*32 + mt*16 + g;
                ab[mt][0] = smw[Ab + r*20 + kw + tig];
                ab[mt][1] = smw[Ab + (r+8)*20 + kw + tig];
                ab[mt][2] = smw[Ab + r*20 + kw + tig + 4];
                ab[mt][3] = smw[Ab + (r+8)*20 + kw + tig + 4];
                af[mt][0] = smw[Ab + AW + r*20 + kw + tig];
                af[mt][1] = smw[Ab + AW + (r+8)*20 + kw + tig];
                af[mt][2] = smw[Ab + AW + r*20 + kw + tig + 4];
                af[mt][3] = smw[Ab + AW + (r+8)*20 + kw + tig + 4];
            }
#pragma unroll
            for (int nt = 0; nt < 8; nt++) {
                int nl = warp_n*64 + nt*8 + g;
                uint32_t bbf[2], bsf[2];
#pragma unroll
                for (int j = 0; j < 2; j++) {
                    int kk = ks*16 + 8*j + 2*tig;
                    int cil = kk / KW, jj = kk - cil*KW;
                    int wd = Bb + cil*NW + nl*(S/2) + (jj >> 1);
                    bbf[j] = smw[wd];
                    bsf[j] = smw[wd + CI*NW];
                }
#pragma unroll
                for (int mt = 0; mt < 2; mt++) {
                    mma_bf16(acc[mt][nt], ab[mt], bbf);
                    mma_bf16(acc[mt][nt], ab[mt], bsf);
                    mma_bf16(acc[mt][nt], af[mt], bbf);
                }
            }
        }
        __syncthreads();
        if (tid == 0 && c + 3 < NC) issue(c + 3, s);
        s = (s == 2) ? 0 : s + 1;
    }

#pragma unroll
    for (int mt = 0; mt < 2; mt++) {
        int co0 = blockIdx.y*128 + warp_m*32 + mt*16 + g;
#pragma unroll
        for (int nt = 0; nt < 8; nt++) {
            int n = n0 + warp_n*64 + nt*8 + 2*tig;
            if (n < Lout) {
                *(float2*)&out[(size_t)(b*CC + co0)*Lout + n]     = make_float2(acc[mt][nt][0], acc[mt][nt][1]);
                *(float2*)&out[(size_t)(b*CC + co0 + 8)*Lout + n] = make_float2(acc[mt][nt][2], acc[mt][nt][3]);
            }
        }
    }
}

__global__ void buildz_kernel(const int* __restrict__ ts, const float* __restrict__ sc,
                              const float* __restrict__ sh) {
    int t = blockIdx.x, b = blockIdx.y, d = threadIdx.x;
    float v = 0.f;
    if (t <= ts[b]) {
        float r = g_c5[(b*CC + d)*L5 + t];
        v = fmaxf(fmaf(r, sc[d], sh[d]), 0.f);
    }
    g_z[(t*BB + b)*CC + d] = v;
}

__global__ void gi_gemm_kernel(const float* __restrict__ wih) {
    __shared__ float As[16*65];
    __shared__ float Bs[16*65];
    int tid = threadIdx.x, tx = tid & 15, ty = tid >> 4;
    int r0 = blockIdx.x * 64, g0 = blockIdx.y * 64;
    float acc[4][4] = {};
    for (int k0 = 0; k0 < CC; k0 += 16) {
        for (int i = tid; i < 1024; i += 256) {
            int rl = i >> 4, kk = i & 15;
            As[kk*65 + rl] = g_z[(r0+rl)*CC + k0 + kk];
            Bs[kk*65 + rl] = wih[(g0+rl)*CC + k0 + kk];
        }
        __syncthreads();
#pragma unroll
        for (int kk = 0; kk < 16; kk++) {
            float av[4], bv[4];
#pragma unroll
            for (int i = 0; i < 4; i++) av[i] = As[kk*65 + ty*4 + i];
#pragma unroll
            for (int j = 0; j < 4; j++) bv[j] = Bs[kk*65 + tx*4 + j];
#pragma unroll
            for (int i = 0; i < 4; i++)
#pragma unroll
                for (int j = 0; j < 4; j++)
                    acc[i][j] = fmaf(av[i], bv[j], acc[i][j]);
        }
        __syncthreads();
    }
#pragma unroll
    for (int i = 0; i < 4; i++)
#pragma unroll
        for (int j = 0; j < 4; j++)
            g_gi[(r0 + ty*4 + i)*768 + g0 + tx*4 + j] = acc[i][j];
}

__global__ void gru_kernel(const float* __restrict__ whh, const float* __restrict__ bih,
                           const float* __restrict__ bhh, const int* __restrict__ ts) {
    __shared__ float ws[3*8*256];
    __shared__ float h_s[BB*HID];
    __shared__ float part[BB*8*2*3];
    __shared__ float bih_s[24], bhh_s[24];
    __shared__ int ts_s[BB];
    int tid = threadIdx.x, j0 = blockIdx.x * 8;
    int b = tid >> 4, jl = (tid >> 1) & 7, half = tid & 1;
    for (int i = tid; i < 6144; i += 256) {
        int g = i >> 11, rest = i & 2047, jj = rest >> 8, k = rest & 255;
        ws[i] = whh[(g*256 + j0 + jj)*256 + k];
    }
    if (tid < 24) {
        int g = tid / 8, jj = tid % 8;
        bih_s[tid] = bih[g*256 + j0 + jj];
        bhh_s[tid] = bhh[g*256 + j0 + jj];
    }
    if (tid < BB) ts_s[tid] = ts[tid];
    __syncthreads();
    for (int t = 0; t < TT; t++) {
        const float* hin = g_hbuf[t & 1];
        for (int i = tid; i < BB*HID; i += 256) h_s[i] = __ldcg(&hin[i]);
        __syncthreads();
        float ar = 0.f, az = 0.f, an = 0.f;
        const float4* h4  = (const float4*)&h_s[b*256 + half*128];
        const float4* wr4 = (const float4*)&ws[(0*8 + jl)*256 + half*128];
        const float4* wz4 = (const float4*)&ws[(1*8 + jl)*256 + half*128];
        const float4* wn4 = (const float4*)&ws[(2*8 + jl)*256 + half*128];
#pragma unroll 8
        for (int k = 0; k < 32; k++) {
            float4 hv = h4[k];
            float4 a = wr4[k]; ar += a.x*hv.x + a.y*hv.y + a.z*hv.z + a.w*hv.w;
            float4 c = wz4[k]; az += c.x*hv.x + c.y*hv.y + c.z*hv.z + c.w*hv.w;
            float4 d = wn4[k]; an += d.x*hv.x + d.y*hv.y + d.z*hv.z + d.w*hv.w;
        }
        int pb = ((b*8 + jl)*2 + half)*3;
        part[pb+0] = ar; part[pb+1] = az; part[pb+2] = an;
        __syncthreads();
        if (half == 0) {
            int p2 = ((b*8 + jl)*2)*3;
            float hr = part[p2+0] + part[p2+3] + bhh_s[jl];
            float hz = part[p2+1] + part[p2+4] + bhh_s[8+jl];
            float hn = part[p2+2] + part[p2+5] + bhh_s[16+jl];
            const float* gi = &g_gi[(t*BB + b)*768];
            float ir  = gi[j0+jl]       + bih_s[jl];
            float iz  = gi[256 + j0+jl] + bih_s[8+jl];
            float in_ = gi[512 + j0+jl] + bih_s[16+jl];
            float r  = 1.f / (1.f + expf(-(ir + hr)));
            float zg = 1.f / (1.f + expf(-(iz + hz)));
            float n  = tanhf(in_ + r*hn);
            float hprev = h_s[b*256 + j0 + jl];
            float hnew = (1.f - zg)*n + zg*hprev;
            __stcg(&g_hbuf[(t+1) & 1][b*256 + j0 + jl], hnew);
            if (t == ts_s[b]) g_ct[b*256 + j0 + jl] = hnew;
            __threadfence();
        }
        __syncthreads();
        if (tid == 0) {
            atomicAdd(&g_bar_cnt, 1u);
            unsigned target = 32u * (unsigned)(t + 1);
            while (*((volatile unsigned*)&g_bar_cnt) < target) { }
        }
        __syncthreads();
    }
}

__global__ void enc_kernel(const int* __restrict__ ts, const float* __restrict__ sc,
                           const float* __restrict__ sh) {
    int k = blockIdx.x, b = blockIdx.y, d = threadIdx.x;
    int t = ts[b] + k + 1;
    float r = g_c5[(b*CC + d)*L5 + t];
    g_enc[(k*BB + b)*CC + d] = fmaxf(fmaf(r, sc[d], sh[d]), 0.f);
}

__global__ void pred_kernel(const float* __restrict__ wk, const float* __restrict__ wkb) {
    int k = blockIdx.x, b = blockIdx.y, d = threadIdx.x;
    __shared__ float ct[HID];
    if (d < HID) ct[d] = g_ct[b*HID + d];
    __syncthreads();
    float acc = wkb[k*CC + d];
    const float4* w4 = (const float4*)&wk[(k*CC + d)*HID];
#pragma unroll 4
    for (int h = 0; h < HID/4; h++) {
        float4 w = w4[h];
        const float* c = &ct[h*4];
        acc += w.x*c[0] + w.y*c[1] + w.z*c[2] + w.w*c[3];
    }
    g_pred[(k*BB + b)*CC + d] = acc;
}

__global__ void total_kernel() {
    int k = blockIdx.x, tid = threadIdx.x;
    int b = tid >> 4, c = tid & 15;
    const float* e = &g_enc[(k*BB + b)*CC];
    const float* p = &g_pred[(k*BB + c)*CC];
    float acc = 0.f;
    for (int d = 0; d < CC; d++) acc += e[d] * p[d];
    g_total[(k*BB + b)*BB + c] = acc;
}

__global__ void final_kernel(float* __restrict__ out) {
    __shared__ float lse_s[KCPC*BB];
    __shared__ float contrib[KCPC*BB];
    __shared__ int corr[BB];
    int tid = threadIdx.x;
    if (tid < KCPC*BB) {
        int b = tid & 15;
        const float* row = &g_total[tid*BB];
        float m = row[0];
        for (int c = 1; c < BB; c++) m = fmaxf(m, row[c]);
        float s = 0.f;
        for (int c = 0; c < BB; c++) s += expf(row[c] - m);
        float lse = m + logf(s);
        lse_s[tid] = lse;
        contrib[tid] = row[b] - lse;
    }
    __syncthreads();
    if (tid == 0) {
        float s = 0.f;
        for (int i = 0; i < KCPC*BB; i++) s += contrib[i];
        out[1] = s / (-(float)(BB*KCPC));
    }
    if (tid < BB) {
        int c = tid;
        float best = -1e30f; int bi = -1;
        for (int b = 0; b < BB; b++) {
            float v = g_total[((KCPC-1)*BB + b)*BB + c] - lse_s[(KCPC-1)*BB + b];
            if (v > best) { best = v; bi = b; }
        }
        corr[tid] = (bi == c) ? 1 : 0;
    }
    __syncthreads();
    if (tid == 0) {
        int cs = 0;
        for (int i = 0; i < BB; i++) cs += corr[i];
        out[0] = (float)cs / (float)BB;
    }
    for (int i = tid; i < BB*HID; i += blockDim.x) out[2 + i] = g_hbuf[0][i];
}

extern "C" void kernel_launch(void* const* d_in, const int* in_sizes, int n_in,
                              void* d_out, int out_size) {
    (void)in_sizes; (void)n_in; (void)out_size;
    const float* x      = (const float*)d_in[0];
    const float* hidden = (const float*)d_in[1];
    const int*   tsamp  = (const int*)d_in[3];
    const float* w1     = (const float*)d_in[4];
    const float* w2     = (const float*)d_in[5];
    const float* w345   = (const float*)d_in[6];
    const float* gamma  = (const float*)d_in[7];
    const float* beta   = (const float*)d_in[8];
    const float* wih    = (const float*)d_in[9];
    const float* whh    = (const float*)d_in[10];
    const float* bih    = (const float*)d_in[11];
    const float* bhh    = (const float*)d_in[12];
    const float* wk     = (const float*)d_in[13];
    const float* wkb    = (const float*)d_in[14];
    float* out = (float*)d_out;

    float *p_c1, *p_c2, *p_c3, *p_c4, *p_c5, *p_sc, *p_sh;
    uint32_t *p_w2b, *p_w2s, *p_w345b, *p_w345s, *p_apb, *p_aps;
    cudaGetSymbolAddress((void**)&p_c1, g_c1);
    cudaGetSymbolAddress((void**)&p_c2, g_c2);
    cudaGetSymbolAddress((void**)&p_c3, g_c3);
    cudaGetSymbolAddress((void**)&p_c4, g_c4);
    cudaGetSymbolAddress((void**)&p_c5, g_c5);
    cudaGetSymbolAddress((void**)&p_sc, g_scale);
    cudaGetSymbolAddress((void**)&p_sh, g_shift);
    cudaGetSymbolAddress((void**)&p_w2b, g_w2b);
    cudaGetSymbolAddress((void**)&p_w2s, g_w2s);
    cudaGetSymbolAddress((void**)&p_w345b, g_w345b);
    cudaGetSymbolAddress((void**)&p_w345s, g_w345s);
    cudaGetSymbolAddress((void**)&p_apb, g_apb);
    cudaGetSymbolAddress((void**)&p_aps, g_aps);

    const int SM_L2   = (32 + 3*(2*2560 + 2*4*260))*4;   // 86528
    const int SM_L345 = (32 + 3*(2*2560 + 2*8*132))*4;   // 86912
    cudaFuncSetAttribute(conv_tc_kernel<8,4,4096,8200,260>,
                         cudaFuncAttributeMaxDynamicSharedMemorySize, SM_L2);
    cudaFuncSetAttribute(conv_tc_kernel<4,2,2048,2056,132>,
                         cudaFuncAttributeMaxDynamicSharedMemorySize, SM_L345);
    cudaFuncSetAttribute(conv_tc_kernel<4,2,2048,1032,132>,
                         cudaFuncAttributeMaxDynamicSharedMemorySize, SM_L345);
    cudaFuncSetAttribute(conv_tc_kernel<4,2,2048,520,132>,
                         cudaFuncAttributeMaxDynamicSharedMemorySize, SM_L345);

    init_kernel<<<16, 256>>>(hidden);
    prepw_kernel<4096><<<(512*2048 + 255)/256, 256>>>(w2, p_w2b, p_w2s);
    prepw_kernel<2048><<<(512*1024 + 255)/256, 256>>>(w345 + 0*512*2048, p_w345b + 0*655360, p_w345s + 0*655360);
    prepw_kernel<2048><<<(512*1024 + 255)/256, 256>>>(w345 + 1*512*2048, p_w345b + 1*655360, p_w345s + 1*655360);
    prepw_kernel<2048><<<(512*1024 + 255)/256, 256>>>(w345 + 2*512*2048, p_w345b + 2*655360, p_w345s + 2*655360);

    conv1_kernel<<<dim3(63, BB), 256>>>(x, w1);
    stats_kernel<<<CC, 256>>>(p_c1, gamma, beta, p_sc, p_sh, L1);
    prepa_kernel<L1,8200,2><<<dim3(CC, BB), 256>>>(p_c1, p_sc, p_sh);

    conv_tc_kernel<8,4,4096,8200,260><<<dim3(32, 4, BB), 256, SM_L2>>>(
        p_apb, p_aps, p_w2b, p_w2s, p_c2, L2);
    stats_kernel<<<CC, 256>>>(p_c2, gamma + CC, beta + CC, p_sc + CC, p_sh + CC, L2);
    prepa_kernel<L2,2056,1><<<dim3(CC, BB), 256>>>(p_c2, p_sc + CC, p_sh + CC);

    conv_tc_kernel<4,2,2048,2056,132><<<dim3(16, 4, BB), 256, SM_L345>>>(
        p_apb, p_aps, p_w345b + 0*655360, p_w345s + 0*655360, p_c3, L3);
    stats_kernel<<<CC, 256>>>(p_c3, gamma + 2*CC, beta + 2*CC, p_sc + 2*CC, p_sh + 2*CC, L3);
    prepa_kernel<L3,1032,1><<<dim3(CC, BB), 256>>>(p_c3, p_sc + 2*CC, p_sh + 2*CC);

    conv_tc_kernel<4,2,2048,1032,132><<<dim3(8, 4, BB), 256, SM_L345>>>(
        p_apb, p_aps, p_w345b + 1*655360, p_w345s + 1*655360, p_c4, L4);
    stats_kernel<<<CC, 256>>>(p_c4, gamma + 3*CC, beta + 3*CC, p_sc + 3*CC, p_sh + 3*CC, L4);
    prepa_kernel<L4,520,1><<<dim3(CC, BB), 256>>>(p_c4, p_sc + 3*CC, p_sh + 3*CC);

    conv_tc_kernel<4,2,2048,520,132><<<dim3(4, 4, BB), 256, SM_L345>>>(
        p_apb, p_aps, p_w345b + 2*655360, p_w345s + 2*655360, p_c5, L5);
    stats_kernel<<<CC, 256>>>(p_c5, gamma + 4*CC, beta + 4*CC, p_sc + 4*CC, p_sh + 4*CC, L5);

    buildz_kernel<<<dim3(TT, BB), CC>>>(tsamp, p_sc + 4*CC, p_sh + 4*CC);
    gi_gemm_kernel<<<dim3(125, 12), 256>>>(wih);
    gru_kernel<<<32, 256>>>(whh, bih, bhh, tsamp);

    enc_kernel<<<dim3(KCPC, BB), CC>>>(tsamp, p_sc + 4*CC, p_sh + 4*CC);
    pred_kernel<<<dim3(KCPC, BB), CC>>>(wk, wkb);
    total_kernel<<<KCPC, 256>>>();
    final_kernel<<<1, 256>>>(out);
}

// round 12
// speedup vs baseline: 2.0872x; 1.1624x over previous
#include <cuda_runtime.h>
#include <cuda_fp16.h>
#include <math.h>
#include <stdint.h>

#define BB 16
#define CC 512
#define L0 80000
#define L1 16000
#define L2 4000
#define L3 2000
#define L4 1000
#define L5 500
#define TT 500
#define HID 256
#define KCPC 12

__device__ float g_c1[BB*CC*L1];
__device__ float g_c2[BB*CC*L2];
__device__ float g_c3[BB*CC*L3];
__device__ float g_c4[BB*CC*L4];
__device__ float g_c5[BB*CC*L5];
__device__ float g_scale[5*CC];
__device__ float g_shift[5*CC];
__device__ uint32_t g_w2b[1310720];     // fp16x2 chunk-major weights: [128ch][4mt][128][20]
__device__ uint32_t g_w345b[3*655360];  // [64ch][4mt][128][20] per layer
__device__ uint32_t g_apb[(size_t)BB*CC*8200];   // fp16x2 activations
__device__ float g_z[TT*BB*CC];
__device__ float g_gi[TT*BB*768];
__device__ float g_hbuf[2][BB*HID];
__device__ float g_ct[BB*HID];
__device__ float g_enc[KCPC*BB*CC];
__device__ float g_pred[KCPC*BB*CC];
__device__ float g_total[KCPC*BB*BB];
__device__ unsigned g_bar_cnt;

__device__ __forceinline__ uint32_t smem_to_u32(const void* p) {
    uint32_t a;
    asm("{ .reg .u64 t; cvta.to.shared.u64 t, %1; cvt.u32.u64 %0, t; }" : "=r"(a) : "l"(p));
    return a;
}
__device__ __forceinline__ uint32_t pack_h2(float v0, float v1) {
    __half2 h = __floats2half2_rn(v0, v1);
    return *(uint32_t*)&h;
}
__device__ __forceinline__ void mma_fp16(float* d, const uint32_t* a, const uint32_t* bfr) {
    asm volatile(
        "mma.sync.aligned.m16n8k16.row.col.f32.f16.f16.f32 "
        "{%0,%1,%2,%3}, {%4,%5,%6,%7}, {%8,%9}, {%0,%1,%2,%3};"
        : "+f"(d[0]), "+f"(d[1]), "+f"(d[2]), "+f"(d[3])
        : "r"(a[0]), "r"(a[1]), "r"(a[2]), "r"(a[3]), "r"(bfr[0]), "r"(bfr[1]));
}
#define MBARRIER_INIT(addr, cnt) \
    asm volatile("mbarrier.init.shared.b64 [%0], %1;" :: "r"((uint32_t)(addr)), "r"((uint32_t)(cnt)) : "memory")
#define MBARRIER_EXPECT_TX(addr, bytes) \
    asm volatile("mbarrier.arrive.expect_tx.shared.b64 _, [%0], %1;" :: "r"((uint32_t)(addr)), "r"((uint32_t)(bytes)) : "memory")
#define MBARRIER_WAIT_PARITY(addr, par) do { \
    uint32_t _m = (uint32_t)(addr); uint32_t _p = (uint32_t)(par); uint32_t _d; \
    asm volatile("{\n\t.reg .pred p;\n\tmbarrier.try_wait.parity.shared.b64 p, [%1], %2;\n\tselp.b32 %0, 1, 0, p;\n\t}" \
        : "=r"(_d) : "r"(_m), "r"(_p) : "memory"); \
    if (!_d) { \
        asm volatile("{\n\t.reg .pred P1;\n\tWL_%=:\n\tmbarrier.try_wait.parity.shared.b64 P1, [%0], %1;\n\t@P1 bra.uni WD_%=;\n\tbra.uni WL_%=;\n\tWD_%=:\n\t}" \
            :: "r"(_m), "r"(_p) : "memory"); \
    } \
} while (0)
#define BULK_G2S(dst, src, bytes, mb) \
    asm volatile("cp.async.bulk.shared::cluster.global.mbarrier::complete_tx::bytes [%0], [%1], %2, [%3];" \
        :: "r"((uint32_t)(dst)), "l"(src), "r"((uint32_t)(bytes)), "r"((uint32_t)(mb)) : "memory")

__global__ void init_kernel(const float* __restrict__ hidden) {
    if (blockIdx.x == 0 && threadIdx.x == 0) g_bar_cnt = 0u;
    int i = blockIdx.x * blockDim.x + threadIdx.x;
    if (i < BB*HID) g_hbuf[0][i] = hidden[i];
}

// weights -> padded chunk-major fp16 image: dst[((chunk*4+mt)*128+row)*20+word]
template<int KTOT>
__global__ void prepw_kernel(const float* __restrict__ w, uint32_t* __restrict__ wb) {
    int i = blockIdx.x*256 + threadIdx.x;
    if (i >= 512*(KTOT/2)) return;
    int co = i / (KTOT/2), wp = i % (KTOT/2);
    int chunk = wp >> 4, word = wp & 15;
    size_t d = (((size_t)chunk*4 + (co>>7))*128 + (co&127))*20 + word;
    wb[d] = pack_h2(w[(size_t)co*KTOT + 2*wp], w[(size_t)co*KTOT + 2*wp + 1]);
}

template<int LIN, int LPW, int SH>
__global__ void prepa_kernel(const float* __restrict__ raw, const float* __restrict__ sc,
                             const float* __restrict__ shf) {
    int ci = blockIdx.x, b = blockIdx.y;
    float s = sc[ci], t = shf[ci];
    const float* src = raw + ((size_t)b*CC + ci)*LIN;
    uint32_t* db = g_apb + ((size_t)(b*CC) + ci)*LPW;
    for (int w = threadIdx.x; w < LPW; w += 256) {
        int p0 = 2*w - SH;
        float v0 = (p0 >= 0 && p0 < LIN) ? fmaxf(fmaf(src[p0], s, t), 0.f) : 0.f;
        float v1 = (p0+1 >= 0 && p0+1 < LIN) ? fmaxf(fmaf(src[p0+1], s, t), 0.f) : 0.f;
        db[w] = pack_h2(v0, v1);
    }
}

__global__ void conv1_kernel(const float* __restrict__ x, const float* __restrict__ w) {
    __shared__ float wsm[CC*10];
    __shared__ float xs[256*5 + 10];
    int b = blockIdx.y, o0 = blockIdx.x * 256, tid = threadIdx.x;
    for (int i = tid; i < CC*10; i += 256) wsm[i] = w[i];
    int p0 = o0*5 - 3;
    for (int i = tid; i < 256*5 + 10; i += 256) {
        int p = p0 + i;
        xs[i] = (p >= 0 && p < L0) ? x[b*L0 + p] : 0.f;
    }
    __syncthreads();
    int o = o0 + tid;
    if (o >= L1) return;
    float xr[10];
#pragma unroll
    for (int j = 0; j < 10; j++) xr[j] = xs[tid*5 + j];
    for (int co = 0; co < CC; co++) {
        float acc = 0.f;
#pragma unroll
        for (int j = 0; j < 10; j++) acc = fmaf(wsm[co*10 + j], xr[j], acc);
        g_c1[(b*CC + co)*L1 + o] = acc;
    }
}

__global__ void stats_kernel(const float* __restrict__ raw, const float* __restrict__ gamma,
                             const float* __restrict__ beta, float* __restrict__ scale,
                             float* __restrict__ shift, int L) {
    int c = blockIdx.x, tid = threadIdx.x;
    double s = 0.0, s2 = 0.0;
    for (int b = 0; b < BB; b++) {
        const float* p = raw + (size_t)(b*CC + c)*L;
        for (int l = tid; l < L; l += 256) { float v = p[l]; s += v; s2 += (double)v*v; }
    }
    __shared__ double rs[256], rs2[256];
    rs[tid] = s; rs2[tid] = s2; __syncthreads();
    for (int st = 128; st > 0; st >>= 1) {
        if (tid < st) { rs[tid] += rs[tid+st]; rs2[tid] += rs2[tid+st]; }
        __syncthreads();
    }
    if (tid == 0) {
        double n = (double)BB * (double)L;
        double mean = rs[0]/n, var = rs2[0]/n - mean*mean;
        double sc = (double)gamma[c] / sqrt(var + 1e-5);
        scale[c] = (float)sc;
        shift[c] = (float)((double)beta[c] - mean*sc);
    }
}

// ===== all-TMA fp16 conv: 128co x 128n tile, 256 thr, 2 CTA/SM, 3 stages, 1 mma/tile =====
template<int KW, int S, int KTOT, int LPW, int NW>
__global__ void __launch_bounds__(256, 2)
conv_tc_kernel(const uint32_t* __restrict__ pb, const uint32_t* __restrict__ wb,
               float* __restrict__ out, int Lout) {
    constexpr int CI = 32/KW, NC = KTOT/32;
    constexpr int AW = 2560;                 // 128 rows x 20 words
    constexpr int BSTW = CI*NW;
    constexpr int STGW = AW + BSTW;
    constexpr int HDR = 32;
    extern __shared__ __align__(128) uint32_t smw[];
    uint32_t sbase = smem_to_u32(smw);
    int tid = threadIdx.x, wid = tid >> 5, lane = tid & 31;
    int g = lane >> 2, tig = lane & 3;
    int warp_m = wid >> 1, warp_n = wid & 1;
    int n0 = blockIdx.x*128, b = blockIdx.z;
    uint32_t txb = (uint32_t)(10240 + CI*NW*4);

    if (tid == 0) { MBARRIER_INIT(sbase, 1); MBARRIER_INIT(sbase + 8, 1); MBARRIER_INIT(sbase + 16, 1); }
    __syncthreads();
    asm volatile("fence.proxy.async;" ::: "memory");

    auto issue = [&](int c, int s) {
        uint32_t mb = sbase + s*8;
        uint32_t ast = sbase + (uint32_t)(HDR + s*STGW)*4;
        uint32_t bst = ast + AW*4;
        MBARRIER_EXPECT_TX(mb, txb);
        size_t aoff = ((size_t)c*4 + blockIdx.y)*AW;
        BULK_G2S(ast, wb + aoff, 10240, mb);
        int base = n0*(S/2);
        for (int r = 0; r < CI; r++) {
            size_t so = ((size_t)(b*CC) + (size_t)c*CI + r)*LPW + base;
            BULK_G2S(bst + (uint32_t)(r*NW)*4, pb + so, NW*4, mb);
        }
    };
    if (tid == 0) { issue(0, 0); issue(1, 1); issue(2, 2); }

    float acc[2][8][4];
#pragma unroll
    for (int mt = 0; mt < 2; mt++)
#pragma unroll
        for (int nt = 0; nt < 8; nt++)
#pragma unroll
            for (int q = 0; q < 4; q++) acc[mt][nt][q] = 0.f;

    int ph[3] = {0, 0, 0};
    int s = 0;
    for (int c = 0; c < NC; c++) {
        MBARRIER_WAIT_PARITY(sbase + s*8, ph[s]); ph[s] ^= 1;
        int Ab = HDR + s*STGW;
        int Bb = Ab + AW;
#pragma unroll
        for (int ks = 0; ks < 2; ks++) {
            int kw = ks*8;
            uint32_t ab[2][4];
#pragma unroll
            for (int mt = 0; mt < 2; mt++) {
                int r = warp_m*32 + mt*16 + g;
                ab[mt][0] = smw[Ab + r*20 + kw + tig];
                ab[mt][1] = smw[Ab + (r+8)*20 + kw + tig];
                ab[mt][2] = smw[Ab + r*20 + kw + tig + 4];
                ab[mt][3] = smw[Ab + (r+8)*20 + kw + tig + 4];
            }
#pragma unroll
            for (int nt = 0; nt < 8; nt++) {
                int nl = warp_n*64 + nt*8 + g;
                uint32_t bbf[2];
#pragma unroll
                for (int j = 0; j < 2; j++) {
                    int kk = ks*16 + 8*j + 2*tig;
                    int cil = kk / KW, jj = kk - cil*KW;
                    bbf[j] = smw[Bb + cil*NW + nl*(S/2) + (jj >> 1)];
                }
#pragma unroll
                for (int mt = 0; mt < 2; mt++)
                    mma_fp16(acc[mt][nt], ab[mt], bbf);
            }
        }
        __syncthreads();
        if (tid == 0 && c + 3 < NC) issue(c + 3, s);
        s = (s == 2) ? 0 : s + 1;
    }

#pragma unroll
    for (int mt = 0; mt < 2; mt++) {
        int co0 = blockIdx.y*128 + warp_m*32 + mt*16 + g;
#pragma unroll
        for (int nt = 0; nt < 8; nt++) {
            int n = n0 + warp_n*64 + nt*8 + 2*tig;
            if (n < Lout) {
                *(float2*)&out[(size_t)(b*CC + co0)*Lout + n]     = make_float2(acc[mt][nt][0], acc[mt][nt][1]);
                *(float2*)&out[(size_t)(b*CC + co0 + 8)*Lout + n] = make_float2(acc[mt][nt][2], acc[mt][nt][3]);
            }
        }
    }
}

__global__ void buildz_kernel(const int* __restrict__ ts, const float* __restrict__ sc,
                              const float* __restrict__ sh) {
    int t = blockIdx.x, b = blockIdx.y, d = threadIdx.x;
    float v = 0.f;
    if (t <= ts[b]) {
        float r = g_c5[(b*CC + d)*L5 + t];
        v = fmaxf(fmaf(r, sc[d], sh[d]), 0.f);
    }
    g_z[(t*BB + b)*CC + d] = v;
}

__global__ void gi_gemm_kernel(const float* __restrict__ wih) {
    __shared__ float As[16*65];
    __shared__ float Bs[16*65];
    int tid = threadIdx.x, tx = tid & 15, ty = tid >> 4;
    int r0 = blockIdx.x * 64, g0 = blockIdx.y * 64;
    float acc[4][4] = {};
    for (int k0 = 0; k0 < CC; k0 += 16) {
        for (int i = tid; i < 1024; i += 256) {
            int rl = i >> 4, kk = i & 15;
            As[kk*65 + rl] = g_z[(r0+rl)*CC + k0 + kk];
            Bs[kk*65 + rl] = wih[(g0+rl)*CC + k0 + kk];
        }
        __syncthreads();
#pragma unroll
        for (int kk = 0; kk < 16; kk++) {
            float av[4], bv[4];
#pragma unroll
            for (int i = 0; i < 4; i++) av[i] = As[kk*65 + ty*4 + i];
#pragma unroll
            for (int j = 0; j < 4; j++) bv[j] = Bs[kk*65 + tx*4 + j];
#pragma unroll
            for (int i = 0; i < 4; i++)
#pragma unroll
                for (int j = 0; j < 4; j++)
                    acc[i][j] = fmaf(av[i], bv[j], acc[i][j]);
        }
        __syncthreads();
    }
#pragma unroll
    for (int i = 0; i < 4; i++)
#pragma unroll
        for (int j = 0; j < 4; j++)
            g_gi[(r0 + ty*4 + i)*768 + g0 + tx*4 + j] = acc[i][j];
}

__global__ void gru_kernel(const float* __restrict__ whh, const float* __restrict__ bih,
                           const float* __restrict__ bhh, const int* __restrict__ ts) {
    __shared__ float ws[3*8*256];
    __shared__ float h_s[BB*HID];
    __shared__ float part[BB*8*2*3];
    __shared__ float bih_s[24], bhh_s[24];
    __shared__ int ts_s[BB];
    int tid = threadIdx.x, j0 = blockIdx.x * 8;
    int b = tid >> 4, jl = (tid >> 1) & 7, half = tid & 1;
    for (int i = tid; i < 6144; i += 256) {
        int g = i >> 11, rest = i & 2047, jj = rest >> 8, k = rest & 255;
        ws[i] = whh[(g*256 + j0 + jj)*256 + k];
    }
    if (tid < 24) {
        int g = tid / 8, jj = tid % 8;
        bih_s[tid] = bih[g*256 + j0 + jj];
        bhh_s[tid] = bhh[g*256 + j0 + jj];
    }
    if (tid < BB) ts_s[tid] = ts[tid];
    __syncthreads();
    for (int t = 0; t < TT; t++) {
        const float* hin = g_hbuf[t & 1];
        for (int i = tid; i < BB*HID; i += 256) h_s[i] = __ldcg(&hin[i]);
        __syncthreads();
        float ar = 0.f, az = 0.f, an = 0.f;
        const float4* h4  = (const float4*)&h_s[b*256 + half*128];
        const float4* wr4 = (const float4*)&ws[(0*8 + jl)*256 + half*128];
        const float4* wz4 = (const float4*)&ws[(1*8 + jl)*256 + half*128];
        const float4* wn4 = (const float4*)&ws[(2*8 + jl)*256 + half*128];
#pragma unroll 8
        for (int k = 0; k < 32; k++) {
            float4 hv = h4[k];
            float4 a = wr4[k]; ar += a.x*hv.x + a.y*hv.y + a.z*hv.z + a.w*hv.w;
            float4 c = wz4[k]; az += c.x*hv.x + c.y*hv.y + c.z*hv.z + c.w*hv.w;
            float4 d = wn4[k]; an += d.x*hv.x + d.y*hv.y + d.z*hv.z + d.w*hv.w;
        }
        int pb = ((b*8 + jl)*2 + half)*3;
        part[pb+0] = ar; part[pb+1] = az; part[pb+2] = an;
        __syncthreads();
        if (half == 0) {
            int p2 = ((b*8 + jl)*2)*3;
            float hr = part[p2+0] + part[p2+3] + bhh_s[jl];
            float hz = part[p2+1] + part[p2+4] + bhh_s[8+jl];
            float hn = part[p2+2] + part[p2+5] + bhh_s[16+jl];
            const float* gi = &g_gi[(t*BB + b)*768];
            float ir  = gi[j0+jl]       + bih_s[jl];
            float iz  = gi[256 + j0+jl] + bih_s[8+jl];
            float in_ = gi[512 + j0+jl] + bih_s[16+jl];
            float r  = 1.f / (1.f + expf(-(ir + hr)));
            float zg = 1.f / (1.f + expf(-(iz + hz)));
            float n  = tanhf(in_ + r*hn);
            float hprev = h_s[b*256 + j0 + jl];
            float hnew = (1.f - zg)*n + zg*hprev;
            __stcg(&g_hbuf[(t+1) & 1][b*256 + j0 + jl], hnew);
            if (t == ts_s[b]) g_ct[b*256 + j0 + jl] = hnew;
            __threadfence();
        }
        __syncthreads();
        if (tid == 0) {
            atomicAdd(&g_bar_cnt, 1u);
            unsigned target = 32u * (unsigned)(t + 1);
            while (*((volatile unsigned*)&g_bar_cnt) < target) { }
        }
        __syncthreads();
    }
}

__global__ void enc_kernel(const int* __restrict__ ts, const float* __restrict__ sc,
                           const float* __restrict__ sh) {
    int k = blockIdx.x, b = blockIdx.y, d = threadIdx.x;
    int t = ts[b] + k + 1;
    float r = g_c5[(b*CC + d)*L5 + t];
    g_enc[(k*BB + b)*CC + d] = fmaxf(fmaf(r, sc[d], sh[d]), 0.f);
}

__global__ void pred_kernel(const float* __restrict__ wk, const float* __restrict__ wkb) {
    int k = blockIdx.x, b = blockIdx.y, d = threadIdx.x;
    __shared__ float ct[HID];
    if (d < HID) ct[d] = g_ct[b*HID + d];
    __syncthreads();
    float acc = wkb[k*CC + d];
    const float4* w4 = (const float4*)&wk[(k*CC + d)*HID];
#pragma unroll 4
    for (int h = 0; h < HID/4; h++) {
        float4 w = w4[h];
        const float* c = &ct[h*4];
        acc += w.x*c[0] + w.y*c[1] + w.z*c[2] + w.w*c[3];
    }
    g_pred[(k*BB + b)*CC + d] = acc;
}

__global__ void total_kernel() {
    int k = blockIdx.x, tid = threadIdx.x;
    int b = tid >> 4, c = tid & 15;
    const float* e = &g_enc[(k*BB + b)*CC];
    const float* p = &g_pred[(k*BB + c)*CC];
    float acc = 0.f;
    for (int d = 0; d < CC; d++) acc += e[d] * p[d];
    g_total[(k*BB + b)*BB + c] = acc;
}

__global__ void final_kernel(float* __restrict__ out) {
    __shared__ float lse_s[KCPC*BB];
    __shared__ float contrib[KCPC*BB];
    __shared__ int corr[BB];
    int tid = threadIdx.x;
    if (tid < KCPC*BB) {
        int b = tid & 15;
        const float* row = &g_total[tid*BB];
        float m = row[0];
        for (int c = 1; c < BB; c++) m = fmaxf(m, row[c]);
        float s = 0.f;
        for (int c = 0; c < BB; c++) s += expf(row[c] - m);
        float lse = m + logf(s);
        lse_s[tid] = lse;
        contrib[tid] = row[b] - lse;
    }
    __syncthreads();
    if (tid == 0) {
        float s = 0.f;
        for (int i = 0; i < KCPC*BB; i++) s += contrib[i];
        out[1] = s / (-(float)(BB*KCPC));
    }
    if (tid < BB) {
        int c = tid;
        float best = -1e30f; int bi = -1;
        for (int b = 0; b < BB; b++) {
            float v = g_total[((KCPC-1)*BB + b)*BB + c] - lse_s[(KCPC-1)*BB + b];
            if (v > best) { best = v; bi = b; }
        }
        corr[tid] = (bi == c) ? 1 : 0;
    }
    __syncthreads();
    if (tid == 0) {
        int cs = 0;
        for (int i = 0; i < BB; i++) cs += corr[i];
        out[0] = (float)cs / (float)BB;
    }
    for (int i = tid; i < BB*HID; i += blockDim.x) out[2 + i] = g_hbuf[0][i];
}

extern "C" void kernel_launch(void* const* d_in, const int* in_sizes, int n_in,
                              void* d_out, int out_size) {
    (void)in_sizes; (void)n_in; (void)out_size;
    const float* x      = (const float*)d_in[0];
    const float* hidden = (const float*)d_in[1];
    const int*   tsamp  = (const int*)d_in[3];
    const float* w1     = (const float*)d_in[4];
    const float* w2     = (const float*)d_in[5];
    const float* w345   = (const float*)d_in[6];
    const float* gamma  = (const float*)d_in[7];
    const float* beta   = (const float*)d_in[8];
    const float* wih    = (const float*)d_in[9];
    const float* whh    = (const float*)d_in[10];
    const float* bih    = (const float*)d_in[11];
    const float* bhh    = (const float*)d_in[12];
    const float* wk     = (const float*)d_in[13];
    const float* wkb    = (const float*)d_in[14];
    float* out = (float*)d_out;

    float *p_c1, *p_c2, *p_c3, *p_c4, *p_c5, *p_sc, *p_sh;
    uint32_t *p_w2b, *p_w345b, *p_apb;
    cudaGetSymbolAddress((void**)&p_c1, g_c1);
    cudaGetSymbolAddress((void**)&p_c2, g_c2);
    cudaGetSymbolAddress((void**)&p_c3, g_c3);
    cudaGetSymbolAddress((void**)&p_c4, g_c4);
    cudaGetSymbolAddress((void**)&p_c5, g_c5);
    cudaGetSymbolAddress((void**)&p_sc, g_scale);
    cudaGetSymbolAddress((void**)&p_sh, g_shift);
    cudaGetSymbolAddress((void**)&p_w2b, g_w2b);
    cudaGetSymbolAddress((void**)&p_w345b, g_w345b);
    cudaGetSymbolAddress((void**)&p_apb, g_apb);

    const int SM_L2   = (32 + 3*(2560 + 4*260))*4;   // 43328
    const int SM_L345 = (32 + 3*(2560 + 8*132))*4;   // 43520
    cudaFuncSetAttribute(conv_tc_kernel<8,4,4096,8200,260>,
                         cudaFuncAttributeMaxDynamicSharedMemorySize, SM_L2);
    cudaFuncSetAttribute(conv_tc_kernel<4,2,2048,2056,132>,
                         cudaFuncAttributeMaxDynamicSharedMemorySize, SM_L345);
    cudaFuncSetAttribute(conv_tc_kernel<4,2,2048,1032,132>,
                         cudaFuncAttributeMaxDynamicSharedMemorySize, SM_L345);
    cudaFuncSetAttribute(conv_tc_kernel<4,2,2048,520,132>,
                         cudaFuncAttributeMaxDynamicSharedMemorySize, SM_L345);

    init_kernel<<<16, 256>>>(hidden);
    prepw_kernel<4096><<<(512*2048 + 255)/256, 256>>>(w2, p_w2b);
    prepw_kernel<2048><<<(512*1024 + 255)/256, 256>>>(w345 + 0*512*2048, p_w345b + 0*655360);
    prepw_kernel<2048><<<(512*1024 + 255)/256, 256>>>(w345 + 1*512*2048, p_w345b + 1*655360);
    prepw_kernel<2048><<<(512*1024 + 255)/256, 256>>>(w345 + 2*512*2048, p_w345b + 2*655360);

    conv1_kernel<<<dim3(63, BB), 256>>>(x, w1);
    stats_kernel<<<CC, 256>>>(p_c1, gamma, beta, p_sc, p_sh, L1);
    prepa_kernel<L1,8200,2><<<dim3(CC, BB), 256>>>(p_c1, p_sc, p_sh);

    conv_tc_kernel<8,4,4096,8200,260><<<dim3(32, 4, BB), 256, SM_L2>>>(
        p_apb, p_w2b, p_c2, L2);
    stats_kernel<<<CC, 256>>>(p_c2, gamma + CC, beta + CC, p_sc + CC, p_sh + CC, L2);
    prepa_kernel<L2,2056,1><<<dim3(CC, BB), 256>>>(p_c2, p_sc + CC, p_sh + CC);

    conv_tc_kernel<4,2,2048,2056,132><<<dim3(16, 4, BB), 256, SM_L345>>>(
        p_apb, p_w345b + 0*655360, p_c3, L3);
    stats_kernel<<<CC, 256>>>(p_c3, gamma + 2*CC, beta + 2*CC, p_sc + 2*CC, p_sh + 2*CC, L3);
    prepa_kernel<L3,1032,1><<<dim3(CC, BB), 256>>>(p_c3, p_sc + 2*CC, p_sh + 2*CC);

    conv_tc_kernel<4,2,2048,1032,132><<<dim3(8, 4, BB), 256, SM_L345>>>(
        p_apb, p_w345b + 1*655360, p_c4, L4);
    stats_kernel<<<CC, 256>>>(p_c4, gamma + 3*CC, beta + 3*CC, p_sc + 3*CC, p_sh + 3*CC, L4);
    prepa_kernel<L4,520,1><<<dim3(CC, BB), 256>>>(p_c4, p_sc + 3*CC, p_sh + 3*CC);

    conv_tc_kernel<4,2,2048,520,132><<<dim3(4, 4, BB), 256, SM_L345>>>(
        p_apb, p_w345b + 2*655360, p_c5, L5);
    stats_kernel<<<CC, 256>>>(p_c5, gamma + 4*CC, beta + 4*CC, p_sc + 4*CC, p_sh + 4*CC, L5);

    buildz_kernel<<<dim3(TT, BB), CC>>>(tsamp, p_sc + 4*CC, p_sh + 4*CC);
    gi_gemm_kernel<<<dim3(125, 12), 256>>>(wih);
    gru_kernel<<<32, 256>>>(whh, bih, bhh, tsamp);

    enc_kernel<<<dim3(KCPC, BB), CC>>>(tsamp, p_sc + 4*CC, p_sh + 4*CC);
    pred_kernel<<<dim3(KCPC, BB), CC>>>(wk, wkb);
    total_kernel<<<KCPC, 256>>>();
    final_kernel<<<1, 256>>>(out);
}

// round 13
// speedup vs baseline: 2.0959x; 1.0042x over previous
#include <cuda_runtime.h>
#include <cuda_fp16.h>
#include <math.h>
#include <stdint.h>

#define BB 16
#define CC 512
#define L0 80000
#define L1 16000
#define L2 4000
#define L3 2000
#define L4 1000
#define L5 500
#define TT 500
#define HID 256
#define KCPC 12

__device__ float g_c1[BB*CC*L1];
__device__ float g_c2[BB*CC*L2];
__device__ float g_c3[BB*CC*L3];
__device__ float g_c4[BB*CC*L4];
__device__ float g_c5[BB*CC*L5];
__device__ float g_scale[5*CC];
__device__ float g_shift[5*CC];
__device__ uint32_t g_w2b[1310720];     // fp16x2 chunk64-major: [64ch][4mt][128][40]
__device__ uint32_t g_w345b[3*655360];  // [32ch][4mt][128][40] per layer
__device__ uint32_t g_apb[(size_t)BB*CC*8200];   // fp16x2 activations
__device__ float g_z[TT*BB*CC];
__device__ float g_gi[TT*BB*768];
__device__ float g_hbuf[2][BB*HID];
__device__ float g_ct[BB*HID];
__device__ float g_enc[KCPC*BB*CC];
__device__ float g_pred[KCPC*BB*CC];
__device__ float g_total[KCPC*BB*BB];
__device__ unsigned g_bar_cnt;

__device__ __forceinline__ uint32_t smem_to_u32(const void* p) {
    uint32_t a;
    asm("{ .reg .u64 t; cvta.to.shared.u64 t, %1; cvt.u32.u64 %0, t; }" : "=r"(a) : "l"(p));
    return a;
}
__device__ __forceinline__ uint32_t pack_h2(float v0, float v1) {
    __half2 h = __floats2half2_rn(v0, v1);
    return *(uint32_t*)&h;
}
__device__ __forceinline__ void mma_fp16(float* d, const uint32_t* a, const uint32_t* bfr) {
    asm volatile(
        "mma.sync.aligned.m16n8k16.row.col.f32.f16.f16.f32 "
        "{%0,%1,%2,%3}, {%4,%5,%6,%7}, {%8,%9}, {%0,%1,%2,%3};"
        : "+f"(d[0]), "+f"(d[1]), "+f"(d[2]), "+f"(d[3])
        : "r"(a[0]), "r"(a[1]), "r"(a[2]), "r"(a[3]), "r"(bfr[0]), "r"(bfr[1]));
}
#define MBARRIER_INIT(addr, cnt) \
    asm volatile("mbarrier.init.shared.b64 [%0], %1;" :: "r"((uint32_t)(addr)), "r"((uint32_t)(cnt)) : "memory")
#define MBARRIER_EXPECT_TX(addr, bytes) \
    asm volatile("mbarrier.arrive.expect_tx.shared.b64 _, [%0], %1;" :: "r"((uint32_t)(addr)), "r"((uint32_t)(bytes)) : "memory")
#define MBARRIER_WAIT_PARITY(addr, par) do { \
    uint32_t _m = (uint32_t)(addr); uint32_t _p = (uint32_t)(par); uint32_t _d; \
    asm volatile("{\n\t.reg .pred p;\n\tmbarrier.try_wait.parity.shared.b64 p, [%1], %2;\n\tselp.b32 %0, 1, 0, p;\n\t}" \
        : "=r"(_d) : "r"(_m), "r"(_p) : "memory"); \
    if (!_d) { \
        asm volatile("{\n\t.reg .pred P1;\n\tWL_%=:\n\tmbarrier.try_wait.parity.shared.b64 P1, [%0], %1;\n\t@P1 bra.uni WD_%=;\n\tbra.uni WL_%=;\n\tWD_%=:\n\t}" \
            :: "r"(_m), "r"(_p) : "memory"); \
    } \
} while (0)
#define BULK_G2S(dst, src, bytes, mb) \
    asm volatile("cp.async.bulk.shared::cluster.global.mbarrier::complete_tx::bytes [%0], [%1], %2, [%3];" \
        :: "r"((uint32_t)(dst)), "l"(src), "r"((uint32_t)(bytes)), "r"((uint32_t)(mb)) : "memory")

__global__ void init_kernel(const float* __restrict__ hidden) {
    if (blockIdx.x == 0 && threadIdx.x == 0) g_bar_cnt = 0u;
    int i = blockIdx.x * blockDim.x + threadIdx.x;
    if (i < BB*HID) g_hbuf[0][i] = hidden[i];
}

// weights -> padded chunk64-major fp16 image: dst[((chunk*4+mt)*128+row)*40+word]
template<int KTOT>
__global__ void prepw_kernel(const float* __restrict__ w, uint32_t* __restrict__ wb) {
    int i = blockIdx.x*256 + threadIdx.x;
    if (i >= 512*(KTOT/2)) return;
    int co = i / (KTOT/2), wp = i % (KTOT/2);
    int chunk = wp >> 5, word = wp & 31;
    size_t d = (((size_t)chunk*4 + (co>>7))*128 + (co&127))*40 + word;
    wb[d] = pack_h2(w[(size_t)co*KTOT + 2*wp], w[(size_t)co*KTOT + 2*wp + 1]);
}

template<int LIN, int LPW, int SH>
__global__ void prepa_kernel(const float* __restrict__ raw, const float* __restrict__ sc,
                             const float* __restrict__ shf) {
    int ci = blockIdx.x, b = blockIdx.y;
    float s = sc[ci], t = shf[ci];
    const float* src = raw + ((size_t)b*CC + ci)*LIN;
    uint32_t* db = g_apb + ((size_t)(b*CC) + ci)*LPW;
    for (int w = threadIdx.x; w < LPW; w += 256) {
        int p0 = 2*w - SH;
        float v0 = (p0 >= 0 && p0 < LIN) ? fmaxf(fmaf(src[p0], s, t), 0.f) : 0.f;
        float v1 = (p0+1 >= 0 && p0+1 < LIN) ? fmaxf(fmaf(src[p0+1], s, t), 0.f) : 0.f;
        db[w] = pack_h2(v0, v1);
    }
}

__global__ void conv1_kernel(const float* __restrict__ x, const float* __restrict__ w) {
    __shared__ float wsm[CC*10];
    __shared__ float xs[256*5 + 10];
    int b = blockIdx.y, o0 = blockIdx.x * 256, tid = threadIdx.x;
    for (int i = tid; i < CC*10; i += 256) wsm[i] = w[i];
    int p0 = o0*5 - 3;
    for (int i = tid; i < 256*5 + 10; i += 256) {
        int p = p0 + i;
        xs[i] = (p >= 0 && p < L0) ? x[b*L0 + p] : 0.f;
    }
    __syncthreads();
    int o = o0 + tid;
    if (o >= L1) return;
    float xr[10];
#pragma unroll
    for (int j = 0; j < 10; j++) xr[j] = xs[tid*5 + j];
    for (int co = 0; co < CC; co++) {
        float acc = 0.f;
#pragma unroll
        for (int j = 0; j < 10; j++) acc = fmaf(wsm[co*10 + j], xr[j], acc);
        g_c1[(b*CC + co)*L1 + o] = acc;
    }
}

__global__ void stats_kernel(const float* __restrict__ raw, const float* __restrict__ gamma,
                             const float* __restrict__ beta, float* __restrict__ scale,
                             float* __restrict__ shift, int L) {
    int c = blockIdx.x, tid = threadIdx.x;
    double s = 0.0, s2 = 0.0;
    for (int b = 0; b < BB; b++) {
        const float* p = raw + (size_t)(b*CC + c)*L;
        for (int l = tid; l < L; l += 256) { float v = p[l]; s += v; s2 += (double)v*v; }
    }
    __shared__ double rs[256], rs2[256];
    rs[tid] = s; rs2[tid] = s2; __syncthreads();
    for (int st = 128; st > 0; st >>= 1) {
        if (tid < st) { rs[tid] += rs[tid+st]; rs2[tid] += rs2[tid+st]; }
        __syncthreads();
    }
    if (tid == 0) {
        double n = (double)BB * (double)L;
        double mean = rs[0]/n, var = rs2[0]/n - mean*mean;
        double sc = (double)gamma[c] / sqrt(var + 1e-5);
        scale[c] = (float)sc;
        shift[c] = (float)((double)beta[c] - mean*sc);
    }
}

// ===== all-TMA fp16 conv: 128co x 128n tile, K-chunk 64, 256 thr, 2 CTA/SM, 3 stages =====
template<int KW, int S, int KTOT, int LPW, int NW>
__global__ void __launch_bounds__(256, 2)
conv_tc_kernel(const uint32_t* __restrict__ pb, const uint32_t* __restrict__ wb,
               float* __restrict__ out, int Lout) {
    constexpr int CI = 64/KW, NC = KTOT/64;
    constexpr int AW = 5120;                 // 128 rows x 40 words
    constexpr int BSTW = CI*NW;
    constexpr int STGW = AW + BSTW;
    constexpr int HDR = 32;
    extern __shared__ __align__(128) uint32_t smw[];
    uint32_t sbase = smem_to_u32(smw);
    int tid = threadIdx.x, wid = tid >> 5, lane = tid & 31;
    int g = lane >> 2, tig = lane & 3;
    int warp_m = wid >> 1, warp_n = wid & 1;
    int n0 = blockIdx.x*128, b = blockIdx.z;
    uint32_t txb = (uint32_t)(20480 + CI*NW*4);

    if (tid == 0) { MBARRIER_INIT(sbase, 1); MBARRIER_INIT(sbase + 8, 1); MBARRIER_INIT(sbase + 16, 1); }
    __syncthreads();
    asm volatile("fence.proxy.async;" ::: "memory");

    auto issue = [&](int c, int s) {
        uint32_t mb = sbase + s*8;
        uint32_t ast = sbase + (uint32_t)(HDR + s*STGW)*4;
        uint32_t bst = ast + AW*4;
        MBARRIER_EXPECT_TX(mb, txb);
        size_t aoff = ((size_t)c*4 + blockIdx.y)*AW;
        BULK_G2S(ast, wb + aoff, 20480, mb);
        int base = n0*(S/2);
        for (int r = 0; r < CI; r++) {
            size_t so = ((size_t)(b*CC) + (size_t)c*CI + r)*LPW + base;
            BULK_G2S(bst + (uint32_t)(r*NW)*4, pb + so, NW*4, mb);
        }
    };
    if (tid == 0) { issue(0, 0); issue(1, 1); if (NC > 2) issue(2, 2); }

    float acc[2][8][4];
#pragma unroll
    for (int mt = 0; mt < 2; mt++)
#pragma unroll
        for (int nt = 0; nt < 8; nt++)
#pragma unroll
            for (int q = 0; q < 4; q++) acc[mt][nt][q] = 0.f;

    int ph[3] = {0, 0, 0};
    int s = 0;
    for (int c = 0; c < NC; c++) {
        MBARRIER_WAIT_PARITY(sbase + s*8, ph[s]); ph[s] ^= 1;
        int Ab = HDR + s*STGW;
        int Bb = Ab + AW;
#pragma unroll
        for (int ks = 0; ks < 4; ks++) {
            int kw = ks*8;
            uint32_t ab[2][4];
#pragma unroll
            for (int mt = 0; mt < 2; mt++) {
                int r = warp_m*32 + mt*16 + g;
                ab[mt][0] = smw[Ab + r*40 + kw + tig];
                ab[mt][1] = smw[Ab + (r+8)*40 + kw + tig];
                ab[mt][2] = smw[Ab + r*40 + kw + tig + 4];
                ab[mt][3] = smw[Ab + (r+8)*40 + kw + tig + 4];
            }
#pragma unroll
            for (int nt = 0; nt < 8; nt++) {
                int nl = warp_n*64 + nt*8 + g;
                uint32_t bbf[2];
#pragma unroll
                for (int j = 0; j < 2; j++) {
                    int kk = ks*16 + 8*j + 2*tig;
                    int cil = kk / KW, jj = kk - cil*KW;
                    bbf[j] = smw[Bb + cil*NW + nl*(S/2) + (jj >> 1)];
                }
#pragma unroll
                for (int mt = 0; mt < 2; mt++)
                    mma_fp16(acc[mt][nt], ab[mt], bbf);
            }
        }
        __syncthreads();
        if (tid == 0 && c + 3 < NC) issue(c + 3, s);
        s = (s == 2) ? 0 : s + 1;
    }

#pragma unroll
    for (int mt = 0; mt < 2; mt++) {
        int co0 = blockIdx.y*128 + warp_m*32 + mt*16 + g;
#pragma unroll
        for (int nt = 0; nt < 8; nt++) {
            int n = n0 + warp_n*64 + nt*8 + 2*tig;
            if (n < Lout) {
                *(float2*)&out[(size_t)(b*CC + co0)*Lout + n]     = make_float2(acc[mt][nt][0], acc[mt][nt][1]);
                *(float2*)&out[(size_t)(b*CC + co0 + 8)*Lout + n] = make_float2(acc[mt][nt][2], acc[mt][nt][3]);
            }
        }
    }
}

__global__ void buildz_kernel(const int* __restrict__ ts, const float* __restrict__ sc,
                              const float* __restrict__ sh) {
    int t = blockIdx.x, b = blockIdx.y, d = threadIdx.x;
    float v = 0.f;
    if (t <= ts[b]) {
        float r = g_c5[(b*CC + d)*L5 + t];
        v = fmaxf(fmaf(r, sc[d], sh[d]), 0.f);
    }
    g_z[(t*BB + b)*CC + d] = v;
}

__global__ void gi_gemm_kernel(const float* __restrict__ wih) {
    __shared__ float As[16*65];
    __shared__ float Bs[16*65];
    int tid = threadIdx.x, tx = tid & 15, ty = tid >> 4;
    int r0 = blockIdx.x * 64, g0 = blockIdx.y * 64;
    float acc[4][4] = {};
    for (int k0 = 0; k0 < CC; k0 += 16) {
        for (int i = tid; i < 1024; i += 256) {
            int rl = i >> 4, kk = i & 15;
            As[kk*65 + rl] = g_z[(r0+rl)*CC + k0 + kk];
            Bs[kk*65 + rl] = wih[(g0+rl)*CC + k0 + kk];
        }
        __syncthreads();
#pragma unroll
        for (int kk = 0; kk < 16; kk++) {
            float av[4], bv[4];
#pragma unroll
            for (int i = 0; i < 4; i++) av[i] = As[kk*65 + ty*4 + i];
#pragma unroll
            for (int j = 0; j < 4; j++) bv[j] = Bs[kk*65 + tx*4 + j];
#pragma unroll
            for (int i = 0; i < 4; i++)
#pragma unroll
                for (int j = 0; j < 4; j++)
                    acc[i][j] = fmaf(av[i], bv[j], acc[i][j]);
        }
        __syncthreads();
    }
#pragma unroll
    for (int i = 0; i < 4; i++)
#pragma unroll
        for (int j = 0; j < 4; j++)
            g_gi[(r0 + ty*4 + i)*768 + g0 + tx*4 + j] = acc[i][j];
}

__global__ void gru_kernel(const float* __restrict__ whh, const float* __restrict__ bih,
                           const float* __restrict__ bhh, const int* __restrict__ ts) {
    __shared__ float ws[3*8*256];
    __shared__ float h_s[BB*HID];
    __shared__ float part[BB*8*2*3];
    __shared__ float bih_s[24], bhh_s[24];
    __shared__ int ts_s[BB];
    int tid = threadIdx.x, j0 = blockIdx.x * 8;
    int b = tid >> 4, jl = (tid >> 1) & 7, half = tid & 1;
    for (int i = tid; i < 6144; i += 256) {
        int g = i >> 11, rest = i & 2047, jj = rest >> 8, k = rest & 255;
        ws[i] = whh[(g*256 + j0 + jj)*256 + k];
    }
    if (tid < 24) {
        int g = tid / 8, jj = tid % 8;
        bih_s[tid] = bih[g*256 + j0 + jj];
        bhh_s[tid] = bhh[g*256 + j0 + jj];
    }
    if (tid < BB) ts_s[tid] = ts[tid];
    __syncthreads();
    for (int t = 0; t < TT; t++) {
        const float* hin = g_hbuf[t & 1];
        for (int i = tid; i < BB*HID; i += 256) h_s[i] = __ldcg(&hin[i]);
        __syncthreads();
        float ar = 0.f, az = 0.f, an = 0.f;
        const float4* h4  = (const float4*)&h_s[b*256 + half*128];
        const float4* wr4 = (const float4*)&ws[(0*8 + jl)*256 + half*128];
        const float4* wz4 = (const float4*)&ws[(1*8 + jl)*256 + half*128];
        const float4* wn4 = (const float4*)&ws[(2*8 + jl)*256 + half*128];
#pragma unroll 8
        for (int k = 0; k < 32; k++) {
            float4 hv = h4[k];
            float4 a = wr4[k]; ar += a.x*hv.x + a.y*hv.y + a.z*hv.z + a.w*hv.w;
            float4 c = wz4[k]; az += c.x*hv.x + c.y*hv.y + c.z*hv.z + c.w*hv.w;
            float4 d = wn4[k]; an += d.x*hv.x + d.y*hv.y + d.z*hv.z + d.w*hv.w;
        }
        int pb = ((b*8 + jl)*2 + half)*3;
        part[pb+0] = ar; part[pb+1] = az; part[pb+2] = an;
        __syncthreads();
        if (half == 0) {
            int p2 = ((b*8 + jl)*2)*3;
            float hr = part[p2+0] + part[p2+3] + bhh_s[jl];
            float hz = part[p2+1] + part[p2+4] + bhh_s[8+jl];
            float hn = part[p2+2] + part[p2+5] + bhh_s[16+jl];
            const float* gi = &g_gi[(t*BB + b)*768];
            float ir  = gi[j0+jl]       + bih_s[jl];
            float iz  = gi[256 + j0+jl] + bih_s[8+jl];
            float in_ = gi[512 + j0+jl] + bih_s[16+jl];
            float r  = 1.f / (1.f + expf(-(ir + hr)));
            float zg = 1.f / (1.f + expf(-(iz + hz)));
            float n  = tanhf(in_ + r*hn);
            float hprev = h_s[b*256 + j0 + jl];
            float hnew = (1.f - zg)*n + zg*hprev;
            __stcg(&g_hbuf[(t+1) & 1][b*256 + j0 + jl], hnew);
            if (t == ts_s[b]) g_ct[b*256 + j0 + jl] = hnew;
            __threadfence();
        }
        __syncthreads();
        if (tid == 0) {
            atomicAdd(&g_bar_cnt, 1u);
            unsigned target = 32u * (unsigned)(t + 1);
            while (*((volatile unsigned*)&g_bar_cnt) < target) { }
        }
        __syncthreads();
    }
}

__global__ void enc_kernel(const int* __restrict__ ts, const float* __restrict__ sc,
                           const float* __restrict__ sh) {
    int k = blockIdx.x, b = blockIdx.y, d = threadIdx.x;
    int t = ts[b] + k + 1;
    float r = g_c5[(b*CC + d)*L5 + t];
    g_enc[(k*BB + b)*CC + d] = fmaxf(fmaf(r, sc[d], sh[d]), 0.f);
}

__global__ void pred_kernel(const float* __restrict__ wk, const float* __restrict__ wkb) {
    int k = blockIdx.x, b = blockIdx.y, d = threadIdx.x;
    __shared__ float ct[HID];
    if (d < HID) ct[d] = g_ct[b*HID + d];
    __syncthreads();
    float acc = wkb[k*CC + d];
    const float4* w4 = (const float4*)&wk[(k*CC + d)*HID];
#pragma unroll 4
    for (int h = 0; h < HID/4; h++) {
        float4 w = w4[h];
        const float* c = &ct[h*4];
        acc += w.x*c[0] + w.y*c[1] + w.z*c[2] + w.w*c[3];
    }
    g_pred[(k*BB + b)*CC + d] = acc;
}

__global__ void total_kernel() {
    int k = blockIdx.x, tid = threadIdx.x;
    int b = tid >> 4, c = tid & 15;
    const float* e = &g_enc[(k*BB + b)*CC];
    const float* p = &g_pred[(k*BB + c)*CC];
    float acc = 0.f;
    for (int d = 0; d < CC; d++) acc += e[d] * p[d];
    g_total[(k*BB + b)*BB + c] = acc;
}

__global__ void final_kernel(float* __restrict__ out) {
    __shared__ float lse_s[KCPC*BB];
    __shared__ float contrib[KCPC*BB];
    __shared__ int corr[BB];
    int tid = threadIdx.x;
    if (tid < KCPC*BB) {
        int b = tid & 15;
        const float* row = &g_total[tid*BB];
        float m = row[0];
        for (int c = 1; c < BB; c++) m = fmaxf(m, row[c]);
        float s = 0.f;
        for (int c = 0; c < BB; c++) s += expf(row[c] - m);
        float lse = m + logf(s);
        lse_s[tid] = lse;
        contrib[tid] = row[b] - lse;
    }
    __syncthreads();
    if (tid == 0) {
        float s = 0.f;
        for (int i = 0; i < KCPC*BB; i++) s += contrib[i];
        out[1] = s / (-(float)(BB*KCPC));
    }
    if (tid < BB) {
        int c = tid;
        float best = -1e30f; int bi = -1;
        for (int b = 0; b < BB; b++) {
            float v = g_total[((KCPC-1)*BB + b)*BB + c] - lse_s[(KCPC-1)*BB + b];
            if (v > best) { best = v; bi = b; }
        }
        corr[tid] = (bi == c) ? 1 : 0;
    }
    __syncthreads();
    if (tid == 0) {
        int cs = 0;
        for (int i = 0; i < BB; i++) cs += corr[i];
        out[0] = (float)cs / (float)BB;
    }
    for (int i = tid; i < BB*HID; i += blockDim.x) out[2 + i] = g_hbuf[0][i];
}

extern "C" void kernel_launch(void* const* d_in, const int* in_sizes, int n_in,
                              void* d_out, int out_size) {
    (void)in_sizes; (void)n_in; (void)out_size;
    const float* x      = (const float*)d_in[0];
    const float* hidden = (const float*)d_in[1];
    const int*   tsamp  = (const int*)d_in[3];
    const float* w1     = (const float*)d_in[4];
    const float* w2     = (const float*)d_in[5];
    const float* w345   = (const float*)d_in[6];
    const float* gamma  = (const float*)d_in[7];
    const float* beta   = (const float*)d_in[8];
    const float* wih    = (const float*)d_in[9];
    const float* whh    = (const float*)d_in[10];
    const float* bih    = (const float*)d_in[11];
    const float* bhh    = (const float*)d_in[12];
    const float* wk     = (const float*)d_in[13];
    const float* wkb    = (const float*)d_in[14];
    float* out = (float*)d_out;

    float *p_c1, *p_c2, *p_c3, *p_c4, *p_c5, *p_sc, *p_sh;
    uint32_t *p_w2b, *p_w345b, *p_apb;
    cudaGetSymbolAddress((void**)&p_c1, g_c1);
    cudaGetSymbolAddress((void**)&p_c2, g_c2);
    cudaGetSymbolAddress((void**)&p_c3, g_c3);
    cudaGetSymbolAddress((void**)&p_c4, g_c4);
    cudaGetSymbolAddress((void**)&p_c5, g_c5);
    cudaGetSymbolAddress((void**)&p_sc, g_scale);
    cudaGetSymbolAddress((void**)&p_sh, g_shift);
    cudaGetSymbolAddress((void**)&p_w2b, g_w2b);
    cudaGetSymbolAddress((void**)&p_w345b, g_w345b);
    cudaGetSymbolAddress((void**)&p_apb, g_apb);

    const int SM_L2   = (32 + 3*(5120 + 8*260))*4;    // 86528
    const int SM_L345 = (32 + 3*(5120 + 16*144))*4;   // 89216
    cudaFuncSetAttribute(conv_tc_kernel<8,4,4096,8200,260>,
                         cudaFuncAttributeMaxDynamicSharedMemorySize, SM_L2);
    cudaFuncSetAttribute(conv_tc_kernel<4,2,2048,2064,144>,
                         cudaFuncAttributeMaxDynamicSharedMemorySize, SM_L345);
    cudaFuncSetAttribute(conv_tc_kernel<4,2,2048,1040,144>,
                         cudaFuncAttributeMaxDynamicSharedMemorySize, SM_L345);
    cudaFuncSetAttribute(conv_tc_kernel<4,2,2048,528,144>,
                         cudaFuncAttributeMaxDynamicSharedMemorySize, SM_L345);

    // order chosen so ncu (-s 5 -c 1) captures conv_tc layer-2 as launch #6
    init_kernel<<<16, 256>>>(hidden);                                         // 1
    conv1_kernel<<<dim3(63, BB), 256>>>(x, w1);                               // 2
    stats_kernel<<<CC, 256>>>(p_c1, gamma, beta, p_sc, p_sh, L1);             // 3
    prepa_kernel<L1,8200,2><<<dim3(CC, BB), 256>>>(p_c1, p_sc, p_sh);         // 4
    prepw_kernel<4096><<<(512*2048 + 255)/256, 256>>>(w2, p_w2b);             // 5

    conv_tc_kernel<8,4,4096,8200,260><<<dim3(32, 4, BB), 256, SM_L2>>>(       // 6 (profiled)
        p_apb, p_w2b, p_c2, L2);

    prepw_kernel<2048><<<(512*1024 + 255)/256, 256>>>(w345 + 0*512*2048, p_w345b + 0*655360);
    prepw_kernel<2048><<<(512*1024 + 255)/256, 256>>>(w345 + 1*512*2048, p_w345b + 1*655360);
    prepw_kernel<2048><<<(512*1024 + 255)/256, 256>>>(w345 + 2*512*2048, p_w345b + 2*655360);

    stats_kernel<<<CC, 256>>>(p_c2, gamma + CC, beta + CC, p_sc + CC, p_sh + CC, L2);
    prepa_kernel<L2,2064,1><<<dim3(CC, BB), 256>>>(p_c2, p_sc + CC, p_sh + CC);

    conv_tc_kernel<4,2,2048,2064,144><<<dim3(16, 4, BB), 256, SM_L345>>>(
        p_apb, p_w345b + 0*655360, p_c3, L3);
    stats_kernel<<<CC, 256>>>(p_c3, gamma + 2*CC, beta + 2*CC, p_sc + 2*CC, p_sh + 2*CC, L3);
    prepa_kernel<L3,1040,1><<<dim3(CC, BB), 256>>>(p_c3, p_sc + 2*CC, p_sh + 2*CC);

    conv_tc_kernel<4,2,2048,1040,144><<<dim3(8, 4, BB), 256, SM_L345>>>(
        p_apb, p_w345b + 1*655360, p_c4, L4);
    stats_kernel<<<CC, 256>>>(p_c4, gamma + 3*CC, beta + 3*CC, p_sc + 3*CC, p_sh + 3*CC, L4);
    prepa_kernel<L4,528,1><<<dim3(CC, BB), 256>>>(p_c4, p_sc + 3*CC, p_sh + 3*CC);

    conv_tc_kernel<4,2,2048,528,144><<<dim3(4, 4, BB), 256, SM_L345>>>(
        p_apb, p_w345b + 2*655360, p_c5, L5);
    stats_kernel<<<CC, 256>>>(p_c5, gamma + 4*CC, beta + 4*CC, p_sc + 4*CC, p_sh + 4*CC, L5);

    buildz_kernel<<<dim3(TT, BB), CC>>>(tsamp, p_sc + 4*CC, p_sh + 4*CC);
    gi_gemm_kernel<<<dim3(125, 12), 256>>>(wih);
    gru_kernel<<<32, 256>>>(whh, bih, bhh, tsamp);

    enc_kernel<<<dim3(KCPC, BB), CC>>>(tsamp, p_sc + 4*CC, p_sh + 4*CC);
    pred_kernel<<<dim3(KCPC, BB), CC>>>(wk, wkb);
    total_kernel<<<KCPC, 256>>>();
    final_kernel<<<1, 256>>>(out);
}

// round 14
// speedup vs baseline: 2.1077x; 1.0056x over previous
#include <cuda_runtime.h>
#include <cuda_fp16.h>
#include <math.h>
#include <stdint.h>

#define BB 16
#define CC 512
#define L0 80000
#define L1 16000
#define L2 4000
#define L3 2000
#define L4 1000
#define L5 500
#define TT 500
#define HID 256
#define KCPC 12

__device__ float g_c1[BB*CC*L1];
__device__ float g_c2[BB*CC*L2];
__device__ float g_c3[BB*CC*L3];
__device__ float g_c4[BB*CC*L4];
__device__ float g_c5[BB*CC*L5];
__device__ float g_scale[5*CC];
__device__ float g_shift[5*CC];
__device__ uint32_t g_w2b[1310720];     // fp16x2 chunk64-major: [64ch][4mt][128][40]
__device__ uint32_t g_w345b[3*655360];  // [32ch][4mt][128][40] per layer
__device__ uint32_t g_apb[(size_t)BB*CC*8200];   // fp16x2 activations
__device__ float g_z[TT*BB*CC];
__device__ float g_gi[TT*BB*768];
__device__ float g_hbuf[2][BB*HID];
__device__ float g_ct[BB*HID];
__device__ float g_enc[KCPC*BB*CC];
__device__ float g_pred[KCPC*BB*CC];
__device__ float g_total[KCPC*BB*BB];
__device__ unsigned g_bar_cnt;

__device__ __forceinline__ uint32_t smem_to_u32(const void* p) {
    uint32_t a;
    asm("{ .reg .u64 t; cvta.to.shared.u64 t, %1; cvt.u32.u64 %0, t; }" : "=r"(a) : "l"(p));
    return a;
}
__device__ __forceinline__ uint32_t pack_h2(float v0, float v1) {
    __half2 h = __floats2half2_rn(v0, v1);
    return *(uint32_t*)&h;
}
__device__ __forceinline__ void mma_fp16(float* d, const uint32_t* a, const uint32_t* bfr) {
    asm volatile(
        "mma.sync.aligned.m16n8k16.row.col.f32.f16.f16.f32 "
        "{%0,%1,%2,%3}, {%4,%5,%6,%7}, {%8,%9}, {%0,%1,%2,%3};"
        : "+f"(d[0]), "+f"(d[1]), "+f"(d[2]), "+f"(d[3])
        : "r"(a[0]), "r"(a[1]), "r"(a[2]), "r"(a[3]), "r"(bfr[0]), "r"(bfr[1]));
}
#define MBARRIER_INIT(addr, cnt) \
    asm volatile("mbarrier.init.shared.b64 [%0], %1;" :: "r"((uint32_t)(addr)), "r"((uint32_t)(cnt)) : "memory")
#define MBARRIER_EXPECT_TX(addr, bytes) \
    asm volatile("mbarrier.arrive.expect_tx.shared.b64 _, [%0], %1;" :: "r"((uint32_t)(addr)), "r"((uint32_t)(bytes)) : "memory")
#define MBARRIER_WAIT_PARITY(addr, par) do { \
    uint32_t _m = (uint32_t)(addr); uint32_t _p = (uint32_t)(par); uint32_t _d; \
    asm volatile("{\n\t.reg .pred p;\n\tmbarrier.try_wait.parity.shared.b64 p, [%1], %2;\n\tselp.b32 %0, 1, 0, p;\n\t}" \
        : "=r"(_d) : "r"(_m), "r"(_p) : "memory"); \
    if (!_d) { \
        asm volatile("{\n\t.reg .pred P1;\n\tWL_%=:\n\tmbarrier.try_wait.parity.shared.b64 P1, [%0], %1;\n\t@P1 bra.uni WD_%=;\n\tbra.uni WL_%=;\n\tWD_%=:\n\t}" \
            :: "r"(_m), "r"(_p) : "memory"); \
    } \
} while (0)
#define BULK_G2S(dst, src, bytes, mb) \
    asm volatile("cp.async.bulk.shared::cluster.global.mbarrier::complete_tx::bytes [%0], [%1], %2, [%3];" \
        :: "r"((uint32_t)(dst)), "l"(src), "r"((uint32_t)(bytes)), "r"((uint32_t)(mb)) : "memory")

__global__ void init_kernel(const float* __restrict__ hidden) {
    if (blockIdx.x == 0 && threadIdx.x == 0) g_bar_cnt = 0u;
    int i = blockIdx.x * blockDim.x + threadIdx.x;
    if (i < BB*HID) g_hbuf[0][i] = hidden[i];
}

// weights -> padded chunk64-major fp16 image: dst[((chunk*4+mt)*128+row)*40+word]
template<int KTOT>
__global__ void prepw_kernel(const float* __restrict__ w, uint32_t* __restrict__ wb) {
    int i = blockIdx.x*256 + threadIdx.x;
    if (i >= 512*(KTOT/2)) return;
    int co = i / (KTOT/2), wp = i % (KTOT/2);
    int chunk = wp >> 5, word = wp & 31;
    size_t d = (((size_t)chunk*4 + (co>>7))*128 + (co&127))*40 + word;
    wb[d] = pack_h2(w[(size_t)co*KTOT + 2*wp], w[(size_t)co*KTOT + 2*wp + 1]);
}

// fused: per-channel batch stats -> (scale,shift) -> packed fp16 activation prep
template<int LIN, int LPW, int SH>
__global__ void statsprep_kernel(const float* __restrict__ raw, const float* __restrict__ gamma,
                                 const float* __restrict__ beta, float* __restrict__ scale,
                                 float* __restrict__ shift) {
    int c = blockIdx.x, tid = threadIdx.x;
    double s = 0.0, s2 = 0.0;
    for (int b = 0; b < BB; b++) {
        const float* p = raw + (size_t)(b*CC + c)*LIN;
        for (int l = tid; l < LIN; l += 256) { float v = p[l]; s += v; s2 += (double)v*v; }
    }
    __shared__ double rs[256], rs2[256];
    __shared__ float sc_s, sh_s;
    rs[tid] = s; rs2[tid] = s2; __syncthreads();
    for (int st = 128; st > 0; st >>= 1) {
        if (tid < st) { rs[tid] += rs[tid+st]; rs2[tid] += rs2[tid+st]; }
        __syncthreads();
    }
    if (tid == 0) {
        double n = (double)BB * (double)LIN;
        double mean = rs[0]/n, var = rs2[0]/n - mean*mean;
        double scd = (double)gamma[c] / sqrt(var + 1e-5);
        float scf = (float)scd;
        float shf = (float)((double)beta[c] - mean*scd);
        scale[c] = scf; shift[c] = shf;
        sc_s = scf; sh_s = shf;
    }
    __syncthreads();
    float scf = sc_s, shf = sh_s;
    for (int b = 0; b < BB; b++) {
        const float* src = raw + (size_t)(b*CC + c)*LIN;
        uint32_t* db = g_apb + ((size_t)(b*CC) + c)*LPW;
        for (int w = tid; w < LPW; w += 256) {
            int p0 = 2*w - SH;
            float v0 = (p0 >= 0 && p0 < LIN) ? fmaxf(fmaf(src[p0], scf, shf), 0.f) : 0.f;
            float v1 = (p0+1 >= 0 && p0+1 < LIN) ? fmaxf(fmaf(src[p0+1], scf, shf), 0.f) : 0.f;
            db[w] = pack_h2(v0, v1);
        }
    }
}

__global__ void conv1_kernel(const float* __restrict__ x, const float* __restrict__ w) {
    __shared__ float wsm[CC*10];
    __shared__ float xs[256*5 + 10];
    int b = blockIdx.y, o0 = blockIdx.x * 256, tid = threadIdx.x;
    for (int i = tid; i < CC*10; i += 256) wsm[i] = w[i];
    int p0 = o0*5 - 3;
    for (int i = tid; i < 256*5 + 10; i += 256) {
        int p = p0 + i;
        xs[i] = (p >= 0 && p < L0) ? x[b*L0 + p] : 0.f;
    }
    __syncthreads();
    int o = o0 + tid;
    if (o >= L1) return;
    float xr[10];
#pragma unroll
    for (int j = 0; j < 10; j++) xr[j] = xs[tid*5 + j];
    for (int co = 0; co < CC; co++) {
        float acc = 0.f;
#pragma unroll
        for (int j = 0; j < 10; j++) acc = fmaf(wsm[co*10 + j], xr[j], acc);
        g_c1[(b*CC + co)*L1 + o] = acc;
    }
}

__global__ void stats_kernel(const float* __restrict__ raw, const float* __restrict__ gamma,
                             const float* __restrict__ beta, float* __restrict__ scale,
                             float* __restrict__ shift, int L) {
    int c = blockIdx.x, tid = threadIdx.x;
    double s = 0.0, s2 = 0.0;
    for (int b = 0; b < BB; b++) {
        const float* p = raw + (size_t)(b*CC + c)*L;
        for (int l = tid; l < L; l += 256) { float v = p[l]; s += v; s2 += (double)v*v; }
    }
    __shared__ double rs[256], rs2[256];
    rs[tid] = s; rs2[tid] = s2; __syncthreads();
    for (int st = 128; st > 0; st >>= 1) {
        if (tid < st) { rs[tid] += rs[tid+st]; rs2[tid] += rs2[tid+st]; }
        __syncthreads();
    }
    if (tid == 0) {
        double n = (double)BB * (double)L;
        double mean = rs[0]/n, var = rs2[0]/n - mean*mean;
        double sc = (double)gamma[c] / sqrt(var + 1e-5);
        scale[c] = (float)sc;
        shift[c] = (float)((double)beta[c] - mean*sc);
    }
}

// ===== all-TMA fp16 conv: 128co x 128n tile, K-chunk 64, 256 thr, 2 CTA/SM, 3 stages =====
template<int KW, int S, int KTOT, int LPW, int NW>
__global__ void __launch_bounds__(256, 2)
conv_tc_kernel(const uint32_t* __restrict__ pb, const uint32_t* __restrict__ wb,
               float* __restrict__ out, int Lout) {
    constexpr int CI = 64/KW, NC = KTOT/64;
    constexpr int AW = 5120;                 // 128 rows x 40 words
    constexpr int BSTW = CI*NW;
    constexpr int STGW = AW + BSTW;
    constexpr int HDR = 32;
    extern __shared__ __align__(128) uint32_t smw[];
    uint32_t sbase = smem_to_u32(smw);
    int tid = threadIdx.x, wid = tid >> 5, lane = tid & 31;
    int g = lane >> 2, tig = lane & 3;
    int warp_m = wid >> 1, warp_n = wid & 1;
    int n0 = blockIdx.x*128, b = blockIdx.z;
    uint32_t txb = (uint32_t)(20480 + CI*NW*4);

    if (tid == 0) { MBARRIER_INIT(sbase, 1); MBARRIER_INIT(sbase + 8, 1); MBARRIER_INIT(sbase + 16, 1); }
    __syncthreads();
    asm volatile("fence.proxy.async;" ::: "memory");

    auto issue = [&](int c, int s) {
        uint32_t mb = sbase + s*8;
        uint32_t ast = sbase + (uint32_t)(HDR + s*STGW)*4;
        uint32_t bst = ast + AW*4;
        MBARRIER_EXPECT_TX(mb, txb);
        size_t aoff = ((size_t)c*4 + blockIdx.y)*AW;
        BULK_G2S(ast, wb + aoff, 20480, mb);
        int base = n0*(S/2);
        for (int r = 0; r < CI; r++) {
            size_t so = ((size_t)(b*CC) + (size_t)c*CI + r)*LPW + base;
            BULK_G2S(bst + (uint32_t)(r*NW)*4, pb + so, NW*4, mb);
        }
    };
    if (tid == 0) { issue(0, 0); issue(1, 1); if (NC > 2) issue(2, 2); }

    float acc[2][8][4];
#pragma unroll
    for (int mt = 0; mt < 2; mt++)
#pragma unroll
        for (int nt = 0; nt < 8; nt++)
#pragma unroll
            for (int q = 0; q < 4; q++) acc[mt][nt][q] = 0.f;

    int ph[3] = {0, 0, 0};
    int s = 0;
    for (int c = 0; c < NC; c++) {
        MBARRIER_WAIT_PARITY(sbase + s*8, ph[s]); ph[s] ^= 1;
        int Ab = HDR + s*STGW;
        int Bb = Ab + AW;
#pragma unroll
        for (int ks = 0; ks < 4; ks++) {
            int kw = ks*8;
            uint32_t ab[2][4];
#pragma unroll
            for (int mt = 0; mt < 2; mt++) {
                int r = warp_m*32 + mt*16 + g;
                ab[mt][0] = smw[Ab + r*40 + kw + tig];
                ab[mt][1] = smw[Ab + (r+8)*40 + kw + tig];
                ab[mt][2] = smw[Ab + r*40 + kw + tig + 4];
                ab[mt][3] = smw[Ab + (r+8)*40 + kw + tig + 4];
            }
#pragma unroll
            for (int nt = 0; nt < 8; nt++) {
                int nl = warp_n*64 + nt*8 + g;
                uint32_t bbf[2];
#pragma unroll
                for (int j = 0; j < 2; j++) {
                    int kk = ks*16 + 8*j + 2*tig;
                    int cil = kk / KW, jj = kk - cil*KW;
                    bbf[j] = smw[Bb + cil*NW + nl*(S/2) + (jj >> 1)];
                }
#pragma unroll
                for (int mt = 0; mt < 2; mt++)
                    mma_fp16(acc[mt][nt], ab[mt], bbf);
            }
        }
        __syncthreads();
        if (tid == 0 && c + 3 < NC) issue(c + 3, s);
        s = (s == 2) ? 0 : s + 1;
    }

#pragma unroll
    for (int mt = 0; mt < 2; mt++) {
        int co0 = blockIdx.y*128 + warp_m*32 + mt*16 + g;
#pragma unroll
        for (int nt = 0; nt < 8; nt++) {
            int n = n0 + warp_n*64 + nt*8 + 2*tig;
            if (n < Lout) {
                *(float2*)&out[(size_t)(b*CC + co0)*Lout + n]     = make_float2(acc[mt][nt][0], acc[mt][nt][1]);
                *(float2*)&out[(size_t)(b*CC + co0 + 8)*Lout + n] = make_float2(acc[mt][nt][2], acc[mt][nt][3]);
            }
        }
    }
}

__global__ void buildz_kernel(const int* __restrict__ ts, const float* __restrict__ sc,
                              const float* __restrict__ sh) {
    int t = blockIdx.x, b = blockIdx.y, d = threadIdx.x;
    float v = 0.f;
    if (t <= ts[b]) {
        float r = g_c5[(b*CC + d)*L5 + t];
        v = fmaxf(fmaf(r, sc[d], sh[d]), 0.f);
    }
    g_z[(t*BB + b)*CC + d] = v;
}

__global__ void gi_gemm_kernel(const float* __restrict__ wih) {
    __shared__ float As[16*65];
    __shared__ float Bs[16*65];
    int tid = threadIdx.x, tx = tid & 15, ty = tid >> 4;
    int r0 = blockIdx.x * 64, g0 = blockIdx.y * 64;
    float acc[4][4] = {};
    for (int k0 = 0; k0 < CC; k0 += 16) {
        for (int i = tid; i < 1024; i += 256) {
            int rl = i >> 4, kk = i & 15;
            As[kk*65 + rl] = g_z[(r0+rl)*CC + k0 + kk];
            Bs[kk*65 + rl] = wih[(g0+rl)*CC + k0 + kk];
        }
        __syncthreads();
#pragma unroll
        for (int kk = 0; kk < 16; kk++) {
            float av[4], bv[4];
#pragma unroll
            for (int i = 0; i < 4; i++) av[i] = As[kk*65 + ty*4 + i];
#pragma unroll
            for (int j = 0; j < 4; j++) bv[j] = Bs[kk*65 + tx*4 + j];
#pragma unroll
            for (int i = 0; i < 4; i++)
#pragma unroll
                for (int j = 0; j < 4; j++)
                    acc[i][j] = fmaf(av[i], bv[j], acc[i][j]);
        }
        __syncthreads();
    }
#pragma unroll
    for (int i = 0; i < 4; i++)
#pragma unroll
        for (int j = 0; j < 4; j++)
            g_gi[(r0 + ty*4 + i)*768 + g0 + tx*4 + j] = acc[i][j];
}

__global__ void gru_kernel(const float* __restrict__ whh, const float* __restrict__ bih,
                           const float* __restrict__ bhh, const int* __restrict__ ts) {
    __shared__ float ws[3*8*256];
    __shared__ float h_s[BB*HID];
    __shared__ float part[BB*8*2*3];
    __shared__ float bih_s[24], bhh_s[24];
    __shared__ int ts_s[BB];
    int tid = threadIdx.x, j0 = blockIdx.x * 8;
    int b = tid >> 4, jl = (tid >> 1) & 7, half = tid & 1;
    for (int i = tid; i < 6144; i += 256) {
        int g = i >> 11, rest = i & 2047, jj = rest >> 8, k = rest & 255;
        ws[i] = whh[(g*256 + j0 + jj)*256 + k];
    }
    if (tid < 24) {
        int g = tid / 8, jj = tid % 8;
        bih_s[tid] = bih[g*256 + j0 + jj];
        bhh_s[tid] = bhh[g*256 + j0 + jj];
    }
    if (tid < BB) ts_s[tid] = ts[tid];
    __syncthreads();
    for (int t = 0; t < TT; t++) {
        const float* hin = g_hbuf[t & 1];
        for (int i = tid; i < BB*HID; i += 256) h_s[i] = __ldcg(&hin[i]);
        __syncthreads();
        float ar = 0.f, az = 0.f, an = 0.f;
        const float4* h4  = (const float4*)&h_s[b*256 + half*128];
        const float4* wr4 = (const float4*)&ws[(0*8 + jl)*256 + half*128];
        const float4* wz4 = (const float4*)&ws[(1*8 + jl)*256 + half*128];
        const float4* wn4 = (const float4*)&ws[(2*8 + jl)*256 + half*128];
#pragma unroll 8
        for (int k = 0; k < 32; k++) {
            float4 hv = h4[k];
            float4 a = wr4[k]; ar += a.x*hv.x + a.y*hv.y + a.z*hv.z + a.w*hv.w;
            float4 c = wz4[k]; az += c.x*hv.x + c.y*hv.y + c.z*hv.z + c.w*hv.w;
            float4 d = wn4[k]; an += d.x*hv.x + d.y*hv.y + d.z*hv.z + d.w*hv.w;
        }
        int pb = ((b*8 + jl)*2 + half)*3;
        part[pb+0] = ar; part[pb+1] = az; part[pb+2] = an;
        __syncthreads();
        if (half == 0) {
            int p2 = ((b*8 + jl)*2)*3;
            float hr = part[p2+0] + part[p2+3] + bhh_s[jl];
            float hz = part[p2+1] + part[p2+4] + bhh_s[8+jl];
            float hn = part[p2+2] + part[p2+5] + bhh_s[16+jl];
            const float* gi = &g_gi[(t*BB + b)*768];
            float ir  = gi[j0+jl]       + bih_s[jl];
            float iz  = gi[256 + j0+jl] + bih_s[8+jl];
            float in_ = gi[512 + j0+jl] + bih_s[16+jl];
            float r  = 1.f / (1.f + expf(-(ir + hr)));
            float zg = 1.f / (1.f + expf(-(iz + hz)));
            float n  = tanhf(in_ + r*hn);
            float hprev = h_s[b*256 + j0 + jl];
            float hnew = (1.f - zg)*n + zg*hprev;
            __stcg(&g_hbuf[(t+1) & 1][b*256 + j0 + jl], hnew);
            if (t == ts_s[b]) g_ct[b*256 + j0 + jl] = hnew;
        }
        __syncthreads();
        if (tid == 0) {
            __threadfence();   // cumulative: orders all block stores (released to tid0 via bar) at gpu scope
            atomicAdd(&g_bar_cnt, 1u);
            unsigned target = 32u * (unsigned)(t + 1);
            while (*((volatile unsigned*)&g_bar_cnt) < target) { }
        }
        __syncthreads();
    }
}

__global__ void enc_kernel(const int* __restrict__ ts, const float* __restrict__ sc,
                           const float* __restrict__ sh) {
    int k = blockIdx.x, b = blockIdx.y, d = threadIdx.x;
    int t = ts[b] + k + 1;
    float r = g_c5[(b*CC + d)*L5 + t];
    g_enc[(k*BB + b)*CC + d] = fmaxf(fmaf(r, sc[d], sh[d]), 0.f);
}

__global__ void pred_kernel(const float* __restrict__ wk, const float* __restrict__ wkb) {
    int k = blockIdx.x, b = blockIdx.y, d = threadIdx.x;
    __shared__ float ct[HID];
    if (d < HID) ct[d] = g_ct[b*HID + d];
    __syncthreads();
    float acc = wkb[k*CC + d];
    const float4* w4 = (const float4*)&wk[(k*CC + d)*HID];
#pragma unroll 4
    for (int h = 0; h < HID/4; h++) {
        float4 w = w4[h];
        const float* c = &ct[h*4];
        acc += w.x*c[0] + w.y*c[1] + w.z*c[2] + w.w*c[3];
    }
    g_pred[(k*BB + b)*CC + d] = acc;
}

__global__ void total_kernel() {
    int k = blockIdx.x, tid = threadIdx.x;
    int b = tid >> 4, c = tid & 15;
    const float* e = &g_enc[(k*BB + b)*CC];
    const float* p = &g_pred[(k*BB + c)*CC];
    float acc = 0.f;
    for (int d = 0; d < CC; d++) acc += e[d] * p[d];
    g_total[(k*BB + b)*BB + c] = acc;
}

__global__ void final_kernel(float* __restrict__ out) {
    __shared__ float lse_s[KCPC*BB];
    __shared__ float contrib[KCPC*BB];
    __shared__ int corr[BB];
    int tid = threadIdx.x;
    if (tid < KCPC*BB) {
        int b = tid & 15;
        const float* row = &g_total[tid*BB];
        float m = row[0];
        for (int c = 1; c < BB; c++) m = fmaxf(m, row[c]);
        float s = 0.f;
        for (int c = 0; c < BB; c++) s += expf(row[c] - m);
        float lse = m + logf(s);
        lse_s[tid] = lse;
        contrib[tid] = row[b] - lse;
    }
    __syncthreads();
    if (tid == 0) {
        float s = 0.f;
        for (int i = 0; i < KCPC*BB; i++) s += contrib[i];
        out[1] = s / (-(float)(BB*KCPC));
    }
    if (tid < BB) {
        int c = tid;
        float best = -1e30f; int bi = -1;
        for (int b = 0; b < BB; b++) {
            float v = g_total[((KCPC-1)*BB + b)*BB + c] - lse_s[(KCPC-1)*BB + b];
            if (v > best) { best = v; bi = b; }
        }
        corr[tid] = (bi == c) ? 1 : 0;
    }
    __syncthreads();
    if (tid == 0) {
        int cs = 0;
        for (int i = 0; i < BB; i++) cs += corr[i];
        out[0] = (float)cs / (float)BB;
    }
    for (int i = tid; i < BB*HID; i += blockDim.x) out[2 + i] = g_hbuf[0][i];
}

extern "C" void kernel_launch(void* const* d_in, const int* in_sizes, int n_in,
                              void* d_out, int out_size) {
    (void)in_sizes; (void)n_in; (void)out_size;
    const float* x      = (const float*)d_in[0];
    const float* hidden = (const float*)d_in[1];
    const int*   tsamp  = (const int*)d_in[3];
    const float* w1     = (const float*)d_in[4];
    const float* w2     = (const float*)d_in[5];
    const float* w345   = (const float*)d_in[6];
    const float* gamma  = (const float*)d_in[7];
    const float* beta   = (const float*)d_in[8];
    const float* wih    = (const float*)d_in[9];
    const float* whh    = (const float*)d_in[10];
    const float* bih    = (const float*)d_in[11];
    const float* bhh    = (const float*)d_in[12];
    const float* wk     = (const float*)d_in[13];
    const float* wkb    = (const float*)d_in[14];
    float* out = (float*)d_out;

    float *p_c1, *p_c2, *p_c3, *p_c4, *p_c5, *p_sc, *p_sh;
    uint32_t *p_w2b, *p_w345b, *p_apb;
    cudaGetSymbolAddress((void**)&p_c1, g_c1);
    cudaGetSymbolAddress((void**)&p_c2, g_c2);
    cudaGetSymbolAddress((void**)&p_c3, g_c3);
    cudaGetSymbolAddress((void**)&p_c4, g_c4);
    cudaGetSymbolAddress((void**)&p_c5, g_c5);
    cudaGetSymbolAddress((void**)&p_sc, g_scale);
    cudaGetSymbolAddress((void**)&p_sh, g_shift);
    cudaGetSymbolAddress((void**)&p_w2b, g_w2b);
    cudaGetSymbolAddress((void**)&p_w345b, g_w345b);
    cudaGetSymbolAddress((void**)&p_apb, g_apb);

    const int SM_L2   = (32 + 3*(5120 + 8*260))*4;    // 86528
    const int SM_L345 = (32 + 3*(5120 + 16*144))*4;   // 89216
    cudaFuncSetAttribute(conv_tc_kernel<8,4,4096,8200,260>,
                         cudaFuncAttributeMaxDynamicSharedMemorySize, SM_L2);
    cudaFuncSetAttribute(conv_tc_kernel<4,2,2048,2064,144>,
                         cudaFuncAttributeMaxDynamicSharedMemorySize, SM_L345);
    cudaFuncSetAttribute(conv_tc_kernel<4,2,2048,1040,144>,
                         cudaFuncAttributeMaxDynamicSharedMemorySize, SM_L345);
    cudaFuncSetAttribute(conv_tc_kernel<4,2,2048,528,144>,
                         cudaFuncAttributeMaxDynamicSharedMemorySize, SM_L345);

    // dep-minimal prefix so conv_tc L2 is my launch #4 (ncu -s5 -c1 seems to land there)
    conv1_kernel<<<dim3(63, BB), 256>>>(x, w1);                               // 1
    statsprep_kernel<L1,8200,2><<<CC, 256>>>(p_c1, gamma, beta, p_sc, p_sh);  // 2
    prepw_kernel<4096><<<(512*2048 + 255)/256, 256>>>(w2, p_w2b);             // 3
    conv_tc_kernel<8,4,4096,8200,260><<<dim3(32, 4, BB), 256, SM_L2>>>(       // 4 (profile target)
        p_apb, p_w2b, p_c2, L2);

    init_kernel<<<16, 256>>>(hidden);
    prepw_kernel<2048><<<(512*1024 + 255)/256, 256>>>(w345 + 0*512*2048, p_w345b + 0*655360);
    prepw_kernel<2048><<<(512*1024 + 255)/256, 256>>>(w345 + 1*512*2048, p_w345b + 1*655360);
    prepw_kernel<2048><<<(512*1024 + 255)/256, 256>>>(w345 + 2*512*2048, p_w345b + 2*655360);

    statsprep_kernel<L2,2064,1><<<CC, 256>>>(p_c2, gamma + CC, beta + CC, p_sc + CC, p_sh + CC);
    conv_tc_kernel<4,2,2048,2064,144><<<dim3(16, 4, BB), 256, SM_L345>>>(
        p_apb, p_w345b + 0*655360, p_c3, L3);

    statsprep_kernel<L3,1040,1><<<CC, 256>>>(p_c3, gamma + 2*CC, beta + 2*CC, p_sc + 2*CC, p_sh + 2*CC);
    conv_tc_kernel<4,2,2048,1040,144><<<dim3(8, 4, BB), 256, SM_L345>>>(
        p_apb, p_w345b + 1*655360, p_c4, L4);

    statsprep_kernel<L4,528,1><<<CC, 256>>>(p_c4, gamma + 3*CC, beta + 3*CC, p_sc + 3*CC, p_sh + 3*CC);
    conv_tc_kernel<4,2,2048,528,144><<<dim3(4, 4, BB), 256, SM_L345>>>(
        p_apb, p_w345b + 2*655360, p_c5, L5);

    stats_kernel<<<CC, 256>>>(p_c5, gamma + 4*CC, beta + 4*CC, p_sc + 4*CC, p_sh + 4*CC, L5);

    buildz_kernel<<<dim3(TT, BB), CC>>>(tsamp, p_sc + 4*CC, p_sh + 4*CC);
    gi_gemm_kernel<<<dim3(125, 12), 256>>>(wih);
    gru_kernel<<<32, 256>>>(whh, bih, bhh, tsamp);

    enc_kernel<<<dim3(KCPC, BB), CC>>>(tsamp, p_sc + 4*CC, p_sh + 4*CC);
    pred_kernel<<<dim3(KCPC, BB), CC>>>(wk, wkb);
    total_kernel<<<KCPC, 256>>>();
    final_kernel<<<1, 256>>>(out);
}